// round 6
// baseline (speedup 1.0000x reference)
#include <cuda_runtime.h>
#include <cuda_bf16.h>
#include <math_constants.h>
#include <cstdint>

// Problem constants
#define Bb 2
#define Ss 2048
#define Dd 1024
#define Hh 16
#define HD 64
#define Mtot (Bb*Ss)   // 4096 rows

// ---------------------------------------------------------------------------
// Scratch (__device__ globals; allocation-free rule)
// ---------------------------------------------------------------------------
__device__ __nv_bfloat16 g_xh [Mtot*Dd], g_xl [Mtot*Dd];
__device__ __nv_bfloat16 g_wqh[Dd*Dd],   g_wql[Dd*Dd];
__device__ __nv_bfloat16 g_wkh[Dd*Dd],   g_wkl[Dd*Dd];
__device__ __nv_bfloat16 g_wvh[Dd*Dd],   g_wvl[Dd*Dd];
__device__ __nv_bfloat16 g_woh[Dd*Dd],   g_wol[Dd*Dd];
__device__ __nv_bfloat16 g_Qh [Mtot*Dd], g_Ql [Mtot*Dd];   // pre-scaled by 0.125
__device__ __nv_bfloat16 g_Kh [Mtot*Dd], g_Kl [Mtot*Dd];
__device__ __nv_bfloat16 g_Vh [Mtot*Dd], g_Vl [Mtot*Dd];
__device__ __nv_bfloat16 g_aoh[Mtot*Dd], g_aol[Mtot*Dd];

// ---------------------------------------------------------------------------
// PTX helpers (compute_103-safe: ldmatrix / mma.sync / cp.async)
// ---------------------------------------------------------------------------
__device__ __forceinline__ uint32_t smem_u32(const void* p) {
    uint32_t a;
    asm("{ .reg .u64 t; cvta.to.shared.u64 t, %1; cvt.u32.u64 %0, t; }"
        : "=r"(a) : "l"(p));
    return a;
}

__device__ __forceinline__ void ldm_x4(uint32_t& r0, uint32_t& r1,
                                       uint32_t& r2, uint32_t& r3, uint32_t addr) {
    asm volatile("ldmatrix.sync.aligned.m8n8.x4.shared.b16 {%0,%1,%2,%3}, [%4];"
                 : "=r"(r0), "=r"(r1), "=r"(r2), "=r"(r3) : "r"(addr));
}

__device__ __forceinline__ void ldm_x4_t(uint32_t& r0, uint32_t& r1,
                                         uint32_t& r2, uint32_t& r3, uint32_t addr) {
    asm volatile("ldmatrix.sync.aligned.m8n8.x4.trans.shared.b16 {%0,%1,%2,%3}, [%4];"
                 : "=r"(r0), "=r"(r1), "=r"(r2), "=r"(r3) : "r"(addr));
}

__device__ __forceinline__ void mma16816(float* c, const uint32_t* a, const uint32_t* b) {
    asm volatile(
        "mma.sync.aligned.m16n8k16.row.col.f32.bf16.bf16.f32 "
        "{%0,%1,%2,%3}, {%4,%5,%6,%7}, {%8,%9}, {%0,%1,%2,%3};"
        : "+f"(c[0]), "+f"(c[1]), "+f"(c[2]), "+f"(c[3])
        : "r"(a[0]), "r"(a[1]), "r"(a[2]), "r"(a[3]), "r"(b[0]), "r"(b[1]));
}

#define CP_ASYNC16(dst, src) \
    asm volatile("cp.async.cg.shared.global [%0], [%1], 16;" :: "r"(dst), "l"(src))
#define CP_COMMIT() asm volatile("cp.async.commit_group;" ::: "memory")
#define CP_WAIT(n)  asm volatile("cp.async.wait_group %0;" :: "n"(n) : "memory")

// pack two fp32 -> bf16x2 reg (first arg in low half = element k)
__device__ __forceinline__ uint32_t pk_bf2(float lo, float hi) {
    uint32_t r;
    asm("cvt.rn.bf16x2.f32 %0, %1, %2;" : "=r"(r) : "f"(hi), "f"(lo));
    return r;
}
__device__ __forceinline__ float bf_trunc(float x) {
    return __bfloat162float(__float2bfloat16(x));
}

// ---------------------------------------------------------------------------
// fp32 -> bf16 hi/lo split kernels
// ---------------------------------------------------------------------------
__device__ __forceinline__ void split4(const float* __restrict__ src,
                                       __nv_bfloat16* __restrict__ hi,
                                       __nv_bfloat16* __restrict__ lo, int i)
{
    float4 v = *(const float4*)(src + i);
    __nv_bfloat16 ha = __float2bfloat16(v.x);
    __nv_bfloat16 hb = __float2bfloat16(v.y);
    __nv_bfloat16 hc = __float2bfloat16(v.z);
    __nv_bfloat16 hd = __float2bfloat16(v.w);
    __nv_bfloat16 la = __float2bfloat16(v.x - __bfloat162float(ha));
    __nv_bfloat16 lb = __float2bfloat16(v.y - __bfloat162float(hb));
    __nv_bfloat16 lc = __float2bfloat16(v.z - __bfloat162float(hc));
    __nv_bfloat16 ld = __float2bfloat16(v.w - __bfloat162float(hd));
    *(__nv_bfloat162*)(hi + i)     = __halves2bfloat162(ha, hb);
    *(__nv_bfloat162*)(hi + i + 2) = __halves2bfloat162(hc, hd);
    *(__nv_bfloat162*)(lo + i)     = __halves2bfloat162(la, lb);
    *(__nv_bfloat162*)(lo + i + 2) = __halves2bfloat162(lc, ld);
}

__global__ __launch_bounds__(256)
void split_bf16(const float* __restrict__ src,
                __nv_bfloat16* __restrict__ hi,
                __nv_bfloat16* __restrict__ lo, int n)
{
    int i = (blockIdx.x * 256 + threadIdx.x) * 4;
    if (i < n) split4(src, hi, lo, i);
}

__global__ __launch_bounds__(256)
void split_w4(const float* w0, const float* w1, const float* w2, const float* w3,
              __nv_bfloat16* h0, __nv_bfloat16* l0, __nv_bfloat16* h1, __nv_bfloat16* l1,
              __nv_bfloat16* h2, __nv_bfloat16* l2, __nv_bfloat16* h3, __nv_bfloat16* l3)
{
    const float* src; __nv_bfloat16 *hi, *lo;
    switch (blockIdx.y) {
        case 0: src = w0; hi = h0; lo = l0; break;
        case 1: src = w1; hi = h1; lo = l1; break;
        case 2: src = w2; hi = h2; lo = l2; break;
        default: src = w3; hi = h3; lo = l3; break;
    }
    int i = (blockIdx.x * 256 + threadIdx.x) * 4;
    if (i < Dd*Dd) split4(src, hi, lo, i);
}

// ---------------------------------------------------------------------------
// HMMA bf16x3 GEMM: C = (Ah+Al) @ (Bh+Bl)^T. Two epilogues:
//   SPLIT=0: fp32 + bias -> C
//   SPLIT=1: (scale*C) split into bf16 hi/lo -> Ch, Cl
// Tile 128x128x32, 8 warps, warp tile 64x32, 3-stage cp.async, 1 sync/chunk.
// ---------------------------------------------------------------------------
#define GM 128
#define GN 128
#define GKC 32
#define NCHUNK (Dd / GKC)        // 32
#define TILEB (128 * GKC * 2)    // 8192
#define STAGEB (4 * TILEB)       // 32KB: AH | AL | BH | BL
#define GEMM_SMEM (3 * STAGEB)   // 96KB

__device__ __forceinline__ uint32_t sw_addr(uint32_t base, int row, int unit) {
    return base + row * 64 + ((unit ^ ((row >> 1) & 3)) << 4);
}

__device__ __forceinline__ void cp_tile(uint32_t sdst, const __nv_bfloat16* __restrict__ g,
                                        int tid)
{
    #pragma unroll
    for (int i = 0; i < 2; i++) {
        int u   = tid + i * 256;
        int row = u >> 2;
        int cu  = u & 3;
        CP_ASYNC16(sw_addr(sdst, row, cu), g + (size_t)row * Dd + cu * 8);
    }
}

__device__ __forceinline__ void cp_stage(uint32_t s,
    const __nv_bfloat16* gAh, const __nv_bfloat16* gAl,
    const __nv_bfloat16* gBh, const __nv_bfloat16* gBl, int kc, int tid)
{
    cp_tile(s,           gAh + kc, tid);
    cp_tile(s + TILEB,   gAl + kc, tid);
    cp_tile(s + 2*TILEB, gBh + kc, tid);
    cp_tile(s + 3*TILEB, gBl + kc, tid);
    CP_COMMIT();
}

template<int SPLIT>
__device__ __forceinline__ void gemm_tc_body(
    const __nv_bfloat16* __restrict__ Ah, const __nv_bfloat16* __restrict__ Al,
    const __nv_bfloat16* __restrict__ Bh, const __nv_bfloat16* __restrict__ Bl,
    const float* __restrict__ bias, float* __restrict__ C,
    __nv_bfloat16* __restrict__ Ch, __nv_bfloat16* __restrict__ Cl, float scale)
{
    extern __shared__ char smem[];
    const uint32_t sb = smem_u32(smem);
    const int tid = threadIdx.x;
    const int wid = tid >> 5;
    const int lid = tid & 31;
    const int wm  = wid >> 2;
    const int wn  = wid & 3;
    const int m0  = blockIdx.y * GM;
    const int n0  = blockIdx.x * GN;

    const __nv_bfloat16* gAh = Ah + (size_t)m0 * Dd;
    const __nv_bfloat16* gAl = Al + (size_t)m0 * Dd;
    const __nv_bfloat16* gBh = Bh + (size_t)n0 * Dd;
    const __nv_bfloat16* gBl = Bl + (size_t)n0 * Dd;

    float acc[4][4][4];
    #pragma unroll
    for (int i = 0; i < 4; i++)
        #pragma unroll
        for (int j = 0; j < 4; j++)
            #pragma unroll
            for (int k = 0; k < 4; k++) acc[i][j][k] = 0.f;

    const int a_row = wm * 64 + (lid & 15);
    const int a_ku  = lid >> 4;
    const int b_row = wn * 32 + (lid & 7) + ((lid >> 4) << 3);
    const int b_ku  = (lid >> 3) & 1;

    // prologue: chunks 0,1 -> stages 0,1
    cp_stage(sb,          gAh, gAl, gBh, gBl, 0,   tid);
    cp_stage(sb + STAGEB, gAh, gAl, gBh, gBl, GKC, tid);

    int stage = 0;
    for (int c = 0; c < NCHUNK; c++) {
        if (c + 1 < NCHUNK) { CP_WAIT(1); } else { CP_WAIT(0); }
        __syncthreads();   // chunk c visible; all warps done with chunk c-1
        if (c + 2 < NCHUNK) {
            int ns = stage + 2; if (ns >= 3) ns -= 3;
            cp_stage(sb + ns * STAGEB, gAh, gAl, gBh, gBl, (c + 2) * GKC, tid);
        }

        const uint32_t sa_h = sb + stage * STAGEB;
        const uint32_t sa_l = sa_h + TILEB;
        const uint32_t sbh  = sa_h + 2*TILEB;
        const uint32_t sbl  = sa_h + 3*TILEB;
        if (++stage == 3) stage = 0;

        #pragma unroll
        for (int ks = 0; ks < 2; ks++) {
            const int ku = ks * 2;
            uint32_t bh[8], bl[8];
            #pragma unroll
            for (int pr = 0; pr < 2; pr++) {
                ldm_x4(bh[pr*4+0], bh[pr*4+1], bh[pr*4+2], bh[pr*4+3],
                       sw_addr(sbh, b_row + pr*16, ku + b_ku));
                ldm_x4(bl[pr*4+0], bl[pr*4+1], bl[pr*4+2], bl[pr*4+3],
                       sw_addr(sbl, b_row + pr*16, ku + b_ku));
            }
            #pragma unroll
            for (int mt = 0; mt < 4; mt++) {
                uint32_t ah[4], al[4];
                ldm_x4(ah[0], ah[1], ah[2], ah[3],
                       sw_addr(sa_h, a_row + mt*16, ku + a_ku));
                ldm_x4(al[0], al[1], al[2], al[3],
                       sw_addr(sa_l, a_row + mt*16, ku + a_ku));
                #pragma unroll
                for (int nt = 0; nt < 4; nt++) {
                    mma16816(acc[mt][nt], ah, &bh[nt*2]);
                    mma16816(acc[mt][nt], al, &bh[nt*2]);
                    mma16816(acc[mt][nt], ah, &bl[nt*2]);
                }
            }
        }
    }

    #pragma unroll
    for (int mt = 0; mt < 4; mt++) {
        const int row = m0 + wm*64 + mt*16 + (lid >> 2);
        #pragma unroll
        for (int nt = 0; nt < 4; nt++) {
            const int col = n0 + wn*32 + nt*8 + (lid & 3)*2;
            if (SPLIT) {
                #pragma unroll
                for (int half = 0; half < 2; half++) {
                    const int r = row + half * 8;
                    float va = acc[mt][nt][half*2+0] * scale;
                    float vb = acc[mt][nt][half*2+1] * scale;
                    __nv_bfloat16 ha = __float2bfloat16(va);
                    __nv_bfloat16 hb = __float2bfloat16(vb);
                    __nv_bfloat16 la = __float2bfloat16(va - __bfloat162float(ha));
                    __nv_bfloat16 lb = __float2bfloat16(vb - __bfloat162float(hb));
                    *(__nv_bfloat162*)(Ch + (size_t)r * Dd + col) = __halves2bfloat162(ha, hb);
                    *(__nv_bfloat162*)(Cl + (size_t)r * Dd + col) = __halves2bfloat162(la, lb);
                }
            } else {
                float2 v0 = make_float2(acc[mt][nt][0], acc[mt][nt][1]);
                float2 v1 = make_float2(acc[mt][nt][2], acc[mt][nt][3]);
                float2 bv = *(const float2*)(bias + col);
                v0.x += bv.x; v0.y += bv.y;
                v1.x += bv.x; v1.y += bv.y;
                *(float2*)(C + (size_t)row * Dd + col)       = v0;
                *(float2*)(C + (size_t)(row + 8) * Dd + col) = v1;
            }
        }
    }
}

__global__ __launch_bounds__(256)
void gemm_qkv_tc()
{
    const __nv_bfloat16 *Bh, *Bl; __nv_bfloat16 *Ch, *Cl; float sc;
    if (blockIdx.z == 0)      { Bh = g_wqh; Bl = g_wql; Ch = g_Qh; Cl = g_Ql; sc = 0.125f; }
    else if (blockIdx.z == 1) { Bh = g_wkh; Bl = g_wkl; Ch = g_Kh; Cl = g_Kl; sc = 1.f; }
    else                      { Bh = g_wvh; Bl = g_wvl; Ch = g_Vh; Cl = g_Vl; sc = 1.f; }
    gemm_tc_body<1>(g_xh, g_xl, Bh, Bl, nullptr, nullptr, Ch, Cl, sc);
}

__global__ __launch_bounds__(256)
void gemm_o_tc(const float* bias, float* out)
{
    gemm_tc_body<0>(g_aoh, g_aol, g_woh, g_wol, bias, out, nullptr, nullptr, 1.f);
}

// ---------------------------------------------------------------------------
// HMMA flash attention. Block = 128 q rows of one (b,h); 8 warps x 16 rows.
// KV chunks of 64 keys, 3-stage cp.async, 1 sync/chunk. x3 error correction
// on QK^T and PV. Writes AO as bf16 hi/lo directly.
// ---------------------------------------------------------------------------
#define AQ 128
#define AKC 64
#define SQH 0
#define SQL 16384
#define SKV 32768
#define KVSTAGE 32768   // KH 0 | KL 8192 | VH 16384 | VL 24576
#define ATT_SMEM (SKV + 3 * KVSTAGE)   // 131072

__device__ __forceinline__ uint32_t asw(uint32_t base, int row, int unit) {
    return base + row * 128 + ((unit ^ (row & 7)) << 4);
}

__device__ __forceinline__ void cp_kv(uint32_t sbase, int brow0, int h, int tid)
{
    #pragma unroll
    for (int i = 0; i < 2; i++) {
        int u = tid + i * 256;
        int row = u >> 3;
        int un = u & 7;
        size_t g = ((size_t)(brow0 + row)) * Dd + h * HD + un * 8;
        CP_ASYNC16(asw(sbase,          row, un), g_Kh + g);
        CP_ASYNC16(asw(sbase +  8192,  row, un), g_Kl + g);
        CP_ASYNC16(asw(sbase + 16384,  row, un), g_Vh + g);
        CP_ASYNC16(asw(sbase + 24576,  row, un), g_Vl + g);
    }
    CP_COMMIT();
}

__global__ __launch_bounds__(256)
void attn_mma()
{
    extern __shared__ char smem[];
    const uint32_t sb = smem_u32(smem);
    const int tid = threadIdx.x;
    const int wid = tid >> 5;
    const int lid = tid & 31;
    const int q0  = blockIdx.x * AQ;
    const int b   = blockIdx.y >> 4;
    const int h   = blockIdx.y & 15;

    // group 0: Q (hi/lo), 128 rows x 8 units each
    #pragma unroll
    for (int i = 0; i < 4; i++) {
        int u = tid + i * 256;
        int row = u >> 3;
        int un = u & 7;
        size_t g = ((size_t)(b * Ss + q0 + row)) * Dd + h * HD + un * 8;
        CP_ASYNC16(asw(sb + SQH, row, un), g_Qh + g);
        CP_ASYNC16(asw(sb + SQL, row, un), g_Ql + g);
    }
    CP_COMMIT();

    // groups 1,2: KV chunks 0,1 -> stages 0,1
    cp_kv(sb + SKV,           b * Ss,       h, tid);
    cp_kv(sb + SKV + KVSTAGE, b * Ss + AKC, h, tid);

    CP_WAIT(2);   // Q resident
    __syncthreads();

    // Q fragments for this warp's 16 rows (4 k-tiles, hi/lo)
    uint32_t qh[4][4], ql[4][4];
    {
        const int r = wid * 16 + (lid & 15);
        const int ub = lid >> 4;
        #pragma unroll
        for (int ks = 0; ks < 4; ks++) {
            ldm_x4(qh[ks][0], qh[ks][1], qh[ks][2], qh[ks][3],
                   asw(sb + SQH, r, ks*2 + ub));
            ldm_x4(ql[ks][0], ql[ks][1], ql[ks][2], ql[ks][3],
                   asw(sb + SQL, r, ks*2 + ub));
        }
    }

    float o[8][4];
    #pragma unroll
    for (int i = 0; i < 8; i++)
        #pragma unroll
        for (int j = 0; j < 4; j++) o[i][j] = 0.f;
    float m0 = -CUDART_INF_F, m1 = -CUDART_INF_F, l0 = 0.f, l1 = 0.f;

    const int kb_row = (lid & 7) + ((lid >> 4) << 3);
    const int kb_ku  = (lid >> 3) & 1;
    const int v_row  = lid & 15;
    const int v_ub   = lid >> 4;

    const int NC = Ss / AKC;    // 32
    int stage = 0;
    for (int c = 0; c < NC; c++) {
        if (c + 1 < NC) { CP_WAIT(1); } else { CP_WAIT(0); }
        __syncthreads();   // chunk c visible; all warps done with chunk c-1
        if (c + 2 < NC) {
            int ns = stage + 2; if (ns >= 3) ns -= 3;
            cp_kv(sb + SKV + ns * KVSTAGE, b * Ss + (c + 2) * AKC, h, tid);
        }

        const uint32_t skh = sb + SKV + stage * KVSTAGE;
        const uint32_t skl = skh + 8192;
        const uint32_t svh = skh + 16384;
        const uint32_t svl = skh + 24576;
        if (++stage == 3) stage = 0;

        // S = Q K^T  (x3 corrected), 16x64 per warp
        float s[8][4];
        #pragma unroll
        for (int i = 0; i < 8; i++)
            #pragma unroll
            for (int j = 0; j < 4; j++) s[i][j] = 0.f;

        #pragma unroll
        for (int ks = 0; ks < 4; ks++) {
            #pragma unroll
            for (int g = 0; g < 4; g++) {
                uint32_t kh4[4], kl4[4];
                ldm_x4(kh4[0], kh4[1], kh4[2], kh4[3],
                       asw(skh, g*16 + kb_row, ks*2 + kb_ku));
                ldm_x4(kl4[0], kl4[1], kl4[2], kl4[3],
                       asw(skl, g*16 + kb_row, ks*2 + kb_ku));
                mma16816(s[2*g],   qh[ks], &kh4[0]);
                mma16816(s[2*g],   ql[ks], &kh4[0]);
                mma16816(s[2*g],   qh[ks], &kl4[0]);
                mma16816(s[2*g+1], qh[ks], &kh4[2]);
                mma16816(s[2*g+1], ql[ks], &kh4[2]);
                mma16816(s[2*g+1], qh[ks], &kl4[2]);
            }
        }

        // online softmax (rows r and r+8 per thread)
        float rm0 = fmaxf(s[0][0], s[0][1]);
        float rm1 = fmaxf(s[0][2], s[0][3]);
        #pragma unroll
        for (int nt = 1; nt < 8; nt++) {
            rm0 = fmaxf(rm0, fmaxf(s[nt][0], s[nt][1]));
            rm1 = fmaxf(rm1, fmaxf(s[nt][2], s[nt][3]));
        }
        rm0 = fmaxf(rm0, __shfl_xor_sync(0xffffffffu, rm0, 1));
        rm0 = fmaxf(rm0, __shfl_xor_sync(0xffffffffu, rm0, 2));
        rm1 = fmaxf(rm1, __shfl_xor_sync(0xffffffffu, rm1, 1));
        rm1 = fmaxf(rm1, __shfl_xor_sync(0xffffffffu, rm1, 2));
        const float mn0 = fmaxf(m0, rm0);
        const float mn1 = fmaxf(m1, rm1);
        const float c0 = __expf(m0 - mn0);
        const float c1 = __expf(m1 - mn1);
        float sum0 = 0.f, sum1 = 0.f;
        #pragma unroll
        for (int nt = 0; nt < 8; nt++) {
            s[nt][0] = __expf(s[nt][0] - mn0); sum0 += s[nt][0];
            s[nt][1] = __expf(s[nt][1] - mn0); sum0 += s[nt][1];
            s[nt][2] = __expf(s[nt][2] - mn1); sum1 += s[nt][2];
            s[nt][3] = __expf(s[nt][3] - mn1); sum1 += s[nt][3];
            o[nt][0] *= c0; o[nt][1] *= c0;
            o[nt][2] *= c1; o[nt][3] *= c1;
        }
        sum0 += __shfl_xor_sync(0xffffffffu, sum0, 1);
        sum0 += __shfl_xor_sync(0xffffffffu, sum0, 2);
        sum1 += __shfl_xor_sync(0xffffffffu, sum1, 1);
        sum1 += __shfl_xor_sync(0xffffffffu, sum1, 2);
        l0 = l0 * c0 + sum0;
        l1 = l1 * c1 + sum1;
        m0 = mn0; m1 = mn1;

        // O += P V  (x3 corrected)
        #pragma unroll
        for (int kt = 0; kt < 4; kt++) {
            uint32_t pah[4], pal[4];
            {
                const float* t0 = s[2*kt];
                const float* t1 = s[2*kt+1];
                pah[0] = pk_bf2(t0[0], t0[1]);
                pah[1] = pk_bf2(t0[2], t0[3]);
                pah[2] = pk_bf2(t1[0], t1[1]);
                pah[3] = pk_bf2(t1[2], t1[3]);
                pal[0] = pk_bf2(t0[0]-bf_trunc(t0[0]), t0[1]-bf_trunc(t0[1]));
                pal[1] = pk_bf2(t0[2]-bf_trunc(t0[2]), t0[3]-bf_trunc(t0[3]));
                pal[2] = pk_bf2(t1[0]-bf_trunc(t1[0]), t1[1]-bf_trunc(t1[1]));
                pal[3] = pk_bf2(t1[2]-bf_trunc(t1[2]), t1[3]-bf_trunc(t1[3]));
            }
            #pragma unroll
            for (int db = 0; db < 4; db++) {
                uint32_t vh4[4], vl4[4];
                ldm_x4_t(vh4[0], vh4[1], vh4[2], vh4[3],
                         asw(svh, kt*16 + v_row, db*2 + v_ub));
                ldm_x4_t(vl4[0], vl4[1], vl4[2], vl4[3],
                         asw(svl, kt*16 + v_row, db*2 + v_ub));
                mma16816(o[2*db + 0], pah, &vh4[0]);
                mma16816(o[2*db + 0], pal, &vh4[0]);
                mma16816(o[2*db + 0], pah, &vl4[0]);
                mma16816(o[2*db + 1], pah, &vh4[2]);
                mma16816(o[2*db + 1], pal, &vh4[2]);
                mma16816(o[2*db + 1], pah, &vl4[2]);
            }
        }
    }

    // normalize + write AO hi/lo
    const float inv0 = 1.f / l0;
    const float inv1 = 1.f / l1;
    const int gr0 = b * Ss + q0 + wid*16 + (lid >> 2);
    #pragma unroll
    for (int nt = 0; nt < 8; nt++) {
        const int col = h * HD + nt*8 + (lid & 3)*2;
        float va = o[nt][0] * inv0, vb = o[nt][1] * inv0;
        float vc = o[nt][2] * inv1, vd = o[nt][3] * inv1;
        __nv_bfloat16 ha = __float2bfloat16(va), hb = __float2bfloat16(vb);
        __nv_bfloat16 hc = __float2bfloat16(vc), hd = __float2bfloat16(vd);
        *(__nv_bfloat162*)(g_aoh + (size_t)gr0 * Dd + col) = __halves2bfloat162(ha, hb);
        *(__nv_bfloat162*)(g_aol + (size_t)gr0 * Dd + col) =
            __halves2bfloat162(__float2bfloat16(va - __bfloat162float(ha)),
                               __float2bfloat16(vb - __bfloat162float(hb)));
        *(__nv_bfloat162*)(g_aoh + (size_t)(gr0 + 8) * Dd + col) = __halves2bfloat162(hc, hd);
        *(__nv_bfloat162*)(g_aol + (size_t)(gr0 + 8) * Dd + col) =
            __halves2bfloat162(__float2bfloat16(vc - __bfloat162float(hc)),
                               __float2bfloat16(vd - __bfloat162float(hd)));
    }
}

// ---------------------------------------------------------------------------
extern "C" void kernel_launch(void* const* d_in, const int* in_sizes, int n_in,
                              void* d_out, int out_size)
{
    const float* x  = (const float*)d_in[0];
    const float* Wq = (const float*)d_in[1];
    const float* Wk = (const float*)d_in[2];
    const float* Wv = (const float*)d_in[3];
    const float* Wo = (const float*)d_in[4];
    const float* bo = (const float*)d_in[5];
    float* out = (float*)d_out;

    cudaFuncSetAttribute(gemm_qkv_tc, cudaFuncAttributeMaxDynamicSharedMemorySize, GEMM_SMEM);
    cudaFuncSetAttribute(gemm_o_tc,   cudaFuncAttributeMaxDynamicSharedMemorySize, GEMM_SMEM);
    cudaFuncSetAttribute(attn_mma,    cudaFuncAttributeMaxDynamicSharedMemorySize, ATT_SMEM);

    void *pxh, *pxl, *pqh, *pql, *pkh, *pkl, *pvh, *pvl, *poh, *pol;
    cudaGetSymbolAddress(&pxh, g_xh);  cudaGetSymbolAddress(&pxl, g_xl);
    cudaGetSymbolAddress(&pqh, g_wqh); cudaGetSymbolAddress(&pql, g_wql);
    cudaGetSymbolAddress(&pkh, g_wkh); cudaGetSymbolAddress(&pkl, g_wkl);
    cudaGetSymbolAddress(&pvh, g_wvh); cudaGetSymbolAddress(&pvl, g_wvl);
    cudaGetSymbolAddress(&poh, g_woh); cudaGetSymbolAddress(&pol, g_wol);

    // 1) split fp32 inputs -> bf16 hi/lo (x, then all 4 weights in one launch)
    split_bf16<<<(Mtot*Dd)/1024, 256>>>(x, (__nv_bfloat16*)pxh, (__nv_bfloat16*)pxl, Mtot*Dd);
    dim3 gsw((Dd*Dd)/1024, 4);
    split_w4<<<gsw, 256>>>(Wq, Wk, Wv, Wo,
        (__nv_bfloat16*)pqh, (__nv_bfloat16*)pql,
        (__nv_bfloat16*)pkh, (__nv_bfloat16*)pkl,
        (__nv_bfloat16*)pvh, (__nv_bfloat16*)pvl,
        (__nv_bfloat16*)poh, (__nv_bfloat16*)pol);

    // 2) QKV projections -> bf16 hi/lo (Q pre-scaled by 1/sqrt(HD))
    dim3 gqkv(Dd / GN, Mtot / GM, 3);
    gemm_qkv_tc<<<gqkv, 256, GEMM_SMEM>>>();

    // 3) HMMA flash attention -> AO hi/lo
    dim3 gattn(Ss / AQ, Bb * Hh);
    attn_mma<<<gattn, 256, ATT_SMEM>>>();

    // 4) output projection (+bias) -> fp32 out
    dim3 gout(Dd / GN, Mtot / GM, 1);
    gemm_o_tc<<<gout, 256, GEMM_SMEM>>>(bo, out);
}

// round 8
// speedup vs baseline: 1.1253x; 1.1253x over previous
#include <cuda_runtime.h>
#include <cuda_bf16.h>
#include <math_constants.h>
#include <cstdint>

// Problem constants
#define Bb 2
#define Ss 2048
#define Dd 1024
#define Hh 16
#define HD 64
#define Mtot (Bb*Ss)   // 4096 rows

// ---------------------------------------------------------------------------
// Scratch (__device__ globals; allocation-free rule)
// ---------------------------------------------------------------------------
__device__ __nv_bfloat16 g_xh [Mtot*Dd], g_xl [Mtot*Dd];
__device__ __nv_bfloat16 g_wqh[Dd*Dd],   g_wql[Dd*Dd];
__device__ __nv_bfloat16 g_wkh[Dd*Dd],   g_wkl[Dd*Dd];
__device__ __nv_bfloat16 g_wvh[Dd*Dd],   g_wvl[Dd*Dd];
__device__ __nv_bfloat16 g_woh[Dd*Dd],   g_wol[Dd*Dd];
__device__ __nv_bfloat16 g_Qh [Mtot*Dd], g_Ql [Mtot*Dd];   // pre-scaled by 0.125
__device__ __nv_bfloat16 g_Kh [Mtot*Dd], g_Kl [Mtot*Dd];
__device__ __nv_bfloat16 g_Vh [Mtot*Dd], g_Vl [Mtot*Dd];
__device__ __nv_bfloat16 g_aoh[Mtot*Dd], g_aol[Mtot*Dd];

// ---------------------------------------------------------------------------
// PTX helpers (compute_103-safe: ldmatrix / mma.sync / cp.async)
// ---------------------------------------------------------------------------
__device__ __forceinline__ uint32_t smem_u32(const void* p) {
    uint32_t a;
    asm("{ .reg .u64 t; cvta.to.shared.u64 t, %1; cvt.u32.u64 %0, t; }"
        : "=r"(a) : "l"(p));
    return a;
}

__device__ __forceinline__ void ldm_x4(uint32_t& r0, uint32_t& r1,
                                       uint32_t& r2, uint32_t& r3, uint32_t addr) {
    asm volatile("ldmatrix.sync.aligned.m8n8.x4.shared.b16 {%0,%1,%2,%3}, [%4];"
                 : "=r"(r0), "=r"(r1), "=r"(r2), "=r"(r3) : "r"(addr));
}

__device__ __forceinline__ void ldm_x4_t(uint32_t& r0, uint32_t& r1,
                                         uint32_t& r2, uint32_t& r3, uint32_t addr) {
    asm volatile("ldmatrix.sync.aligned.m8n8.x4.trans.shared.b16 {%0,%1,%2,%3}, [%4];"
                 : "=r"(r0), "=r"(r1), "=r"(r2), "=r"(r3) : "r"(addr));
}

__device__ __forceinline__ void mma16816(float* c, const uint32_t* a, const uint32_t* b) {
    asm volatile(
        "mma.sync.aligned.m16n8k16.row.col.f32.bf16.bf16.f32 "
        "{%0,%1,%2,%3}, {%4,%5,%6,%7}, {%8,%9}, {%0,%1,%2,%3};"
        : "+f"(c[0]), "+f"(c[1]), "+f"(c[2]), "+f"(c[3])
        : "r"(a[0]), "r"(a[1]), "r"(a[2]), "r"(a[3]), "r"(b[0]), "r"(b[1]));
}

#define CP_ASYNC16(dst, src) \
    asm volatile("cp.async.cg.shared.global [%0], [%1], 16;" :: "r"(dst), "l"(src))
#define CP_COMMIT() asm volatile("cp.async.commit_group;" ::: "memory")
#define CP_WAIT(n)  asm volatile("cp.async.wait_group %0;" :: "n"(n) : "memory")

// pack two fp32 -> bf16x2 reg (first arg in low half = element k)
__device__ __forceinline__ uint32_t pk_bf2(float lo, float hi) {
    uint32_t r;
    asm("cvt.rn.bf16x2.f32 %0, %1, %2;" : "=r"(r) : "f"(hi), "f"(lo));
    return r;
}
__device__ __forceinline__ float bf_trunc(float x) {
    return __bfloat162float(__float2bfloat16(x));
}

// ---------------------------------------------------------------------------
// fp32 -> bf16 hi/lo split kernels
// ---------------------------------------------------------------------------
__device__ __forceinline__ void split4(const float* __restrict__ src,
                                       __nv_bfloat16* __restrict__ hi,
                                       __nv_bfloat16* __restrict__ lo, int i)
{
    float4 v = *(const float4*)(src + i);
    __nv_bfloat16 ha = __float2bfloat16(v.x);
    __nv_bfloat16 hb = __float2bfloat16(v.y);
    __nv_bfloat16 hc = __float2bfloat16(v.z);
    __nv_bfloat16 hd = __float2bfloat16(v.w);
    __nv_bfloat16 la = __float2bfloat16(v.x - __bfloat162float(ha));
    __nv_bfloat16 lb = __float2bfloat16(v.y - __bfloat162float(hb));
    __nv_bfloat16 lc = __float2bfloat16(v.z - __bfloat162float(hc));
    __nv_bfloat16 ld = __float2bfloat16(v.w - __bfloat162float(hd));
    *(__nv_bfloat162*)(hi + i)     = __halves2bfloat162(ha, hb);
    *(__nv_bfloat162*)(hi + i + 2) = __halves2bfloat162(hc, hd);
    *(__nv_bfloat162*)(lo + i)     = __halves2bfloat162(la, lb);
    *(__nv_bfloat162*)(lo + i + 2) = __halves2bfloat162(lc, ld);
}

__global__ __launch_bounds__(256)
void split_bf16(const float* __restrict__ src,
                __nv_bfloat16* __restrict__ hi,
                __nv_bfloat16* __restrict__ lo, int n)
{
    int i = (blockIdx.x * 256 + threadIdx.x) * 4;
    if (i < n) split4(src, hi, lo, i);
}

__global__ __launch_bounds__(256)
void split_w4(const float* w0, const float* w1, const float* w2, const float* w3,
              __nv_bfloat16* h0, __nv_bfloat16* l0, __nv_bfloat16* h1, __nv_bfloat16* l1,
              __nv_bfloat16* h2, __nv_bfloat16* l2, __nv_bfloat16* h3, __nv_bfloat16* l3)
{
    const float* src; __nv_bfloat16 *hi, *lo;
    switch (blockIdx.y) {
        case 0: src = w0; hi = h0; lo = l0; break;
        case 1: src = w1; hi = h1; lo = l1; break;
        case 2: src = w2; hi = h2; lo = l2; break;
        default: src = w3; hi = h3; lo = l3; break;
    }
    int i = (blockIdx.x * 256 + threadIdx.x) * 4;
    if (i < Dd*Dd) split4(src, hi, lo, i);
}

// ---------------------------------------------------------------------------
// HMMA bf16x3 GEMM: C = (Ah+Al) @ (Bh+Bl)^T. Two epilogues:
//   SPLIT=0: fp32 + bias -> C
//   SPLIT=1: (scale*C) split into bf16 hi/lo -> Ch, Cl
// Tile 128x128x32, 8 warps, warp tile 64x32, 2-stage cp.async.
// __launch_bounds__(256,2): 2 CTAs/SM (smem 64KB, regs capped at 128).
// ---------------------------------------------------------------------------
#define GM 128
#define GN 128
#define GKC 32
#define NCHUNK (Dd / GKC)        // 32
#define TILEB (128 * GKC * 2)    // 8192
#define STAGEB (4 * TILEB)       // 32KB: AH | AL | BH | BL
#define GEMM_SMEM (2 * STAGEB)   // 64KB

__device__ __forceinline__ uint32_t sw_addr(uint32_t base, int row, int unit) {
    return base + row * 64 + ((unit ^ ((row >> 1) & 3)) << 4);
}

__device__ __forceinline__ void cp_tile(uint32_t sdst, const __nv_bfloat16* __restrict__ g,
                                        int tid)
{
    #pragma unroll
    for (int i = 0; i < 2; i++) {
        int u   = tid + i * 256;
        int row = u >> 2;
        int cu  = u & 3;
        CP_ASYNC16(sw_addr(sdst, row, cu), g + (size_t)row * Dd + cu * 8);
    }
}

template<int SPLIT>
__device__ __forceinline__ void gemm_tc_body(
    const __nv_bfloat16* __restrict__ Ah, const __nv_bfloat16* __restrict__ Al,
    const __nv_bfloat16* __restrict__ Bh, const __nv_bfloat16* __restrict__ Bl,
    const float* __restrict__ bias, float* __restrict__ C,
    __nv_bfloat16* __restrict__ Ch, __nv_bfloat16* __restrict__ Cl, float scale)
{
    extern __shared__ char smem[];
    const uint32_t sb = smem_u32(smem);
    const int tid = threadIdx.x;
    const int wid = tid >> 5;
    const int lid = tid & 31;
    const int wm  = wid >> 2;
    const int wn  = wid & 3;
    const int m0  = blockIdx.y * GM;
    const int n0  = blockIdx.x * GN;

    const __nv_bfloat16* gAh = Ah + (size_t)m0 * Dd;
    const __nv_bfloat16* gAl = Al + (size_t)m0 * Dd;
    const __nv_bfloat16* gBh = Bh + (size_t)n0 * Dd;
    const __nv_bfloat16* gBl = Bl + (size_t)n0 * Dd;

    float acc[4][4][4];
    #pragma unroll
    for (int i = 0; i < 4; i++)
        #pragma unroll
        for (int j = 0; j < 4; j++)
            #pragma unroll
            for (int k = 0; k < 4; k++) acc[i][j][k] = 0.f;

    const int a_row = wm * 64 + (lid & 15);
    const int a_ku  = lid >> 4;
    const int b_row = wn * 32 + (lid & 7) + ((lid >> 4) << 3);
    const int b_ku  = (lid >> 3) & 1;

    {
        uint32_t s = sb;
        cp_tile(s,             gAh, tid);
        cp_tile(s + TILEB,     gAl, tid);
        cp_tile(s + 2*TILEB,   gBh, tid);
        cp_tile(s + 3*TILEB,   gBl, tid);
        CP_COMMIT();
    }

    for (int c = 0; c < NCHUNK; c++) {
        if (c + 1 < NCHUNK) {
            uint32_t s = sb + ((c + 1) & 1) * STAGEB;
            const int kc = (c + 1) * GKC;
            cp_tile(s,           gAh + kc, tid);
            cp_tile(s + TILEB,   gAl + kc, tid);
            cp_tile(s + 2*TILEB, gBh + kc, tid);
            cp_tile(s + 3*TILEB, gBl + kc, tid);
            CP_COMMIT();
            CP_WAIT(1);
        } else {
            CP_WAIT(0);
        }
        __syncthreads();

        const uint32_t sa_h = sb + (c & 1) * STAGEB;
        const uint32_t sa_l = sa_h + TILEB;
        const uint32_t sbh  = sa_h + 2*TILEB;
        const uint32_t sbl  = sa_h + 3*TILEB;

        #pragma unroll
        for (int ks = 0; ks < 2; ks++) {
            const int ku = ks * 2;
            uint32_t bh[8], bl[8];
            #pragma unroll
            for (int pr = 0; pr < 2; pr++) {
                ldm_x4(bh[pr*4+0], bh[pr*4+1], bh[pr*4+2], bh[pr*4+3],
                       sw_addr(sbh, b_row + pr*16, ku + b_ku));
                ldm_x4(bl[pr*4+0], bl[pr*4+1], bl[pr*4+2], bl[pr*4+3],
                       sw_addr(sbl, b_row + pr*16, ku + b_ku));
            }
            #pragma unroll
            for (int mt = 0; mt < 4; mt++) {
                uint32_t ah[4], al[4];
                ldm_x4(ah[0], ah[1], ah[2], ah[3],
                       sw_addr(sa_h, a_row + mt*16, ku + a_ku));
                ldm_x4(al[0], al[1], al[2], al[3],
                       sw_addr(sa_l, a_row + mt*16, ku + a_ku));
                #pragma unroll
                for (int nt = 0; nt < 4; nt++) {
                    mma16816(acc[mt][nt], ah, &bh[nt*2]);
                    mma16816(acc[mt][nt], al, &bh[nt*2]);
                    mma16816(acc[mt][nt], ah, &bl[nt*2]);
                }
            }
        }
        __syncthreads();
    }

    #pragma unroll
    for (int mt = 0; mt < 4; mt++) {
        const int row = m0 + wm*64 + mt*16 + (lid >> 2);
        #pragma unroll
        for (int nt = 0; nt < 4; nt++) {
            const int col = n0 + wn*32 + nt*8 + (lid & 3)*2;
            if (SPLIT) {
                #pragma unroll
                for (int half = 0; half < 2; half++) {
                    const int r = row + half * 8;
                    float va = acc[mt][nt][half*2+0] * scale;
                    float vb = acc[mt][nt][half*2+1] * scale;
                    __nv_bfloat16 ha = __float2bfloat16(va);
                    __nv_bfloat16 hb = __float2bfloat16(vb);
                    __nv_bfloat16 la = __float2bfloat16(va - __bfloat162float(ha));
                    __nv_bfloat16 lb = __float2bfloat16(vb - __bfloat162float(hb));
                    *(__nv_bfloat162*)(Ch + (size_t)r * Dd + col) = __halves2bfloat162(ha, hb);
                    *(__nv_bfloat162*)(Cl + (size_t)r * Dd + col) = __halves2bfloat162(la, lb);
                }
            } else {
                float2 v0 = make_float2(acc[mt][nt][0], acc[mt][nt][1]);
                float2 v1 = make_float2(acc[mt][nt][2], acc[mt][nt][3]);
                float2 bv = *(const float2*)(bias + col);
                v0.x += bv.x; v0.y += bv.y;
                v1.x += bv.x; v1.y += bv.y;
                *(float2*)(C + (size_t)row * Dd + col)       = v0;
                *(float2*)(C + (size_t)(row + 8) * Dd + col) = v1;
            }
        }
    }
}

__global__ __launch_bounds__(256, 2)
void gemm_qkv_tc()
{
    const __nv_bfloat16 *Bh, *Bl; __nv_bfloat16 *Ch, *Cl; float sc;
    if (blockIdx.z == 0)      { Bh = g_wqh; Bl = g_wql; Ch = g_Qh; Cl = g_Ql; sc = 0.125f; }
    else if (blockIdx.z == 1) { Bh = g_wkh; Bl = g_wkl; Ch = g_Kh; Cl = g_Kl; sc = 1.f; }
    else                      { Bh = g_wvh; Bl = g_wvl; Ch = g_Vh; Cl = g_Vl; sc = 1.f; }
    gemm_tc_body<1>(g_xh, g_xl, Bh, Bl, nullptr, nullptr, Ch, Cl, sc);
}

__global__ __launch_bounds__(256, 2)
void gemm_o_tc(const float* bias, float* out)
{
    gemm_tc_body<0>(g_aoh, g_aol, g_woh, g_wol, bias, out, nullptr, nullptr, 1.f);
}

// ---------------------------------------------------------------------------
// HMMA flash attention. Block = 128 q rows of one (b,h); 8 warps x 16 rows.
// KV chunks of 64 keys, 2-stage cp.async. x3 error correction on QK^T and PV.
// __launch_bounds__(256,2): 2 CTAs/SM (smem 96KB, regs capped at 128).
// ---------------------------------------------------------------------------
#define AQ 128
#define AKC 64
#define SQH 0
#define SQL 16384
#define SKV 32768
#define KVSTAGE 32768   // KH 0 | KL 8192 | VH 16384 | VL 24576
#define ATT_SMEM (SKV + 2 * KVSTAGE)   // 98304

__device__ __forceinline__ uint32_t asw(uint32_t base, int row, int unit) {
    return base + row * 128 + ((unit ^ (row & 7)) << 4);
}

__device__ __forceinline__ void cp_kv(uint32_t sbase, int brow0, int h, int tid)
{
    #pragma unroll
    for (int i = 0; i < 2; i++) {
        int u = tid + i * 256;
        int row = u >> 3;
        int un = u & 7;
        size_t g = ((size_t)(brow0 + row)) * Dd + h * HD + un * 8;
        CP_ASYNC16(asw(sbase,          row, un), g_Kh + g);
        CP_ASYNC16(asw(sbase +  8192,  row, un), g_Kl + g);
        CP_ASYNC16(asw(sbase + 16384,  row, un), g_Vh + g);
        CP_ASYNC16(asw(sbase + 24576,  row, un), g_Vl + g);
    }
    CP_COMMIT();
}

__global__ __launch_bounds__(256, 2)
void attn_mma()
{
    extern __shared__ char smem[];
    const uint32_t sb = smem_u32(smem);
    const int tid = threadIdx.x;
    const int wid = tid >> 5;
    const int lid = tid & 31;
    const int q0  = blockIdx.x * AQ;
    const int b   = blockIdx.y >> 4;
    const int h   = blockIdx.y & 15;

    // stage Q (hi/lo): 128 rows x 8 units each
    #pragma unroll
    for (int i = 0; i < 4; i++) {
        int u = tid + i * 256;
        int row = u >> 3;
        int un = u & 7;
        size_t g = ((size_t)(b * Ss + q0 + row)) * Dd + h * HD + un * 8;
        CP_ASYNC16(asw(sb + SQH, row, un), g_Qh + g);
        CP_ASYNC16(asw(sb + SQL, row, un), g_Ql + g);
    }
    CP_COMMIT();

    // prologue KV chunk 0
    cp_kv(sb + SKV, b * Ss, h, tid);

    CP_WAIT(1);   // Q resident
    __syncthreads();

    // Q fragments for this warp's 16 rows (4 k-tiles, hi/lo)
    uint32_t qh[4][4], ql[4][4];
    {
        const int r = wid * 16 + (lid & 15);
        const int ub = lid >> 4;
        #pragma unroll
        for (int ks = 0; ks < 4; ks++) {
            ldm_x4(qh[ks][0], qh[ks][1], qh[ks][2], qh[ks][3],
                   asw(sb + SQH, r, ks*2 + ub));
            ldm_x4(ql[ks][0], ql[ks][1], ql[ks][2], ql[ks][3],
                   asw(sb + SQL, r, ks*2 + ub));
        }
    }

    float o[8][4];
    #pragma unroll
    for (int i = 0; i < 8; i++)
        #pragma unroll
        for (int j = 0; j < 4; j++) o[i][j] = 0.f;
    float m0 = -CUDART_INF_F, m1 = -CUDART_INF_F, l0 = 0.f, l1 = 0.f;

    const int kb_row = (lid & 7) + ((lid >> 4) << 3);
    const int kb_ku  = (lid >> 3) & 1;
    const int v_row  = lid & 15;
    const int v_ub   = lid >> 4;

    const int NC = Ss / AKC;    // 32
    for (int c = 0; c < NC; c++) {
        if (c + 1 < NC) {
            cp_kv(sb + SKV + ((c + 1) & 1) * KVSTAGE, b * Ss + (c + 1) * AKC, h, tid);
            CP_WAIT(1);
        } else {
            CP_WAIT(0);
        }
        __syncthreads();

        const uint32_t skh = sb + SKV + (c & 1) * KVSTAGE;
        const uint32_t skl = skh + 8192;
        const uint32_t svh = skh + 16384;
        const uint32_t svl = skh + 24576;

        // S = Q K^T  (x3 corrected), 16x64 per warp
        float s[8][4];
        #pragma unroll
        for (int i = 0; i < 8; i++)
            #pragma unroll
            for (int j = 0; j < 4; j++) s[i][j] = 0.f;

        #pragma unroll
        for (int ks = 0; ks < 4; ks++) {
            #pragma unroll
            for (int g = 0; g < 4; g++) {
                uint32_t kh4[4], kl4[4];
                ldm_x4(kh4[0], kh4[1], kh4[2], kh4[3],
                       asw(skh, g*16 + kb_row, ks*2 + kb_ku));
                ldm_x4(kl4[0], kl4[1], kl4[2], kl4[3],
                       asw(skl, g*16 + kb_row, ks*2 + kb_ku));
                mma16816(s[2*g],   qh[ks], &kh4[0]);
                mma16816(s[2*g],   ql[ks], &kh4[0]);
                mma16816(s[2*g],   qh[ks], &kl4[0]);
                mma16816(s[2*g+1], qh[ks], &kh4[2]);
                mma16816(s[2*g+1], ql[ks], &kh4[2]);
                mma16816(s[2*g+1], qh[ks], &kl4[2]);
            }
        }

        // online softmax (rows r and r+8 per thread)
        float rm0 = fmaxf(s[0][0], s[0][1]);
        float rm1 = fmaxf(s[0][2], s[0][3]);
        #pragma unroll
        for (int nt = 1; nt < 8; nt++) {
            rm0 = fmaxf(rm0, fmaxf(s[nt][0], s[nt][1]));
            rm1 = fmaxf(rm1, fmaxf(s[nt][2], s[nt][3]));
        }
        rm0 = fmaxf(rm0, __shfl_xor_sync(0xffffffffu, rm0, 1));
        rm0 = fmaxf(rm0, __shfl_xor_sync(0xffffffffu, rm0, 2));
        rm1 = fmaxf(rm1, __shfl_xor_sync(0xffffffffu, rm1, 1));
        rm1 = fmaxf(rm1, __shfl_xor_sync(0xffffffffu, rm1, 2));
        const float mn0 = fmaxf(m0, rm0);
        const float mn1 = fmaxf(m1, rm1);
        const float c0 = __expf(m0 - mn0);
        const float c1 = __expf(m1 - mn1);
        float sum0 = 0.f, sum1 = 0.f;
        #pragma unroll
        for (int nt = 0; nt < 8; nt++) {
            s[nt][0] = __expf(s[nt][0] - mn0); sum0 += s[nt][0];
            s[nt][1] = __expf(s[nt][1] - mn0); sum0 += s[nt][1];
            s[nt][2] = __expf(s[nt][2] - mn1); sum1 += s[nt][2];
            s[nt][3] = __expf(s[nt][3] - mn1); sum1 += s[nt][3];
            o[nt][0] *= c0; o[nt][1] *= c0;
            o[nt][2] *= c1; o[nt][3] *= c1;
        }
        sum0 += __shfl_xor_sync(0xffffffffu, sum0, 1);
        sum0 += __shfl_xor_sync(0xffffffffu, sum0, 2);
        sum1 += __shfl_xor_sync(0xffffffffu, sum1, 1);
        sum1 += __shfl_xor_sync(0xffffffffu, sum1, 2);
        l0 = l0 * c0 + sum0;
        l1 = l1 * c1 + sum1;
        m0 = mn0; m1 = mn1;

        // O += P V  (x3 corrected)
        #pragma unroll
        for (int kt = 0; kt < 4; kt++) {
            uint32_t pah[4], pal[4];
            {
                const float* t0 = s[2*kt];
                const float* t1 = s[2*kt+1];
                pah[0] = pk_bf2(t0[0], t0[1]);
                pah[1] = pk_bf2(t0[2], t0[3]);
                pah[2] = pk_bf2(t1[0], t1[1]);
                pah[3] = pk_bf2(t1[2], t1[3]);
                pal[0] = pk_bf2(t0[0]-bf_trunc(t0[0]), t0[1]-bf_trunc(t0[1]));
                pal[1] = pk_bf2(t0[2]-bf_trunc(t0[2]), t0[3]-bf_trunc(t0[3]));
                pal[2] = pk_bf2(t1[0]-bf_trunc(t1[0]), t1[1]-bf_trunc(t1[1]));
                pal[3] = pk_bf2(t1[2]-bf_trunc(t1[2]), t1[3]-bf_trunc(t1[3]));
            }
            #pragma unroll
            for (int db = 0; db < 4; db++) {
                uint32_t vh4[4], vl4[4];
                ldm_x4_t(vh4[0], vh4[1], vh4[2], vh4[3],
                         asw(svh, kt*16 + v_row, db*2 + v_ub));
                ldm_x4_t(vl4[0], vl4[1], vl4[2], vl4[3],
                         asw(svl, kt*16 + v_row, db*2 + v_ub));
                mma16816(o[2*db + 0], pah, &vh4[0]);
                mma16816(o[2*db + 0], pal, &vh4[0]);
                mma16816(o[2*db + 0], pah, &vl4[0]);
                mma16816(o[2*db + 1], pah, &vh4[2]);
                mma16816(o[2*db + 1], pal, &vh4[2]);
                mma16816(o[2*db + 1], pah, &vl4[2]);
            }
        }
        __syncthreads();
    }

    // normalize + write AO hi/lo
    const float inv0 = 1.f / l0;
    const float inv1 = 1.f / l1;
    const int gr0 = b * Ss + q0 + wid*16 + (lid >> 2);
    #pragma unroll
    for (int nt = 0; nt < 8; nt++) {
        const int col = h * HD + nt*8 + (lid & 3)*2;
        float va = o[nt][0] * inv0, vb = o[nt][1] * inv0;
        float vc = o[nt][2] * inv1, vd = o[nt][3] * inv1;
        __nv_bfloat16 ha = __float2bfloat16(va), hb = __float2bfloat16(vb);
        __nv_bfloat16 hc = __float2bfloat16(vc), hd = __float2bfloat16(vd);
        *(__nv_bfloat162*)(g_aoh + (size_t)gr0 * Dd + col) = __halves2bfloat162(ha, hb);
        *(__nv_bfloat162*)(g_aol + (size_t)gr0 * Dd + col) =
            __halves2bfloat162(__float2bfloat16(va - __bfloat162float(ha)),
                               __float2bfloat16(vb - __bfloat162float(hb)));
        *(__nv_bfloat162*)(g_aoh + (size_t)(gr0 + 8) * Dd + col) = __halves2bfloat162(hc, hd);
        *(__nv_bfloat162*)(g_aol + (size_t)(gr0 + 8) * Dd + col) =
            __halves2bfloat162(__float2bfloat16(vc - __bfloat162float(hc)),
                               __float2bfloat16(vd - __bfloat162float(hd)));
    }
}

// ---------------------------------------------------------------------------
extern "C" void kernel_launch(void* const* d_in, const int* in_sizes, int n_in,
                              void* d_out, int out_size)
{
    const float* x  = (const float*)d_in[0];
    const float* Wq = (const float*)d_in[1];
    const float* Wk = (const float*)d_in[2];
    const float* Wv = (const float*)d_in[3];
    const float* Wo = (const float*)d_in[4];
    const float* bo = (const float*)d_in[5];
    float* out = (float*)d_out;

    cudaFuncSetAttribute(gemm_qkv_tc, cudaFuncAttributeMaxDynamicSharedMemorySize, GEMM_SMEM);
    cudaFuncSetAttribute(gemm_o_tc,   cudaFuncAttributeMaxDynamicSharedMemorySize, GEMM_SMEM);
    cudaFuncSetAttribute(attn_mma,    cudaFuncAttributeMaxDynamicSharedMemorySize, ATT_SMEM);

    void *pxh, *pxl, *pqh, *pql, *pkh, *pkl, *pvh, *pvl, *poh, *pol;
    cudaGetSymbolAddress(&pxh, g_xh);  cudaGetSymbolAddress(&pxl, g_xl);
    cudaGetSymbolAddress(&pqh, g_wqh); cudaGetSymbolAddress(&pql, g_wql);
    cudaGetSymbolAddress(&pkh, g_wkh); cudaGetSymbolAddress(&pkl, g_wkl);
    cudaGetSymbolAddress(&pvh, g_wvh); cudaGetSymbolAddress(&pvl, g_wvl);
    cudaGetSymbolAddress(&poh, g_woh); cudaGetSymbolAddress(&pol, g_wol);

    // 1) split fp32 inputs -> bf16 hi/lo (x, then all 4 weights in one launch)
    split_bf16<<<(Mtot*Dd)/1024, 256>>>(x, (__nv_bfloat16*)pxh, (__nv_bfloat16*)pxl, Mtot*Dd);
    dim3 gsw((Dd*Dd)/1024, 4);
    split_w4<<<gsw, 256>>>(Wq, Wk, Wv, Wo,
        (__nv_bfloat16*)pqh, (__nv_bfloat16*)pql,
        (__nv_bfloat16*)pkh, (__nv_bfloat16*)pkl,
        (__nv_bfloat16*)pvh, (__nv_bfloat16*)pvl,
        (__nv_bfloat16*)poh, (__nv_bfloat16*)pol);

    // 2) QKV projections -> bf16 hi/lo (Q pre-scaled by 1/sqrt(HD))
    dim3 gqkv(Dd / GN, Mtot / GM, 3);
    gemm_qkv_tc<<<gqkv, 256, GEMM_SMEM>>>();

    // 3) HMMA flash attention -> AO hi/lo
    dim3 gattn(Ss / AQ, Bb * Hh);
    attn_mma<<<gattn, 256, ATT_SMEM>>>();

    // 4) output projection (+bias) -> fp32 out
    dim3 gout(Dd / GN, Mtot / GM, 1);
    gemm_o_tc<<<gout, 256, GEMM_SMEM>>>(bo, out);
}

// round 9
// speedup vs baseline: 1.1494x; 1.0214x over previous
#include <cuda_runtime.h>
#include <cuda_bf16.h>
#include <math_constants.h>
#include <cstdint>

// Problem constants
#define Bb 2
#define Ss 2048
#define Dd 1024
#define Hh 16
#define HD 64
#define Mtot (Bb*Ss)   // 4096 rows

// ---------------------------------------------------------------------------
// Scratch (__device__ globals; allocation-free rule)
// ---------------------------------------------------------------------------
__device__ __nv_bfloat16 g_xh [Mtot*Dd], g_xl [Mtot*Dd];
__device__ __nv_bfloat16 g_wqh[Dd*Dd],   g_wql[Dd*Dd];
__device__ __nv_bfloat16 g_wkh[Dd*Dd],   g_wkl[Dd*Dd];
__device__ __nv_bfloat16 g_wvh[Dd*Dd],   g_wvl[Dd*Dd];
__device__ __nv_bfloat16 g_woh[Dd*Dd],   g_wol[Dd*Dd];
__device__ __nv_bfloat16 g_Qh [Mtot*Dd], g_Ql [Mtot*Dd];   // pre-scaled by 0.125*log2(e)
__device__ __nv_bfloat16 g_Kh [Mtot*Dd], g_Kl [Mtot*Dd];
__device__ __nv_bfloat16 g_Vh [Mtot*Dd], g_Vl [Mtot*Dd];
__device__ __nv_bfloat16 g_aoh[Mtot*Dd], g_aol[Mtot*Dd];

// ---------------------------------------------------------------------------
// PTX helpers (compute_103-safe: ldmatrix / mma.sync / cp.async)
// ---------------------------------------------------------------------------
__device__ __forceinline__ uint32_t smem_u32(const void* p) {
    uint32_t a;
    asm("{ .reg .u64 t; cvta.to.shared.u64 t, %1; cvt.u32.u64 %0, t; }"
        : "=r"(a) : "l"(p));
    return a;
}

__device__ __forceinline__ void ldm_x4(uint32_t& r0, uint32_t& r1,
                                       uint32_t& r2, uint32_t& r3, uint32_t addr) {
    asm volatile("ldmatrix.sync.aligned.m8n8.x4.shared.b16 {%0,%1,%2,%3}, [%4];"
                 : "=r"(r0), "=r"(r1), "=r"(r2), "=r"(r3) : "r"(addr));
}

__device__ __forceinline__ void ldm_x4_t(uint32_t& r0, uint32_t& r1,
                                         uint32_t& r2, uint32_t& r3, uint32_t addr) {
    asm volatile("ldmatrix.sync.aligned.m8n8.x4.trans.shared.b16 {%0,%1,%2,%3}, [%4];"
                 : "=r"(r0), "=r"(r1), "=r"(r2), "=r"(r3) : "r"(addr));
}

__device__ __forceinline__ void mma16816(float* c, const uint32_t* a, const uint32_t* b) {
    asm volatile(
        "mma.sync.aligned.m16n8k16.row.col.f32.bf16.bf16.f32 "
        "{%0,%1,%2,%3}, {%4,%5,%6,%7}, {%8,%9}, {%0,%1,%2,%3};"
        : "+f"(c[0]), "+f"(c[1]), "+f"(c[2]), "+f"(c[3])
        : "r"(a[0]), "r"(a[1]), "r"(a[2]), "r"(a[3]), "r"(b[0]), "r"(b[1]));
}

#define CP_ASYNC16(dst, src) \
    asm volatile("cp.async.cg.shared.global [%0], [%1], 16;" :: "r"(dst), "l"(src))
#define CP_COMMIT() asm volatile("cp.async.commit_group;" ::: "memory")
#define CP_WAIT(n)  asm volatile("cp.async.wait_group %0;" :: "n"(n) : "memory")

// pack two fp32 -> bf16x2 reg (first arg in low half)
__device__ __forceinline__ uint32_t pk_bf2(float lo, float hi) {
    uint32_t r;
    asm("cvt.rn.bf16x2.f32 %0, %1, %2;" : "=r"(r) : "f"(hi), "f"(lo));
    return r;
}

// pack (a,b) to bf16x2 hi-part + residual lo-part (residual via bit-unpack)
__device__ __forceinline__ void pack_hl(float a, float b, uint32_t& ph, uint32_t& pl) {
    ph = pk_bf2(a, b);
    float ra = a - __uint_as_float(ph << 16);
    float rb = b - __uint_as_float(ph & 0xffff0000u);
    pl = pk_bf2(ra, rb);
}

// ---------------------------------------------------------------------------
// fp32 -> bf16 hi/lo split kernels
// ---------------------------------------------------------------------------
__device__ __forceinline__ void split4(const float* __restrict__ src,
                                       __nv_bfloat16* __restrict__ hi,
                                       __nv_bfloat16* __restrict__ lo, int i)
{
    float4 v = *(const float4*)(src + i);
    __nv_bfloat16 ha = __float2bfloat16(v.x);
    __nv_bfloat16 hb = __float2bfloat16(v.y);
    __nv_bfloat16 hc = __float2bfloat16(v.z);
    __nv_bfloat16 hd = __float2bfloat16(v.w);
    __nv_bfloat16 la = __float2bfloat16(v.x - __bfloat162float(ha));
    __nv_bfloat16 lb = __float2bfloat16(v.y - __bfloat162float(hb));
    __nv_bfloat16 lc = __float2bfloat16(v.z - __bfloat162float(hc));
    __nv_bfloat16 ld = __float2bfloat16(v.w - __bfloat162float(hd));
    *(__nv_bfloat162*)(hi + i)     = __halves2bfloat162(ha, hb);
    *(__nv_bfloat162*)(hi + i + 2) = __halves2bfloat162(hc, hd);
    *(__nv_bfloat162*)(lo + i)     = __halves2bfloat162(la, lb);
    *(__nv_bfloat162*)(lo + i + 2) = __halves2bfloat162(lc, ld);
}

__global__ __launch_bounds__(256)
void split_bf16(const float* __restrict__ src,
                __nv_bfloat16* __restrict__ hi,
                __nv_bfloat16* __restrict__ lo, int n)
{
    int i = (blockIdx.x * 256 + threadIdx.x) * 4;
    if (i < n) split4(src, hi, lo, i);
}

__global__ __launch_bounds__(256)
void split_w4(const float* w0, const float* w1, const float* w2, const float* w3,
              __nv_bfloat16* h0, __nv_bfloat16* l0, __nv_bfloat16* h1, __nv_bfloat16* l1,
              __nv_bfloat16* h2, __nv_bfloat16* l2, __nv_bfloat16* h3, __nv_bfloat16* l3)
{
    const float* src; __nv_bfloat16 *hi, *lo;
    switch (blockIdx.y) {
        case 0: src = w0; hi = h0; lo = l0; break;
        case 1: src = w1; hi = h1; lo = l1; break;
        case 2: src = w2; hi = h2; lo = l2; break;
        default: src = w3; hi = h3; lo = l3; break;
    }
    int i = (blockIdx.x * 256 + threadIdx.x) * 4;
    if (i < Dd*Dd) split4(src, hi, lo, i);
}

// ---------------------------------------------------------------------------
// HMMA bf16x3 GEMM: C = (Ah+Al) @ (Bh+Bl)^T. Two epilogues:
//   SPLIT=0: fp32 + bias -> C
//   SPLIT=1: (scale*C) split into bf16 hi/lo -> Ch, Cl
// Tile 128x128x32, 8 warps, warp tile 64x32, 2-stage cp.async, 2 CTAs/SM.
// ---------------------------------------------------------------------------
#define GM 128
#define GN 128
#define GKC 32
#define NCHUNK (Dd / GKC)        // 32
#define TILEB (128 * GKC * 2)    // 8192
#define STAGEB (4 * TILEB)       // 32KB: AH | AL | BH | BL
#define GEMM_SMEM (2 * STAGEB)   // 64KB

__device__ __forceinline__ uint32_t sw_addr(uint32_t base, int row, int unit) {
    return base + row * 64 + ((unit ^ ((row >> 1) & 3)) << 4);
}

__device__ __forceinline__ void cp_tile(uint32_t sdst, const __nv_bfloat16* __restrict__ g,
                                        int tid)
{
    #pragma unroll
    for (int i = 0; i < 2; i++) {
        int u   = tid + i * 256;
        int row = u >> 2;
        int cu  = u & 3;
        CP_ASYNC16(sw_addr(sdst, row, cu), g + (size_t)row * Dd + cu * 8);
    }
}

template<int SPLIT>
__device__ __forceinline__ void gemm_tc_body(
    const __nv_bfloat16* __restrict__ Ah, const __nv_bfloat16* __restrict__ Al,
    const __nv_bfloat16* __restrict__ Bh, const __nv_bfloat16* __restrict__ Bl,
    const float* __restrict__ bias, float* __restrict__ C,
    __nv_bfloat16* __restrict__ Ch, __nv_bfloat16* __restrict__ Cl, float scale)
{
    extern __shared__ char smem[];
    const uint32_t sb = smem_u32(smem);
    const int tid = threadIdx.x;
    const int wid = tid >> 5;
    const int lid = tid & 31;
    const int wm  = wid >> 2;
    const int wn  = wid & 3;
    const int m0  = blockIdx.y * GM;
    const int n0  = blockIdx.x * GN;

    const __nv_bfloat16* gAh = Ah + (size_t)m0 * Dd;
    const __nv_bfloat16* gAl = Al + (size_t)m0 * Dd;
    const __nv_bfloat16* gBh = Bh + (size_t)n0 * Dd;
    const __nv_bfloat16* gBl = Bl + (size_t)n0 * Dd;

    float acc[4][4][4];
    #pragma unroll
    for (int i = 0; i < 4; i++)
        #pragma unroll
        for (int j = 0; j < 4; j++)
            #pragma unroll
            for (int k = 0; k < 4; k++) acc[i][j][k] = 0.f;

    const int a_row = wm * 64 + (lid & 15);
    const int a_ku  = lid >> 4;
    const int b_row = wn * 32 + (lid & 7) + ((lid >> 4) << 3);
    const int b_ku  = (lid >> 3) & 1;

    {
        uint32_t s = sb;
        cp_tile(s,             gAh, tid);
        cp_tile(s + TILEB,     gAl, tid);
        cp_tile(s + 2*TILEB,   gBh, tid);
        cp_tile(s + 3*TILEB,   gBl, tid);
        CP_COMMIT();
    }

    for (int c = 0; c < NCHUNK; c++) {
        if (c + 1 < NCHUNK) {
            uint32_t s = sb + ((c + 1) & 1) * STAGEB;
            const int kc = (c + 1) * GKC;
            cp_tile(s,           gAh + kc, tid);
            cp_tile(s + TILEB,   gAl + kc, tid);
            cp_tile(s + 2*TILEB, gBh + kc, tid);
            cp_tile(s + 3*TILEB, gBl + kc, tid);
            CP_COMMIT();
            CP_WAIT(1);
        } else {
            CP_WAIT(0);
        }
        __syncthreads();

        const uint32_t sa_h = sb + (c & 1) * STAGEB;
        const uint32_t sa_l = sa_h + TILEB;
        const uint32_t sbh  = sa_h + 2*TILEB;
        const uint32_t sbl  = sa_h + 3*TILEB;

        #pragma unroll
        for (int ks = 0; ks < 2; ks++) {
            const int ku = ks * 2;
            uint32_t bh[8], bl[8];
            #pragma unroll
            for (int pr = 0; pr < 2; pr++) {
                ldm_x4(bh[pr*4+0], bh[pr*4+1], bh[pr*4+2], bh[pr*4+3],
                       sw_addr(sbh, b_row + pr*16, ku + b_ku));
                ldm_x4(bl[pr*4+0], bl[pr*4+1], bl[pr*4+2], bl[pr*4+3],
                       sw_addr(sbl, b_row + pr*16, ku + b_ku));
            }
            #pragma unroll
            for (int mt = 0; mt < 4; mt++) {
                uint32_t ah[4], al[4];
                ldm_x4(ah[0], ah[1], ah[2], ah[3],
                       sw_addr(sa_h, a_row + mt*16, ku + a_ku));
                ldm_x4(al[0], al[1], al[2], al[3],
                       sw_addr(sa_l, a_row + mt*16, ku + a_ku));
                #pragma unroll
                for (int nt = 0; nt < 4; nt++) {
                    mma16816(acc[mt][nt], ah, &bh[nt*2]);
                    mma16816(acc[mt][nt], al, &bh[nt*2]);
                    mma16816(acc[mt][nt], ah, &bl[nt*2]);
                }
            }
        }
        __syncthreads();
    }

    #pragma unroll
    for (int mt = 0; mt < 4; mt++) {
        const int row = m0 + wm*64 + mt*16 + (lid >> 2);
        #pragma unroll
        for (int nt = 0; nt < 4; nt++) {
            const int col = n0 + wn*32 + nt*8 + (lid & 3)*2;
            if (SPLIT) {
                #pragma unroll
                for (int half = 0; half < 2; half++) {
                    const int r = row + half * 8;
                    float va = acc[mt][nt][half*2+0] * scale;
                    float vb = acc[mt][nt][half*2+1] * scale;
                    uint32_t ph, pl;
                    pack_hl(va, vb, ph, pl);
                    *(uint32_t*)(Ch + (size_t)r * Dd + col) = ph;
                    *(uint32_t*)(Cl + (size_t)r * Dd + col) = pl;
                }
            } else {
                float2 v0 = make_float2(acc[mt][nt][0], acc[mt][nt][1]);
                float2 v1 = make_float2(acc[mt][nt][2], acc[mt][nt][3]);
                float2 bv = *(const float2*)(bias + col);
                v0.x += bv.x; v0.y += bv.y;
                v1.x += bv.x; v1.y += bv.y;
                *(float2*)(C + (size_t)row * Dd + col)       = v0;
                *(float2*)(C + (size_t)(row + 8) * Dd + col) = v1;
            }
        }
    }
}

__global__ __launch_bounds__(256, 2)
void gemm_qkv_tc()
{
    const __nv_bfloat16 *Bh, *Bl; __nv_bfloat16 *Ch, *Cl; float sc;
    // Q pre-scaled by (1/sqrt(HD)) * log2(e) so attention works in base-2
    if (blockIdx.z == 0)      { Bh = g_wqh; Bl = g_wql; Ch = g_Qh; Cl = g_Ql; sc = 0.18033688f; }
    else if (blockIdx.z == 1) { Bh = g_wkh; Bl = g_wkl; Ch = g_Kh; Cl = g_Kl; sc = 1.f; }
    else                      { Bh = g_wvh; Bl = g_wvl; Ch = g_Vh; Cl = g_Vl; sc = 1.f; }
    gemm_tc_body<1>(g_xh, g_xl, Bh, Bl, nullptr, nullptr, Ch, Cl, sc);
}

__global__ __launch_bounds__(256, 2)
void gemm_o_tc(const float* bias, float* out)
{
    gemm_tc_body<0>(g_aoh, g_aol, g_woh, g_wol, bias, out, nullptr, nullptr, 1.f);
}

// ---------------------------------------------------------------------------
// HMMA flash attention. Block = 128 q rows of one (b,h); 8 warps x 16 rows.
// KV chunks of 64 keys, 2-stage cp.async, 2 CTAs/SM. Base-2 softmax.
// Q-hi fragments register-resident; Q-lo reloaded per chunk (reg diet).
// ---------------------------------------------------------------------------
#define AQ 128
#define AKC 64
#define SQH 0
#define SQL 16384
#define SKV 32768
#define KVSTAGE 32768   // KH 0 | KL 8192 | VH 16384 | VL 24576
#define ATT_SMEM (SKV + 2 * KVSTAGE)   // 98304

__device__ __forceinline__ uint32_t asw(uint32_t base, int row, int unit) {
    return base + row * 128 + ((unit ^ (row & 7)) << 4);
}

__device__ __forceinline__ void cp_kv(uint32_t sbase, int brow0, int h, int tid)
{
    #pragma unroll
    for (int i = 0; i < 2; i++) {
        int u = tid + i * 256;
        int row = u >> 3;
        int un = u & 7;
        size_t g = ((size_t)(brow0 + row)) * Dd + h * HD + un * 8;
        CP_ASYNC16(asw(sbase,          row, un), g_Kh + g);
        CP_ASYNC16(asw(sbase +  8192,  row, un), g_Kl + g);
        CP_ASYNC16(asw(sbase + 16384,  row, un), g_Vh + g);
        CP_ASYNC16(asw(sbase + 24576,  row, un), g_Vl + g);
    }
    CP_COMMIT();
}

__global__ __launch_bounds__(256, 2)
void attn_mma()
{
    extern __shared__ char smem[];
    const uint32_t sb = smem_u32(smem);
    const int tid = threadIdx.x;
    const int wid = tid >> 5;
    const int lid = tid & 31;
    const int q0  = blockIdx.x * AQ;
    const int b   = blockIdx.y >> 4;
    const int h   = blockIdx.y & 15;

    // stage Q (hi/lo): 128 rows x 8 units each
    #pragma unroll
    for (int i = 0; i < 4; i++) {
        int u = tid + i * 256;
        int row = u >> 3;
        int un = u & 7;
        size_t g = ((size_t)(b * Ss + q0 + row)) * Dd + h * HD + un * 8;
        CP_ASYNC16(asw(sb + SQH, row, un), g_Qh + g);
        CP_ASYNC16(asw(sb + SQL, row, un), g_Ql + g);
    }
    CP_COMMIT();

    // prologue KV chunk 0
    cp_kv(sb + SKV, b * Ss, h, tid);

    CP_WAIT(1);   // Q resident
    __syncthreads();

    const int q_r  = wid * 16 + (lid & 15);
    const int q_ub = lid >> 4;

    // Q-hi fragments resident (16 regs); Q-lo reloaded per chunk from smem
    uint32_t qh[4][4];
    #pragma unroll
    for (int ks = 0; ks < 4; ks++)
        ldm_x4(qh[ks][0], qh[ks][1], qh[ks][2], qh[ks][3],
               asw(sb + SQH, q_r, ks*2 + q_ub));

    float o[8][4];
    #pragma unroll
    for (int i = 0; i < 8; i++)
        #pragma unroll
        for (int j = 0; j < 4; j++) o[i][j] = 0.f;
    float m0 = -CUDART_INF_F, m1 = -CUDART_INF_F, l0 = 0.f, l1 = 0.f;

    const int kb_row = (lid & 7) + ((lid >> 4) << 3);
    const int kb_ku  = (lid >> 3) & 1;
    const int v_row  = lid & 15;
    const int v_ub   = lid >> 4;

    const int NC = Ss / AKC;    // 32
    for (int c = 0; c < NC; c++) {
        if (c + 1 < NC) {
            cp_kv(sb + SKV + ((c + 1) & 1) * KVSTAGE, b * Ss + (c + 1) * AKC, h, tid);
            CP_WAIT(1);
        } else {
            CP_WAIT(0);
        }
        __syncthreads();

        const uint32_t skh = sb + SKV + (c & 1) * KVSTAGE;
        const uint32_t skl = skh + 8192;
        const uint32_t svh = skh + 16384;
        const uint32_t svl = skh + 24576;

        // S = Q K^T  (x3 corrected), 16x64 per warp; scores in log2 domain
        float s[8][4];
        #pragma unroll
        for (int i = 0; i < 8; i++)
            #pragma unroll
            for (int j = 0; j < 4; j++) s[i][j] = 0.f;

        #pragma unroll
        for (int ks = 0; ks < 4; ks++) {
            uint32_t ql4[4];
            ldm_x4(ql4[0], ql4[1], ql4[2], ql4[3],
                   asw(sb + SQL, q_r, ks*2 + q_ub));
            #pragma unroll
            for (int g = 0; g < 4; g++) {
                uint32_t kh4[4], kl4[4];
                ldm_x4(kh4[0], kh4[1], kh4[2], kh4[3],
                       asw(skh, g*16 + kb_row, ks*2 + kb_ku));
                ldm_x4(kl4[0], kl4[1], kl4[2], kl4[3],
                       asw(skl, g*16 + kb_row, ks*2 + kb_ku));
                mma16816(s[2*g],   qh[ks], &kh4[0]);
                mma16816(s[2*g],   ql4,    &kh4[0]);
                mma16816(s[2*g],   qh[ks], &kl4[0]);
                mma16816(s[2*g+1], qh[ks], &kh4[2]);
                mma16816(s[2*g+1], ql4,    &kh4[2]);
                mma16816(s[2*g+1], qh[ks], &kl4[2]);
            }
        }

        // online softmax, base 2 (rows r and r+8 per thread)
        float rm0 = fmaxf(s[0][0], s[0][1]);
        float rm1 = fmaxf(s[0][2], s[0][3]);
        #pragma unroll
        for (int nt = 1; nt < 8; nt++) {
            rm0 = fmaxf(rm0, fmaxf(s[nt][0], s[nt][1]));
            rm1 = fmaxf(rm1, fmaxf(s[nt][2], s[nt][3]));
        }
        rm0 = fmaxf(rm0, __shfl_xor_sync(0xffffffffu, rm0, 1));
        rm0 = fmaxf(rm0, __shfl_xor_sync(0xffffffffu, rm0, 2));
        rm1 = fmaxf(rm1, __shfl_xor_sync(0xffffffffu, rm1, 1));
        rm1 = fmaxf(rm1, __shfl_xor_sync(0xffffffffu, rm1, 2));
        const float mn0 = fmaxf(m0, rm0);
        const float mn1 = fmaxf(m1, rm1);
        const float c0 = exp2f(m0 - mn0);
        const float c1 = exp2f(m1 - mn1);
        float sum0 = 0.f, sum1 = 0.f;
        #pragma unroll
        for (int nt = 0; nt < 8; nt++) {
            s[nt][0] = exp2f(s[nt][0] - mn0); sum0 += s[nt][0];
            s[nt][1] = exp2f(s[nt][1] - mn0); sum0 += s[nt][1];
            s[nt][2] = exp2f(s[nt][2] - mn1); sum1 += s[nt][2];
            s[nt][3] = exp2f(s[nt][3] - mn1); sum1 += s[nt][3];
            o[nt][0] *= c0; o[nt][1] *= c0;
            o[nt][2] *= c1; o[nt][3] *= c1;
        }
        sum0 += __shfl_xor_sync(0xffffffffu, sum0, 1);
        sum0 += __shfl_xor_sync(0xffffffffu, sum0, 2);
        sum1 += __shfl_xor_sync(0xffffffffu, sum1, 1);
        sum1 += __shfl_xor_sync(0xffffffffu, sum1, 2);
        l0 = l0 * c0 + sum0;
        l1 = l1 * c1 + sum1;
        m0 = mn0; m1 = mn1;

        // O += P V  (x3 corrected)
        #pragma unroll
        for (int kt = 0; kt < 4; kt++) {
            uint32_t pah[4], pal[4];
            {
                const float* t0 = s[2*kt];
                const float* t1 = s[2*kt+1];
                pack_hl(t0[0], t0[1], pah[0], pal[0]);
                pack_hl(t0[2], t0[3], pah[1], pal[1]);
                pack_hl(t1[0], t1[1], pah[2], pal[2]);
                pack_hl(t1[2], t1[3], pah[3], pal[3]);
            }
            #pragma unroll
            for (int db = 0; db < 4; db++) {
                uint32_t vh4[4], vl4[4];
                ldm_x4_t(vh4[0], vh4[1], vh4[2], vh4[3],
                         asw(svh, kt*16 + v_row, db*2 + v_ub));
                ldm_x4_t(vl4[0], vl4[1], vl4[2], vl4[3],
                         asw(svl, kt*16 + v_row, db*2 + v_ub));
                mma16816(o[2*db + 0], pah, &vh4[0]);
                mma16816(o[2*db + 0], pal, &vh4[0]);
                mma16816(o[2*db + 0], pah, &vl4[0]);
                mma16816(o[2*db + 1], pah, &vh4[2]);
                mma16816(o[2*db + 1], pal, &vh4[2]);
                mma16816(o[2*db + 1], pah, &vl4[2]);
            }
        }
        __syncthreads();
    }

    // normalize + write AO hi/lo
    const float inv0 = 1.f / l0;
    const float inv1 = 1.f / l1;
    const int gr0 = b * Ss + q0 + wid*16 + (lid >> 2);
    #pragma unroll
    for (int nt = 0; nt < 8; nt++) {
        const int col = h * HD + nt*8 + (lid & 3)*2;
        float va = o[nt][0] * inv0, vb = o[nt][1] * inv0;
        float vc = o[nt][2] * inv1, vd = o[nt][3] * inv1;
        uint32_t ph0, pl0, ph1, pl1;
        pack_hl(va, vb, ph0, pl0);
        pack_hl(vc, vd, ph1, pl1);
        *(uint32_t*)(g_aoh + (size_t)gr0 * Dd + col)       = ph0;
        *(uint32_t*)(g_aol + (size_t)gr0 * Dd + col)       = pl0;
        *(uint32_t*)(g_aoh + (size_t)(gr0 + 8) * Dd + col) = ph1;
        *(uint32_t*)(g_aol + (size_t)(gr0 + 8) * Dd + col) = pl1;
    }
}

// ---------------------------------------------------------------------------
extern "C" void kernel_launch(void* const* d_in, const int* in_sizes, int n_in,
                              void* d_out, int out_size)
{
    const float* x  = (const float*)d_in[0];
    const float* Wq = (const float*)d_in[1];
    const float* Wk = (const float*)d_in[2];
    const float* Wv = (const float*)d_in[3];
    const float* Wo = (const float*)d_in[4];
    const float* bo = (const float*)d_in[5];
    float* out = (float*)d_out;

    cudaFuncSetAttribute(gemm_qkv_tc, cudaFuncAttributeMaxDynamicSharedMemorySize, GEMM_SMEM);
    cudaFuncSetAttribute(gemm_o_tc,   cudaFuncAttributeMaxDynamicSharedMemorySize, GEMM_SMEM);
    cudaFuncSetAttribute(attn_mma,    cudaFuncAttributeMaxDynamicSharedMemorySize, ATT_SMEM);

    void *pxh, *pxl, *pqh, *pql, *pkh, *pkl, *pvh, *pvl, *poh, *pol;
    cudaGetSymbolAddress(&pxh, g_xh);  cudaGetSymbolAddress(&pxl, g_xl);
    cudaGetSymbolAddress(&pqh, g_wqh); cudaGetSymbolAddress(&pql, g_wql);
    cudaGetSymbolAddress(&pkh, g_wkh); cudaGetSymbolAddress(&pkl, g_wkl);
    cudaGetSymbolAddress(&pvh, g_wvh); cudaGetSymbolAddress(&pvl, g_wvl);
    cudaGetSymbolAddress(&poh, g_woh); cudaGetSymbolAddress(&pol, g_wol);

    // 1) split fp32 inputs -> bf16 hi/lo (x, then all 4 weights in one launch)
    split_bf16<<<(Mtot*Dd)/1024, 256>>>(x, (__nv_bfloat16*)pxh, (__nv_bfloat16*)pxl, Mtot*Dd);
    dim3 gsw((Dd*Dd)/1024, 4);
    split_w4<<<gsw, 256>>>(Wq, Wk, Wv, Wo,
        (__nv_bfloat16*)pqh, (__nv_bfloat16*)pql,
        (__nv_bfloat16*)pkh, (__nv_bfloat16*)pkl,
        (__nv_bfloat16*)pvh, (__nv_bfloat16*)pvl,
        (__nv_bfloat16*)poh, (__nv_bfloat16*)pol);

    // 2) QKV projections -> bf16 hi/lo (Q pre-scaled by 0.125*log2e)
    dim3 gqkv(Dd / GN, Mtot / GM, 3);
    gemm_qkv_tc<<<gqkv, 256, GEMM_SMEM>>>();

    // 3) HMMA flash attention -> AO hi/lo
    dim3 gattn(Ss / AQ, Bb * Hh);
    attn_mma<<<gattn, 256, ATT_SMEM>>>();

    // 4) output projection (+bias) -> fp32 out
    dim3 gout(Dd / GN, Mtot / GM, 1);
    gemm_o_tc<<<gout, 256, GEMM_SMEM>>>(bo, out);
}

// round 10
// speedup vs baseline: 1.1660x; 1.0145x over previous
#include <cuda_runtime.h>
#include <cuda_bf16.h>
#include <math_constants.h>
#include <cstdint>

// Problem constants
#define Bb 2
#define Ss 2048
#define Dd 1024
#define Hh 16
#define HD 64
#define Mtot (Bb*Ss)   // 4096 rows

// ---------------------------------------------------------------------------
// Scratch (__device__ globals; allocation-free rule)
// ---------------------------------------------------------------------------
__device__ __nv_bfloat16 g_xh [Mtot*Dd], g_xl [Mtot*Dd];
__device__ __nv_bfloat16 g_wqh[Dd*Dd],   g_wql[Dd*Dd];
__device__ __nv_bfloat16 g_wkh[Dd*Dd],   g_wkl[Dd*Dd];
__device__ __nv_bfloat16 g_wvh[Dd*Dd],   g_wvl[Dd*Dd];
__device__ __nv_bfloat16 g_woh[Dd*Dd],   g_wol[Dd*Dd];
__device__ __nv_bfloat16 g_Qh [Mtot*Dd], g_Ql [Mtot*Dd];   // pre-scaled by 0.125*log2(e)
__device__ __nv_bfloat16 g_Kh [Mtot*Dd], g_Kl [Mtot*Dd];
__device__ __nv_bfloat16 g_Vh [Mtot*Dd], g_Vl [Mtot*Dd];
__device__ __nv_bfloat16 g_aoh[Mtot*Dd], g_aol[Mtot*Dd];

// ---------------------------------------------------------------------------
// PTX helpers (compute_103-safe: ldmatrix / mma.sync / cp.async)
// ---------------------------------------------------------------------------
__device__ __forceinline__ uint32_t smem_u32(const void* p) {
    uint32_t a;
    asm("{ .reg .u64 t; cvta.to.shared.u64 t, %1; cvt.u32.u64 %0, t; }"
        : "=r"(a) : "l"(p));
    return a;
}

__device__ __forceinline__ void ldm_x4(uint32_t& r0, uint32_t& r1,
                                       uint32_t& r2, uint32_t& r3, uint32_t addr) {
    asm volatile("ldmatrix.sync.aligned.m8n8.x4.shared.b16 {%0,%1,%2,%3}, [%4];"
                 : "=r"(r0), "=r"(r1), "=r"(r2), "=r"(r3) : "r"(addr));
}

__device__ __forceinline__ void ldm_x4_t(uint32_t& r0, uint32_t& r1,
                                         uint32_t& r2, uint32_t& r3, uint32_t addr) {
    asm volatile("ldmatrix.sync.aligned.m8n8.x4.trans.shared.b16 {%0,%1,%2,%3}, [%4];"
                 : "=r"(r0), "=r"(r1), "=r"(r2), "=r"(r3) : "r"(addr));
}

__device__ __forceinline__ void mma16816(float* c, const uint32_t* a, const uint32_t* b) {
    asm volatile(
        "mma.sync.aligned.m16n8k16.row.col.f32.bf16.bf16.f32 "
        "{%0,%1,%2,%3}, {%4,%5,%6,%7}, {%8,%9}, {%0,%1,%2,%3};"
        : "+f"(c[0]), "+f"(c[1]), "+f"(c[2]), "+f"(c[3])
        : "r"(a[0]), "r"(a[1]), "r"(a[2]), "r"(a[3]), "r"(b[0]), "r"(b[1]));
}

#define CP_ASYNC16(dst, src) \
    asm volatile("cp.async.cg.shared.global [%0], [%1], 16;" :: "r"(dst), "l"(src))
#define CP_COMMIT() asm volatile("cp.async.commit_group;" ::: "memory")
#define CP_WAIT(n)  asm volatile("cp.async.wait_group %0;" :: "n"(n) : "memory")

// pack two fp32 -> bf16x2 reg (first arg in low half)
__device__ __forceinline__ uint32_t pk_bf2(float lo, float hi) {
    uint32_t r;
    asm("cvt.rn.bf16x2.f32 %0, %1, %2;" : "=r"(r) : "f"(hi), "f"(lo));
    return r;
}

// pack (a,b) to bf16x2 hi-part + residual lo-part (residual via bit-unpack)
__device__ __forceinline__ void pack_hl(float a, float b, uint32_t& ph, uint32_t& pl) {
    ph = pk_bf2(a, b);
    float ra = a - __uint_as_float(ph << 16);
    float rb = b - __uint_as_float(ph & 0xffff0000u);
    pl = pk_bf2(ra, rb);
}

// ---------------------------------------------------------------------------
// fp32 -> bf16 hi/lo split: all 5 tensors in ONE launch
// blockIdx.y: 0..3 -> quarter of x; 4..7 -> Wq/Wk/Wv/Wo
// ---------------------------------------------------------------------------
__device__ __forceinline__ void split4(const float* __restrict__ src,
                                       __nv_bfloat16* __restrict__ hi,
                                       __nv_bfloat16* __restrict__ lo, int i)
{
    float4 v = *(const float4*)(src + i);
    __nv_bfloat16 ha = __float2bfloat16(v.x);
    __nv_bfloat16 hb = __float2bfloat16(v.y);
    __nv_bfloat16 hc = __float2bfloat16(v.z);
    __nv_bfloat16 hd = __float2bfloat16(v.w);
    __nv_bfloat16 la = __float2bfloat16(v.x - __bfloat162float(ha));
    __nv_bfloat16 lb = __float2bfloat16(v.y - __bfloat162float(hb));
    __nv_bfloat16 lc = __float2bfloat16(v.z - __bfloat162float(hc));
    __nv_bfloat16 ld = __float2bfloat16(v.w - __bfloat162float(hd));
    *(__nv_bfloat162*)(hi + i)     = __halves2bfloat162(ha, hb);
    *(__nv_bfloat162*)(hi + i + 2) = __halves2bfloat162(hc, hd);
    *(__nv_bfloat162*)(lo + i)     = __halves2bfloat162(la, lb);
    *(__nv_bfloat162*)(lo + i + 2) = __halves2bfloat162(lc, ld);
}

__global__ __launch_bounds__(256)
void split_all(const float* __restrict__ x,
               const float* __restrict__ Wq, const float* __restrict__ Wk,
               const float* __restrict__ Wv, const float* __restrict__ Wo)
{
    const int seg = blockIdx.y;
    const float* src; __nv_bfloat16 *hi, *lo;
    int base = 0;
    if (seg < 4) {
        src = x; hi = g_xh; lo = g_xl; base = seg * (Dd*Dd);  // x quarters
    } else if (seg == 4) { src = Wq; hi = g_wqh; lo = g_wql; }
    else if (seg == 5)   { src = Wk; hi = g_wkh; lo = g_wkl; }
    else if (seg == 6)   { src = Wv; hi = g_wvh; lo = g_wvl; }
    else                 { src = Wo; hi = g_woh; lo = g_wol; }
    int i = base + (blockIdx.x * 256 + threadIdx.x) * 4;
    split4(src, hi, lo, i);
}

// ---------------------------------------------------------------------------
// HMMA bf16x3 GEMM: C = (Ah+Al) @ (Bh+Bl)^T. Two epilogues:
//   SPLIT=0: fp32 + bias -> C
//   SPLIT=1: (scale*C) split into bf16 hi/lo -> Ch, Cl
// Tile 128x128x32, 8 warps, warp tile 64x32, 2-stage cp.async, 2 CTAs/SM.
// Single __syncthreads per chunk: wait(0) -> sync -> prefetch(c+1) -> compute.
// ---------------------------------------------------------------------------
#define GM 128
#define GN 128
#define GKC 32
#define NCHUNK (Dd / GKC)        // 32
#define TILEB (128 * GKC * 2)    // 8192
#define STAGEB (4 * TILEB)       // 32KB: AH | AL | BH | BL
#define GEMM_SMEM (2 * STAGEB)   // 64KB

__device__ __forceinline__ uint32_t sw_addr(uint32_t base, int row, int unit) {
    return base + row * 64 + ((unit ^ ((row >> 1) & 3)) << 4);
}

__device__ __forceinline__ void cp_tile(uint32_t sdst, const __nv_bfloat16* __restrict__ g,
                                        int tid)
{
    #pragma unroll
    for (int i = 0; i < 2; i++) {
        int u   = tid + i * 256;
        int row = u >> 2;
        int cu  = u & 3;
        CP_ASYNC16(sw_addr(sdst, row, cu), g + (size_t)row * Dd + cu * 8);
    }
}

__device__ __forceinline__ void cp_stage(uint32_t s,
    const __nv_bfloat16* gAh, const __nv_bfloat16* gAl,
    const __nv_bfloat16* gBh, const __nv_bfloat16* gBl, int kc, int tid)
{
    cp_tile(s,           gAh + kc, tid);
    cp_tile(s + TILEB,   gAl + kc, tid);
    cp_tile(s + 2*TILEB, gBh + kc, tid);
    cp_tile(s + 3*TILEB, gBl + kc, tid);
    CP_COMMIT();
}

template<int SPLIT>
__device__ __forceinline__ void gemm_tc_body(
    const __nv_bfloat16* __restrict__ Ah, const __nv_bfloat16* __restrict__ Al,
    const __nv_bfloat16* __restrict__ Bh, const __nv_bfloat16* __restrict__ Bl,
    const float* __restrict__ bias, float* __restrict__ C,
    __nv_bfloat16* __restrict__ Ch, __nv_bfloat16* __restrict__ Cl, float scale)
{
    extern __shared__ char smem[];
    const uint32_t sb = smem_u32(smem);
    const int tid = threadIdx.x;
    const int wid = tid >> 5;
    const int lid = tid & 31;
    const int wm  = wid >> 2;
    const int wn  = wid & 3;
    const int m0  = blockIdx.y * GM;
    const int n0  = blockIdx.x * GN;

    const __nv_bfloat16* gAh = Ah + (size_t)m0 * Dd;
    const __nv_bfloat16* gAl = Al + (size_t)m0 * Dd;
    const __nv_bfloat16* gBh = Bh + (size_t)n0 * Dd;
    const __nv_bfloat16* gBl = Bl + (size_t)n0 * Dd;

    float acc[4][4][4];
    #pragma unroll
    for (int i = 0; i < 4; i++)
        #pragma unroll
        for (int j = 0; j < 4; j++)
            #pragma unroll
            for (int k = 0; k < 4; k++) acc[i][j][k] = 0.f;

    const int a_row = wm * 64 + (lid & 15);
    const int a_ku  = lid >> 4;
    const int b_row = wn * 32 + (lid & 7) + ((lid >> 4) << 3);
    const int b_ku  = (lid >> 3) & 1;

    // prologue: stage0 <- chunk0
    cp_stage(sb, gAh, gAl, gBh, gBl, 0, tid);

    for (int c = 0; c < NCHUNK; c++) {
        CP_WAIT(0);
        __syncthreads();   // publishes chunk c; proves chunk c-1 reads done
        if (c + 1 < NCHUNK)
            cp_stage(sb + ((c + 1) & 1) * STAGEB, gAh, gAl, gBh, gBl, (c + 1) * GKC, tid);

        const uint32_t sa_h = sb + (c & 1) * STAGEB;
        const uint32_t sa_l = sa_h + TILEB;
        const uint32_t sbh  = sa_h + 2*TILEB;
        const uint32_t sbl  = sa_h + 3*TILEB;

        #pragma unroll
        for (int ks = 0; ks < 2; ks++) {
            const int ku = ks * 2;
            uint32_t bh[8], bl[8];
            #pragma unroll
            for (int pr = 0; pr < 2; pr++) {
                ldm_x4(bh[pr*4+0], bh[pr*4+1], bh[pr*4+2], bh[pr*4+3],
                       sw_addr(sbh, b_row + pr*16, ku + b_ku));
                ldm_x4(bl[pr*4+0], bl[pr*4+1], bl[pr*4+2], bl[pr*4+3],
                       sw_addr(sbl, b_row + pr*16, ku + b_ku));
            }
            #pragma unroll
            for (int mt = 0; mt < 4; mt++) {
                uint32_t ah[4], al[4];
                ldm_x4(ah[0], ah[1], ah[2], ah[3],
                       sw_addr(sa_h, a_row + mt*16, ku + a_ku));
                ldm_x4(al[0], al[1], al[2], al[3],
                       sw_addr(sa_l, a_row + mt*16, ku + a_ku));
                #pragma unroll
                for (int nt = 0; nt < 4; nt++) {
                    mma16816(acc[mt][nt], ah, &bh[nt*2]);
                    mma16816(acc[mt][nt], al, &bh[nt*2]);
                    mma16816(acc[mt][nt], ah, &bl[nt*2]);
                }
            }
        }
    }

    #pragma unroll
    for (int mt = 0; mt < 4; mt++) {
        const int row = m0 + wm*64 + mt*16 + (lid >> 2);
        #pragma unroll
        for (int nt = 0; nt < 4; nt++) {
            const int col = n0 + wn*32 + nt*8 + (lid & 3)*2;
            if (SPLIT) {
                #pragma unroll
                for (int half = 0; half < 2; half++) {
                    const int r = row + half * 8;
                    float va = acc[mt][nt][half*2+0] * scale;
                    float vb = acc[mt][nt][half*2+1] * scale;
                    uint32_t ph, pl;
                    pack_hl(va, vb, ph, pl);
                    *(uint32_t*)(Ch + (size_t)r * Dd + col) = ph;
                    *(uint32_t*)(Cl + (size_t)r * Dd + col) = pl;
                }
            } else {
                float2 v0 = make_float2(acc[mt][nt][0], acc[mt][nt][1]);
                float2 v1 = make_float2(acc[mt][nt][2], acc[mt][nt][3]);
                float2 bv = *(const float2*)(bias + col);
                v0.x += bv.x; v0.y += bv.y;
                v1.x += bv.x; v1.y += bv.y;
                *(float2*)(C + (size_t)row * Dd + col)       = v0;
                *(float2*)(C + (size_t)(row + 8) * Dd + col) = v1;
            }
        }
    }
}

__global__ __launch_bounds__(256, 2)
void gemm_qkv_tc()
{
    const __nv_bfloat16 *Bh, *Bl; __nv_bfloat16 *Ch, *Cl; float sc;
    // Q pre-scaled by (1/sqrt(HD)) * log2(e) so attention works in base-2
    if (blockIdx.z == 0)      { Bh = g_wqh; Bl = g_wql; Ch = g_Qh; Cl = g_Ql; sc = 0.18033688f; }
    else if (blockIdx.z == 1) { Bh = g_wkh; Bl = g_wkl; Ch = g_Kh; Cl = g_Kl; sc = 1.f; }
    else                      { Bh = g_wvh; Bl = g_wvl; Ch = g_Vh; Cl = g_Vl; sc = 1.f; }
    gemm_tc_body<1>(g_xh, g_xl, Bh, Bl, nullptr, nullptr, Ch, Cl, sc);
}

__global__ __launch_bounds__(256, 2)
void gemm_o_tc(const float* bias, float* out)
{
    gemm_tc_body<0>(g_aoh, g_aol, g_woh, g_wol, bias, out, nullptr, nullptr, 1.f);
}

// ---------------------------------------------------------------------------
// HMMA flash attention. Block = 128 q rows of one (b,h); 8 warps x 16 rows.
// KV chunks of 64 keys, 2-stage cp.async, 2 CTAs/SM, base-2 softmax.
// Single __syncthreads per chunk: wait(0) -> sync -> prefetch(c+1) -> compute.
// ---------------------------------------------------------------------------
#define AQ 128
#define AKC 64
#define SQH 0
#define SQL 16384
#define SKV 32768
#define KVSTAGE 32768   // KH 0 | KL 8192 | VH 16384 | VL 24576
#define ATT_SMEM (SKV + 2 * KVSTAGE)   // 98304

__device__ __forceinline__ uint32_t asw(uint32_t base, int row, int unit) {
    return base + row * 128 + ((unit ^ (row & 7)) << 4);
}

__device__ __forceinline__ void cp_kv(uint32_t sbase, int brow0, int h, int tid)
{
    #pragma unroll
    for (int i = 0; i < 2; i++) {
        int u = tid + i * 256;
        int row = u >> 3;
        int un = u & 7;
        size_t g = ((size_t)(brow0 + row)) * Dd + h * HD + un * 8;
        CP_ASYNC16(asw(sbase,          row, un), g_Kh + g);
        CP_ASYNC16(asw(sbase +  8192,  row, un), g_Kl + g);
        CP_ASYNC16(asw(sbase + 16384,  row, un), g_Vh + g);
        CP_ASYNC16(asw(sbase + 24576,  row, un), g_Vl + g);
    }
    CP_COMMIT();
}

__global__ __launch_bounds__(256, 2)
void attn_mma()
{
    extern __shared__ char smem[];
    const uint32_t sb = smem_u32(smem);
    const int tid = threadIdx.x;
    const int wid = tid >> 5;
    const int lid = tid & 31;
    const int q0  = blockIdx.x * AQ;
    const int b   = blockIdx.y >> 4;
    const int h   = blockIdx.y & 15;

    // stage Q (hi/lo): 128 rows x 8 units each
    #pragma unroll
    for (int i = 0; i < 4; i++) {
        int u = tid + i * 256;
        int row = u >> 3;
        int un = u & 7;
        size_t g = ((size_t)(b * Ss + q0 + row)) * Dd + h * HD + un * 8;
        CP_ASYNC16(asw(sb + SQH, row, un), g_Qh + g);
        CP_ASYNC16(asw(sb + SQL, row, un), g_Ql + g);
    }
    CP_COMMIT();

    // prologue KV chunk 0 -> stage 0
    cp_kv(sb + SKV, b * Ss, h, tid);

    CP_WAIT(1);   // Q resident (KV0 may still be in flight)
    __syncthreads();

    const int q_r  = wid * 16 + (lid & 15);
    const int q_ub = lid >> 4;

    // Q-hi fragments resident; Q-lo reloaded per chunk from smem
    uint32_t qh[4][4];
    #pragma unroll
    for (int ks = 0; ks < 4; ks++)
        ldm_x4(qh[ks][0], qh[ks][1], qh[ks][2], qh[ks][3],
               asw(sb + SQH, q_r, ks*2 + q_ub));

    float o[8][4];
    #pragma unroll
    for (int i = 0; i < 8; i++)
        #pragma unroll
        for (int j = 0; j < 4; j++) o[i][j] = 0.f;
    float m0 = -CUDART_INF_F, m1 = -CUDART_INF_F, l0 = 0.f, l1 = 0.f;

    const int kb_row = (lid & 7) + ((lid >> 4) << 3);
    const int kb_ku  = (lid >> 3) & 1;
    const int v_row  = lid & 15;
    const int v_ub   = lid >> 4;

    const int NC = Ss / AKC;    // 32
    for (int c = 0; c < NC; c++) {
        CP_WAIT(0);
        __syncthreads();   // publishes KV chunk c; proves chunk c-1 reads done
        if (c + 1 < NC)
            cp_kv(sb + SKV + ((c + 1) & 1) * KVSTAGE, b * Ss + (c + 1) * AKC, h, tid);

        const uint32_t skh = sb + SKV + (c & 1) * KVSTAGE;
        const uint32_t skl = skh + 8192;
        const uint32_t svh = skh + 16384;
        const uint32_t svl = skh + 24576;

        // S = Q K^T  (x3 corrected), 16x64 per warp; scores in log2 domain
        float s[8][4];
        #pragma unroll
        for (int i = 0; i < 8; i++)
            #pragma unroll
            for (int j = 0; j < 4; j++) s[i][j] = 0.f;

        #pragma unroll
        for (int ks = 0; ks < 4; ks++) {
            uint32_t ql4[4];
            ldm_x4(ql4[0], ql4[1], ql4[2], ql4[3],
                   asw(sb + SQL, q_r, ks*2 + q_ub));
            #pragma unroll
            for (int g = 0; g < 4; g++) {
                uint32_t kh4[4], kl4[4];
                ldm_x4(kh4[0], kh4[1], kh4[2], kh4[3],
                       asw(skh, g*16 + kb_row, ks*2 + kb_ku));
                ldm_x4(kl4[0], kl4[1], kl4[2], kl4[3],
                       asw(skl, g*16 + kb_row, ks*2 + kb_ku));
                mma16816(s[2*g],   qh[ks], &kh4[0]);
                mma16816(s[2*g],   ql4,    &kh4[0]);
                mma16816(s[2*g],   qh[ks], &kl4[0]);
                mma16816(s[2*g+1], qh[ks], &kh4[2]);
                mma16816(s[2*g+1], ql4,    &kh4[2]);
                mma16816(s[2*g+1], qh[ks], &kl4[2]);
            }
        }

        // online softmax, base 2 (rows r and r+8 per thread)
        float rm0 = fmaxf(s[0][0], s[0][1]);
        float rm1 = fmaxf(s[0][2], s[0][3]);
        #pragma unroll
        for (int nt = 1; nt < 8; nt++) {
            rm0 = fmaxf(rm0, fmaxf(s[nt][0], s[nt][1]));
            rm1 = fmaxf(rm1, fmaxf(s[nt][2], s[nt][3]));
        }
        rm0 = fmaxf(rm0, __shfl_xor_sync(0xffffffffu, rm0, 1));
        rm0 = fmaxf(rm0, __shfl_xor_sync(0xffffffffu, rm0, 2));
        rm1 = fmaxf(rm1, __shfl_xor_sync(0xffffffffu, rm1, 1));
        rm1 = fmaxf(rm1, __shfl_xor_sync(0xffffffffu, rm1, 2));
        const float mn0 = fmaxf(m0, rm0);
        const float mn1 = fmaxf(m1, rm1);
        const float c0 = exp2f(m0 - mn0);
        const float c1 = exp2f(m1 - mn1);
        float sum0 = 0.f, sum1 = 0.f;
        #pragma unroll
        for (int nt = 0; nt < 8; nt++) {
            s[nt][0] = exp2f(s[nt][0] - mn0); sum0 += s[nt][0];
            s[nt][1] = exp2f(s[nt][1] - mn0); sum0 += s[nt][1];
            s[nt][2] = exp2f(s[nt][2] - mn1); sum1 += s[nt][2];
            s[nt][3] = exp2f(s[nt][3] - mn1); sum1 += s[nt][3];
            o[nt][0] *= c0; o[nt][1] *= c0;
            o[nt][2] *= c1; o[nt][3] *= c1;
        }
        sum0 += __shfl_xor_sync(0xffffffffu, sum0, 1);
        sum0 += __shfl_xor_sync(0xffffffffu, sum0, 2);
        sum1 += __shfl_xor_sync(0xffffffffu, sum1, 1);
        sum1 += __shfl_xor_sync(0xffffffffu, sum1, 2);
        l0 = l0 * c0 + sum0;
        l1 = l1 * c1 + sum1;
        m0 = mn0; m1 = mn1;

        // O += P V  (x3 corrected)
        #pragma unroll
        for (int kt = 0; kt < 4; kt++) {
            uint32_t pah[4], pal[4];
            {
                const float* t0 = s[2*kt];
                const float* t1 = s[2*kt+1];
                pack_hl(t0[0], t0[1], pah[0], pal[0]);
                pack_hl(t0[2], t0[3], pah[1], pal[1]);
                pack_hl(t1[0], t1[1], pah[2], pal[2]);
                pack_hl(t1[2], t1[3], pah[3], pal[3]);
            }
            #pragma unroll
            for (int db = 0; db < 4; db++) {
                uint32_t vh4[4], vl4[4];
                ldm_x4_t(vh4[0], vh4[1], vh4[2], vh4[3],
                         asw(svh, kt*16 + v_row, db*2 + v_ub));
                ldm_x4_t(vl4[0], vl4[1], vl4[2], vl4[3],
                         asw(svl, kt*16 + v_row, db*2 + v_ub));
                mma16816(o[2*db + 0], pah, &vh4[0]);
                mma16816(o[2*db + 0], pal, &vh4[0]);
                mma16816(o[2*db + 0], pah, &vl4[0]);
                mma16816(o[2*db + 1], pah, &vh4[2]);
                mma16816(o[2*db + 1], pal, &vh4[2]);
                mma16816(o[2*db + 1], pah, &vl4[2]);
            }
        }
    }

    // normalize + write AO hi/lo
    const float inv0 = 1.f / l0;
    const float inv1 = 1.f / l1;
    const int gr0 = b * Ss + q0 + wid*16 + (lid >> 2);
    #pragma unroll
    for (int nt = 0; nt < 8; nt++) {
        const int col = h * HD + nt*8 + (lid & 3)*2;
        float va = o[nt][0] * inv0, vb = o[nt][1] * inv0;
        float vc = o[nt][2] * inv1, vd = o[nt][3] * inv1;
        uint32_t ph0, pl0, ph1, pl1;
        pack_hl(va, vb, ph0, pl0);
        pack_hl(vc, vd, ph1, pl1);
        *(uint32_t*)(g_aoh + (size_t)gr0 * Dd + col)       = ph0;
        *(uint32_t*)(g_aol + (size_t)gr0 * Dd + col)       = pl0;
        *(uint32_t*)(g_aoh + (size_t)(gr0 + 8) * Dd + col) = ph1;
        *(uint32_t*)(g_aol + (size_t)(gr0 + 8) * Dd + col) = pl1;
    }
}

// ---------------------------------------------------------------------------
extern "C" void kernel_launch(void* const* d_in, const int* in_sizes, int n_in,
                              void* d_out, int out_size)
{
    const float* x  = (const float*)d_in[0];
    const float* Wq = (const float*)d_in[1];
    const float* Wk = (const float*)d_in[2];
    const float* Wv = (const float*)d_in[3];
    const float* Wo = (const float*)d_in[4];
    const float* bo = (const float*)d_in[5];
    float* out = (float*)d_out;

    cudaFuncSetAttribute(gemm_qkv_tc, cudaFuncAttributeMaxDynamicSharedMemorySize, GEMM_SMEM);
    cudaFuncSetAttribute(gemm_o_tc,   cudaFuncAttributeMaxDynamicSharedMemorySize, GEMM_SMEM);
    cudaFuncSetAttribute(attn_mma,    cudaFuncAttributeMaxDynamicSharedMemorySize, ATT_SMEM);

    // 1) split fp32 inputs -> bf16 hi/lo (one launch: x quarters + 4 weights)
    dim3 gsp((Dd*Dd)/1024, 8);
    split_all<<<gsp, 256>>>(x, Wq, Wk, Wv, Wo);

    // 2) QKV projections -> bf16 hi/lo (Q pre-scaled by 0.125*log2e)
    dim3 gqkv(Dd / GN, Mtot / GM, 3);
    gemm_qkv_tc<<<gqkv, 256, GEMM_SMEM>>>();

    // 3) HMMA flash attention -> AO hi/lo
    dim3 gattn(Ss / AQ, Bb * Hh);
    attn_mma<<<gattn, 256, ATT_SMEM>>>();

    // 4) output projection (+bias) -> fp32 out
    dim3 gout(Dd / GN, Mtot / GM, 1);
    gemm_o_tc<<<gout, 256, GEMM_SMEM>>>(bo, out);
}

// round 11
// speedup vs baseline: 1.1671x; 1.0009x over previous
#include <cuda_runtime.h>
#include <cuda_bf16.h>
#include <math_constants.h>
#include <cstdint>

// Problem constants
#define Bb 2
#define Ss 2048
#define Dd 1024
#define Hh 16
#define HD 64
#define Mtot (Bb*Ss)   // 4096 rows

// ---------------------------------------------------------------------------
// Scratch (__device__ globals; allocation-free rule)
// ---------------------------------------------------------------------------
__device__ __nv_bfloat16 g_xh [Mtot*Dd], g_xl [Mtot*Dd];
__device__ __nv_bfloat16 g_wqh[Dd*Dd],   g_wql[Dd*Dd];
__device__ __nv_bfloat16 g_wkh[Dd*Dd],   g_wkl[Dd*Dd];
__device__ __nv_bfloat16 g_wvh[Dd*Dd],   g_wvl[Dd*Dd];
__device__ __nv_bfloat16 g_woh[Dd*Dd],   g_wol[Dd*Dd];
__device__ __nv_bfloat16 g_Qh [Mtot*Dd], g_Ql [Mtot*Dd];   // pre-scaled by 0.125*log2(e)
__device__ __nv_bfloat16 g_Kh [Mtot*Dd], g_Kl [Mtot*Dd];
__device__ __nv_bfloat16 g_Vh [Mtot*Dd], g_Vl [Mtot*Dd];
__device__ __nv_bfloat16 g_aoh[Mtot*Dd], g_aol[Mtot*Dd];

// ---------------------------------------------------------------------------
// PTX helpers (compute_103-safe: ldmatrix / mma.sync / cp.async)
// ---------------------------------------------------------------------------
__device__ __forceinline__ uint32_t smem_u32(const void* p) {
    uint32_t a;
    asm("{ .reg .u64 t; cvta.to.shared.u64 t, %1; cvt.u32.u64 %0, t; }"
        : "=r"(a) : "l"(p));
    return a;
}

__device__ __forceinline__ void ldm_x4(uint32_t& r0, uint32_t& r1,
                                       uint32_t& r2, uint32_t& r3, uint32_t addr) {
    asm volatile("ldmatrix.sync.aligned.m8n8.x4.shared.b16 {%0,%1,%2,%3}, [%4];"
                 : "=r"(r0), "=r"(r1), "=r"(r2), "=r"(r3) : "r"(addr));
}

__device__ __forceinline__ void ldm_x4_t(uint32_t& r0, uint32_t& r1,
                                         uint32_t& r2, uint32_t& r3, uint32_t addr) {
    asm volatile("ldmatrix.sync.aligned.m8n8.x4.trans.shared.b16 {%0,%1,%2,%3}, [%4];"
                 : "=r"(r0), "=r"(r1), "=r"(r2), "=r"(r3) : "r"(addr));
}

__device__ __forceinline__ void mma16816(float* c, const uint32_t* a, const uint32_t* b) {
    asm volatile(
        "mma.sync.aligned.m16n8k16.row.col.f32.bf16.bf16.f32 "
        "{%0,%1,%2,%3}, {%4,%5,%6,%7}, {%8,%9}, {%0,%1,%2,%3};"
        : "+f"(c[0]), "+f"(c[1]), "+f"(c[2]), "+f"(c[3])
        : "r"(a[0]), "r"(a[1]), "r"(a[2]), "r"(a[3]), "r"(b[0]), "r"(b[1]));
}

#define CP_ASYNC16(dst, src) \
    asm volatile("cp.async.cg.shared.global [%0], [%1], 16;" :: "r"(dst), "l"(src))
#define CP_COMMIT() asm volatile("cp.async.commit_group;" ::: "memory")
#define CP_WAIT(n)  asm volatile("cp.async.wait_group %0;" :: "n"(n) : "memory")

// pack two fp32 -> bf16x2 reg (first arg in low half)
__device__ __forceinline__ uint32_t pk_bf2(float lo, float hi) {
    uint32_t r;
    asm("cvt.rn.bf16x2.f32 %0, %1, %2;" : "=r"(r) : "f"(hi), "f"(lo));
    return r;
}

// pack (a,b) to bf16x2 hi-part + residual lo-part (residual via bit-unpack)
__device__ __forceinline__ void pack_hl(float a, float b, uint32_t& ph, uint32_t& pl) {
    ph = pk_bf2(a, b);
    float ra = a - __uint_as_float(ph << 16);
    float rb = b - __uint_as_float(ph & 0xffff0000u);
    pl = pk_bf2(ra, rb);
}

// ---------------------------------------------------------------------------
// fp32 -> bf16 hi/lo split: all 5 tensors in ONE launch
// blockIdx.y: 0..3 -> quarter of x; 4..7 -> Wq/Wk/Wv/Wo
// ---------------------------------------------------------------------------
__device__ __forceinline__ void split4(const float* __restrict__ src,
                                       __nv_bfloat16* __restrict__ hi,
                                       __nv_bfloat16* __restrict__ lo, int i)
{
    float4 v = *(const float4*)(src + i);
    __nv_bfloat16 ha = __float2bfloat16(v.x);
    __nv_bfloat16 hb = __float2bfloat16(v.y);
    __nv_bfloat16 hc = __float2bfloat16(v.z);
    __nv_bfloat16 hd = __float2bfloat16(v.w);
    __nv_bfloat16 la = __float2bfloat16(v.x - __bfloat162float(ha));
    __nv_bfloat16 lb = __float2bfloat16(v.y - __bfloat162float(hb));
    __nv_bfloat16 lc = __float2bfloat16(v.z - __bfloat162float(hc));
    __nv_bfloat16 ld = __float2bfloat16(v.w - __bfloat162float(hd));
    *(__nv_bfloat162*)(hi + i)     = __halves2bfloat162(ha, hb);
    *(__nv_bfloat162*)(hi + i + 2) = __halves2bfloat162(hc, hd);
    *(__nv_bfloat162*)(lo + i)     = __halves2bfloat162(la, lb);
    *(__nv_bfloat162*)(lo + i + 2) = __halves2bfloat162(lc, ld);
}

__global__ __launch_bounds__(256)
void split_all(const float* __restrict__ x,
               const float* __restrict__ Wq, const float* __restrict__ Wk,
               const float* __restrict__ Wv, const float* __restrict__ Wo)
{
    const int seg = blockIdx.y;
    const float* src; __nv_bfloat16 *hi, *lo;
    int base = 0;
    if (seg < 4) {
        src = x; hi = g_xh; lo = g_xl; base = seg * (Dd*Dd);  // x quarters
    } else if (seg == 4) { src = Wq; hi = g_wqh; lo = g_wql; }
    else if (seg == 5)   { src = Wk; hi = g_wkh; lo = g_wkl; }
    else if (seg == 6)   { src = Wv; hi = g_wvh; lo = g_wvl; }
    else                 { src = Wo; hi = g_woh; lo = g_wol; }
    int i = base + (blockIdx.x * 256 + threadIdx.x) * 4;
    split4(src, hi, lo, i);
}

// ---------------------------------------------------------------------------
// HMMA bf16x3 GEMM: C = (Ah+Al) @ (Bh+Bl)^T. Two epilogues:
//   SPLIT=0: fp32 + bias -> C
//   SPLIT=1: (scale*C) split into bf16 hi/lo -> Ch, Cl
// Tile 128x128x32, 8 warps, warp tile 64x32, 2-stage cp.async, 2 CTAs/SM.
// Term-major mma issue: each accumulator's 3 correction mmas are distance-4.
// ---------------------------------------------------------------------------
#define GM 128
#define GN 128
#define GKC 32
#define NCHUNK (Dd / GKC)        // 32
#define TILEB (128 * GKC * 2)    // 8192
#define STAGEB (4 * TILEB)       // 32KB: AH | AL | BH | BL
#define GEMM_SMEM (2 * STAGEB)   // 64KB

__device__ __forceinline__ uint32_t sw_addr(uint32_t base, int row, int unit) {
    return base + row * 64 + ((unit ^ ((row >> 1) & 3)) << 4);
}

__device__ __forceinline__ void cp_tile(uint32_t sdst, const __nv_bfloat16* __restrict__ g,
                                        int tid)
{
    #pragma unroll
    for (int i = 0; i < 2; i++) {
        int u   = tid + i * 256;
        int row = u >> 2;
        int cu  = u & 3;
        CP_ASYNC16(sw_addr(sdst, row, cu), g + (size_t)row * Dd + cu * 8);
    }
}

__device__ __forceinline__ void cp_stage(uint32_t s,
    const __nv_bfloat16* gAh, const __nv_bfloat16* gAl,
    const __nv_bfloat16* gBh, const __nv_bfloat16* gBl, int kc, int tid)
{
    cp_tile(s,           gAh + kc, tid);
    cp_tile(s + TILEB,   gAl + kc, tid);
    cp_tile(s + 2*TILEB, gBh + kc, tid);
    cp_tile(s + 3*TILEB, gBl + kc, tid);
    CP_COMMIT();
}

template<int SPLIT>
__device__ __forceinline__ void gemm_tc_body(
    const __nv_bfloat16* __restrict__ Ah, const __nv_bfloat16* __restrict__ Al,
    const __nv_bfloat16* __restrict__ Bh, const __nv_bfloat16* __restrict__ Bl,
    const float* __restrict__ bias, float* __restrict__ C,
    __nv_bfloat16* __restrict__ Ch, __nv_bfloat16* __restrict__ Cl, float scale)
{
    extern __shared__ char smem[];
    const uint32_t sb = smem_u32(smem);
    const int tid = threadIdx.x;
    const int wid = tid >> 5;
    const int lid = tid & 31;
    const int wm  = wid >> 2;
    const int wn  = wid & 3;
    const int m0  = blockIdx.y * GM;
    const int n0  = blockIdx.x * GN;

    const __nv_bfloat16* gAh = Ah + (size_t)m0 * Dd;
    const __nv_bfloat16* gAl = Al + (size_t)m0 * Dd;
    const __nv_bfloat16* gBh = Bh + (size_t)n0 * Dd;
    const __nv_bfloat16* gBl = Bl + (size_t)n0 * Dd;

    float acc[4][4][4];
    #pragma unroll
    for (int i = 0; i < 4; i++)
        #pragma unroll
        for (int j = 0; j < 4; j++)
            #pragma unroll
            for (int k = 0; k < 4; k++) acc[i][j][k] = 0.f;

    const int a_row = wm * 64 + (lid & 15);
    const int a_ku  = lid >> 4;
    const int b_row = wn * 32 + (lid & 7) + ((lid >> 4) << 3);
    const int b_ku  = (lid >> 3) & 1;

    // prologue: stage0 <- chunk0
    cp_stage(sb, gAh, gAl, gBh, gBl, 0, tid);

    for (int c = 0; c < NCHUNK; c++) {
        CP_WAIT(0);
        __syncthreads();   // publishes chunk c; proves chunk c-1 reads done
        if (c + 1 < NCHUNK)
            cp_stage(sb + ((c + 1) & 1) * STAGEB, gAh, gAl, gBh, gBl, (c + 1) * GKC, tid);

        const uint32_t sa_h = sb + (c & 1) * STAGEB;
        const uint32_t sa_l = sa_h + TILEB;
        const uint32_t sbh  = sa_h + 2*TILEB;
        const uint32_t sbl  = sa_h + 3*TILEB;

        #pragma unroll
        for (int ks = 0; ks < 2; ks++) {
            const int ku = ks * 2;
            uint32_t bh[8], bl[8];
            #pragma unroll
            for (int pr = 0; pr < 2; pr++) {
                ldm_x4(bh[pr*4+0], bh[pr*4+1], bh[pr*4+2], bh[pr*4+3],
                       sw_addr(sbh, b_row + pr*16, ku + b_ku));
                ldm_x4(bl[pr*4+0], bl[pr*4+1], bl[pr*4+2], bl[pr*4+3],
                       sw_addr(sbl, b_row + pr*16, ku + b_ku));
            }
            #pragma unroll
            for (int mt = 0; mt < 4; mt++) {
                uint32_t ah[4], al[4];
                ldm_x4(ah[0], ah[1], ah[2], ah[3],
                       sw_addr(sa_h, a_row + mt*16, ku + a_ku));
                ldm_x4(al[0], al[1], al[2], al[3],
                       sw_addr(sa_l, a_row + mt*16, ku + a_ku));
                // term-major: per-acc chain distance = 4 mmas
                #pragma unroll
                for (int nt = 0; nt < 4; nt++)
                    mma16816(acc[mt][nt], ah, &bh[nt*2]);
                #pragma unroll
                for (int nt = 0; nt < 4; nt++)
                    mma16816(acc[mt][nt], al, &bh[nt*2]);
                #pragma unroll
                for (int nt = 0; nt < 4; nt++)
                    mma16816(acc[mt][nt], ah, &bl[nt*2]);
            }
        }
    }

    #pragma unroll
    for (int mt = 0; mt < 4; mt++) {
        const int row = m0 + wm*64 + mt*16 + (lid >> 2);
        #pragma unroll
        for (int nt = 0; nt < 4; nt++) {
            const int col = n0 + wn*32 + nt*8 + (lid & 3)*2;
            if (SPLIT) {
                #pragma unroll
                for (int half = 0; half < 2; half++) {
                    const int r = row + half * 8;
                    float va = acc[mt][nt][half*2+0] * scale;
                    float vb = acc[mt][nt][half*2+1] * scale;
                    uint32_t ph, pl;
                    pack_hl(va, vb, ph, pl);
                    *(uint32_t*)(Ch + (size_t)r * Dd + col) = ph;
                    *(uint32_t*)(Cl + (size_t)r * Dd + col) = pl;
                }
            } else {
                float2 v0 = make_float2(acc[mt][nt][0], acc[mt][nt][1]);
                float2 v1 = make_float2(acc[mt][nt][2], acc[mt][nt][3]);
                float2 bv = *(const float2*)(bias + col);
                v0.x += bv.x; v0.y += bv.y;
                v1.x += bv.x; v1.y += bv.y;
                *(float2*)(C + (size_t)row * Dd + col)       = v0;
                *(float2*)(C + (size_t)(row + 8) * Dd + col) = v1;
            }
        }
    }
}

__global__ __launch_bounds__(256, 2)
void gemm_qkv_tc()
{
    const __nv_bfloat16 *Bh, *Bl; __nv_bfloat16 *Ch, *Cl; float sc;
    // Q pre-scaled by (1/sqrt(HD)) * log2(e) so attention works in base-2
    if (blockIdx.z == 0)      { Bh = g_wqh; Bl = g_wql; Ch = g_Qh; Cl = g_Ql; sc = 0.18033688f; }
    else if (blockIdx.z == 1) { Bh = g_wkh; Bl = g_wkl; Ch = g_Kh; Cl = g_Kl; sc = 1.f; }
    else                      { Bh = g_wvh; Bl = g_wvl; Ch = g_Vh; Cl = g_Vl; sc = 1.f; }
    gemm_tc_body<1>(g_xh, g_xl, Bh, Bl, nullptr, nullptr, Ch, Cl, sc);
}

__global__ __launch_bounds__(256, 2)
void gemm_o_tc(const float* bias, float* out)
{
    gemm_tc_body<0>(g_aoh, g_aol, g_woh, g_wol, bias, out, nullptr, nullptr, 1.f);
}

// ---------------------------------------------------------------------------
// HMMA flash attention. Block = 128 q rows of one (b,h); 8 warps x 16 rows.
// KV chunks of 64 keys, 2-stage cp.async, 2 CTAs/SM, base-2 softmax.
// Interleaved mma chains (distance 2) in QK^T and PV.
// ---------------------------------------------------------------------------
#define AQ 128
#define AKC 64
#define SQH 0
#define SQL 16384
#define SKV 32768
#define KVSTAGE 32768   // KH 0 | KL 8192 | VH 16384 | VL 24576
#define ATT_SMEM (SKV + 2 * KVSTAGE)   // 98304

__device__ __forceinline__ uint32_t asw(uint32_t base, int row, int unit) {
    return base + row * 128 + ((unit ^ (row & 7)) << 4);
}

__device__ __forceinline__ void cp_kv(uint32_t sbase, int brow0, int h, int tid)
{
    #pragma unroll
    for (int i = 0; i < 2; i++) {
        int u = tid + i * 256;
        int row = u >> 3;
        int un = u & 7;
        size_t g = ((size_t)(brow0 + row)) * Dd + h * HD + un * 8;
        CP_ASYNC16(asw(sbase,          row, un), g_Kh + g);
        CP_ASYNC16(asw(sbase +  8192,  row, un), g_Kl + g);
        CP_ASYNC16(asw(sbase + 16384,  row, un), g_Vh + g);
        CP_ASYNC16(asw(sbase + 24576,  row, un), g_Vl + g);
    }
    CP_COMMIT();
}

__global__ __launch_bounds__(256, 2)
void attn_mma()
{
    extern __shared__ char smem[];
    const uint32_t sb = smem_u32(smem);
    const int tid = threadIdx.x;
    const int wid = tid >> 5;
    const int lid = tid & 31;
    const int q0  = blockIdx.x * AQ;
    const int b   = blockIdx.y >> 4;
    const int h   = blockIdx.y & 15;

    // stage Q (hi/lo): 128 rows x 8 units each
    #pragma unroll
    for (int i = 0; i < 4; i++) {
        int u = tid + i * 256;
        int row = u >> 3;
        int un = u & 7;
        size_t g = ((size_t)(b * Ss + q0 + row)) * Dd + h * HD + un * 8;
        CP_ASYNC16(asw(sb + SQH, row, un), g_Qh + g);
        CP_ASYNC16(asw(sb + SQL, row, un), g_Ql + g);
    }
    CP_COMMIT();

    // prologue KV chunk 0 -> stage 0
    cp_kv(sb + SKV, b * Ss, h, tid);

    CP_WAIT(1);   // Q resident (KV0 may still be in flight)
    __syncthreads();

    const int q_r  = wid * 16 + (lid & 15);
    const int q_ub = lid >> 4;

    // Q-hi fragments resident; Q-lo reloaded per chunk from smem
    uint32_t qh[4][4];
    #pragma unroll
    for (int ks = 0; ks < 4; ks++)
        ldm_x4(qh[ks][0], qh[ks][1], qh[ks][2], qh[ks][3],
               asw(sb + SQH, q_r, ks*2 + q_ub));

    float o[8][4];
    #pragma unroll
    for (int i = 0; i < 8; i++)
        #pragma unroll
        for (int j = 0; j < 4; j++) o[i][j] = 0.f;
    float m0 = -CUDART_INF_F, m1 = -CUDART_INF_F, l0 = 0.f, l1 = 0.f;

    const int kb_row = (lid & 7) + ((lid >> 4) << 3);
    const int kb_ku  = (lid >> 3) & 1;
    const int v_row  = lid & 15;
    const int v_ub   = lid >> 4;

    const int NC = Ss / AKC;    // 32
    for (int c = 0; c < NC; c++) {
        CP_WAIT(0);
        __syncthreads();   // publishes KV chunk c; proves chunk c-1 reads done
        if (c + 1 < NC)
            cp_kv(sb + SKV + ((c + 1) & 1) * KVSTAGE, b * Ss + (c + 1) * AKC, h, tid);

        const uint32_t skh = sb + SKV + (c & 1) * KVSTAGE;
        const uint32_t skl = skh + 8192;
        const uint32_t svh = skh + 16384;
        const uint32_t svl = skh + 24576;

        // S = Q K^T  (x3 corrected), 16x64 per warp; scores in log2 domain
        float s[8][4];
        #pragma unroll
        for (int i = 0; i < 8; i++)
            #pragma unroll
            for (int j = 0; j < 4; j++) s[i][j] = 0.f;

        #pragma unroll
        for (int ks = 0; ks < 4; ks++) {
            uint32_t ql4[4];
            ldm_x4(ql4[0], ql4[1], ql4[2], ql4[3],
                   asw(sb + SQL, q_r, ks*2 + q_ub));
            #pragma unroll
            for (int g = 0; g < 4; g++) {
                uint32_t kh4[4], kl4[4];
                ldm_x4(kh4[0], kh4[1], kh4[2], kh4[3],
                       asw(skh, g*16 + kb_row, ks*2 + kb_ku));
                ldm_x4(kl4[0], kl4[1], kl4[2], kl4[3],
                       asw(skl, g*16 + kb_row, ks*2 + kb_ku));
                // interleave the two accumulator chains (distance 2)
                mma16816(s[2*g],   qh[ks], &kh4[0]);
                mma16816(s[2*g+1], qh[ks], &kh4[2]);
                mma16816(s[2*g],   ql4,    &kh4[0]);
                mma16816(s[2*g+1], ql4,    &kh4[2]);
                mma16816(s[2*g],   qh[ks], &kl4[0]);
                mma16816(s[2*g+1], qh[ks], &kl4[2]);
            }
        }

        // online softmax, base 2 (rows r and r+8 per thread)
        float rm0 = fmaxf(s[0][0], s[0][1]);
        float rm1 = fmaxf(s[0][2], s[0][3]);
        #pragma unroll
        for (int nt = 1; nt < 8; nt++) {
            rm0 = fmaxf(rm0, fmaxf(s[nt][0], s[nt][1]));
            rm1 = fmaxf(rm1, fmaxf(s[nt][2], s[nt][3]));
        }
        rm0 = fmaxf(rm0, __shfl_xor_sync(0xffffffffu, rm0, 1));
        rm0 = fmaxf(rm0, __shfl_xor_sync(0xffffffffu, rm0, 2));
        rm1 = fmaxf(rm1, __shfl_xor_sync(0xffffffffu, rm1, 1));
        rm1 = fmaxf(rm1, __shfl_xor_sync(0xffffffffu, rm1, 2));
        const float mn0 = fmaxf(m0, rm0);
        const float mn1 = fmaxf(m1, rm1);
        const float c0 = exp2f(m0 - mn0);
        const float c1 = exp2f(m1 - mn1);
        float sum0 = 0.f, sum1 = 0.f;
        #pragma unroll
        for (int nt = 0; nt < 8; nt++) {
            s[nt][0] = exp2f(s[nt][0] - mn0); sum0 += s[nt][0];
            s[nt][1] = exp2f(s[nt][1] - mn0); sum0 += s[nt][1];
            s[nt][2] = exp2f(s[nt][2] - mn1); sum1 += s[nt][2];
            s[nt][3] = exp2f(s[nt][3] - mn1); sum1 += s[nt][3];
            o[nt][0] *= c0; o[nt][1] *= c0;
            o[nt][2] *= c1; o[nt][3] *= c1;
        }
        sum0 += __shfl_xor_sync(0xffffffffu, sum0, 1);
        sum0 += __shfl_xor_sync(0xffffffffu, sum0, 2);
        sum1 += __shfl_xor_sync(0xffffffffu, sum1, 1);
        sum1 += __shfl_xor_sync(0xffffffffu, sum1, 2);
        l0 = l0 * c0 + sum0;
        l1 = l1 * c1 + sum1;
        m0 = mn0; m1 = mn1;

        // O += P V  (x3 corrected), interleaved chains (distance 2)
        #pragma unroll
        for (int kt = 0; kt < 4; kt++) {
            uint32_t pah[4], pal[4];
            {
                const float* t0 = s[2*kt];
                const float* t1 = s[2*kt+1];
                pack_hl(t0[0], t0[1], pah[0], pal[0]);
                pack_hl(t0[2], t0[3], pah[1], pal[1]);
                pack_hl(t1[0], t1[1], pah[2], pal[2]);
                pack_hl(t1[2], t1[3], pah[3], pal[3]);
            }
            #pragma unroll
            for (int db = 0; db < 4; db++) {
                uint32_t vh4[4], vl4[4];
                ldm_x4_t(vh4[0], vh4[1], vh4[2], vh4[3],
                         asw(svh, kt*16 + v_row, db*2 + v_ub));
                ldm_x4_t(vl4[0], vl4[1], vl4[2], vl4[3],
                         asw(svl, kt*16 + v_row, db*2 + v_ub));
                mma16816(o[2*db + 0], pah, &vh4[0]);
                mma16816(o[2*db + 1], pah, &vh4[2]);
                mma16816(o[2*db + 0], pal, &vh4[0]);
                mma16816(o[2*db + 1], pal, &vh4[2]);
                mma16816(o[2*db + 0], pah, &vl4[0]);
                mma16816(o[2*db + 1], pah, &vl4[2]);
            }
        }
    }

    // normalize + write AO hi/lo
    const float inv0 = 1.f / l0;
    const float inv1 = 1.f / l1;
    const int gr0 = b * Ss + q0 + wid*16 + (lid >> 2);
    #pragma unroll
    for (int nt = 0; nt < 8; nt++) {
        const int col = h * HD + nt*8 + (lid & 3)*2;
        float va = o[nt][0] * inv0, vb = o[nt][1] * inv0;
        float vc = o[nt][2] * inv1, vd = o[nt][3] * inv1;
        uint32_t ph0, pl0, ph1, pl1;
        pack_hl(va, vb, ph0, pl0);
        pack_hl(vc, vd, ph1, pl1);
        *(uint32_t*)(g_aoh + (size_t)gr0 * Dd + col)       = ph0;
        *(uint32_t*)(g_aol + (size_t)gr0 * Dd + col)       = pl0;
        *(uint32_t*)(g_aoh + (size_t)(gr0 + 8) * Dd + col) = ph1;
        *(uint32_t*)(g_aol + (size_t)(gr0 + 8) * Dd + col) = pl1;
    }
}

// ---------------------------------------------------------------------------
extern "C" void kernel_launch(void* const* d_in, const int* in_sizes, int n_in,
                              void* d_out, int out_size)
{
    const float* x  = (const float*)d_in[0];
    const float* Wq = (const float*)d_in[1];
    const float* Wk = (const float*)d_in[2];
    const float* Wv = (const float*)d_in[3];
    const float* Wo = (const float*)d_in[4];
    const float* bo = (const float*)d_in[5];
    float* out = (float*)d_out;

    cudaFuncSetAttribute(gemm_qkv_tc, cudaFuncAttributeMaxDynamicSharedMemorySize, GEMM_SMEM);
    cudaFuncSetAttribute(gemm_o_tc,   cudaFuncAttributeMaxDynamicSharedMemorySize, GEMM_SMEM);
    cudaFuncSetAttribute(attn_mma,    cudaFuncAttributeMaxDynamicSharedMemorySize, ATT_SMEM);

    // 1) split fp32 inputs -> bf16 hi/lo (one launch: x quarters + 4 weights)
    dim3 gsp((Dd*Dd)/1024, 8);
    split_all<<<gsp, 256>>>(x, Wq, Wk, Wv, Wo);

    // 2) QKV projections -> bf16 hi/lo (Q pre-scaled by 0.125*log2e)
    dim3 gqkv(Dd / GN, Mtot / GM, 3);
    gemm_qkv_tc<<<gqkv, 256, GEMM_SMEM>>>();

    // 3) HMMA flash attention -> AO hi/lo
    dim3 gattn(Ss / AQ, Bb * Hh);
    attn_mma<<<gattn, 256, ATT_SMEM>>>();

    // 4) output projection (+bias) -> fp32 out
    dim3 gout(Dd / GN, Mtot / GM, 1);
    gemm_o_tc<<<gout, 256, GEMM_SMEM>>>(bo, out);
}

// round 12
// speedup vs baseline: 1.3342x; 1.1432x over previous
#include <cuda_runtime.h>
#include <cuda_bf16.h>
#include <cuda_fp16.h>
#include <math_constants.h>
#include <cstdint>

// Problem constants
#define Bb 2
#define Ss 2048
#define Dd 1024
#define Hh 16
#define HD 64
#define Mtot (Bb*Ss)   // 4096 rows

// ---------------------------------------------------------------------------
// Scratch (__device__ globals; allocation-free rule)
// ---------------------------------------------------------------------------
__device__ __nv_bfloat16 g_xh [Mtot*Dd], g_xl [Mtot*Dd];
__device__ __nv_bfloat16 g_wqh[Dd*Dd],   g_wql[Dd*Dd];
__device__ __nv_bfloat16 g_wkh[Dd*Dd],   g_wkl[Dd*Dd];
__device__ __nv_bfloat16 g_wvh[Dd*Dd],   g_wvl[Dd*Dd];
__device__ __nv_bfloat16 g_woh[Dd*Dd],   g_wol[Dd*Dd];
__device__ __half        g_Qh [Mtot*Dd], g_Ql [Mtot*Dd];   // fp16 hi/lo, pre-scaled 0.125*log2e
__device__ __half        g_Kf [Mtot*Dd];                   // fp16 single
__device__ __half        g_Vf [Mtot*Dd];                   // fp16 single
__device__ __nv_bfloat16 g_aoh[Mtot*Dd], g_aol[Mtot*Dd];

// ---------------------------------------------------------------------------
// PTX helpers (compute_103-safe: ldmatrix / mma.sync / cp.async)
// ---------------------------------------------------------------------------
__device__ __forceinline__ uint32_t smem_u32(const void* p) {
    uint32_t a;
    asm("{ .reg .u64 t; cvta.to.shared.u64 t, %1; cvt.u32.u64 %0, t; }"
        : "=r"(a) : "l"(p));
    return a;
}

__device__ __forceinline__ void ldm_x4(uint32_t& r0, uint32_t& r1,
                                       uint32_t& r2, uint32_t& r3, uint32_t addr) {
    asm volatile("ldmatrix.sync.aligned.m8n8.x4.shared.b16 {%0,%1,%2,%3}, [%4];"
                 : "=r"(r0), "=r"(r1), "=r"(r2), "=r"(r3) : "r"(addr));
}

__device__ __forceinline__ void ldm_x4_t(uint32_t& r0, uint32_t& r1,
                                         uint32_t& r2, uint32_t& r3, uint32_t addr) {
    asm volatile("ldmatrix.sync.aligned.m8n8.x4.trans.shared.b16 {%0,%1,%2,%3}, [%4];"
                 : "=r"(r0), "=r"(r1), "=r"(r2), "=r"(r3) : "r"(addr));
}

// bf16 mma (GEMMs)
__device__ __forceinline__ void mma16816(float* c, const uint32_t* a, const uint32_t* b) {
    asm volatile(
        "mma.sync.aligned.m16n8k16.row.col.f32.bf16.bf16.f32 "
        "{%0,%1,%2,%3}, {%4,%5,%6,%7}, {%8,%9}, {%0,%1,%2,%3};"
        : "+f"(c[0]), "+f"(c[1]), "+f"(c[2]), "+f"(c[3])
        : "r"(a[0]), "r"(a[1]), "r"(a[2]), "r"(a[3]), "r"(b[0]), "r"(b[1]));
}

// fp16 mma (attention)
__device__ __forceinline__ void mma16816h(float* c, const uint32_t* a, const uint32_t* b) {
    asm volatile(
        "mma.sync.aligned.m16n8k16.row.col.f32.f16.f16.f32 "
        "{%0,%1,%2,%3}, {%4,%5,%6,%7}, {%8,%9}, {%0,%1,%2,%3};"
        : "+f"(c[0]), "+f"(c[1]), "+f"(c[2]), "+f"(c[3])
        : "r"(a[0]), "r"(a[1]), "r"(a[2]), "r"(a[3]), "r"(b[0]), "r"(b[1]));
}

#define CP_ASYNC16(dst, src) \
    asm volatile("cp.async.cg.shared.global [%0], [%1], 16;" :: "r"(dst), "l"(src))
#define CP_COMMIT() asm volatile("cp.async.commit_group;" ::: "memory")
#define CP_WAIT(n)  asm volatile("cp.async.wait_group %0;" :: "n"(n) : "memory")

// pack two fp32 -> bf16x2 reg (first arg in low half)
__device__ __forceinline__ uint32_t pk_bf2(float lo, float hi) {
    uint32_t r;
    asm("cvt.rn.bf16x2.f32 %0, %1, %2;" : "=r"(r) : "f"(hi), "f"(lo));
    return r;
}
// pack (a,b) to bf16x2 hi + residual lo (residual via bit-unpack)
__device__ __forceinline__ void pack_hl(float a, float b, uint32_t& ph, uint32_t& pl) {
    ph = pk_bf2(a, b);
    float ra = a - __uint_as_float(ph << 16);
    float rb = b - __uint_as_float(ph & 0xffff0000u);
    pl = pk_bf2(ra, rb);
}

// pack two fp32 -> f16x2 reg (first arg in low half)
__device__ __forceinline__ uint32_t pk_h2(float lo, float hi) {
    uint32_t r;
    asm("cvt.rn.f16x2.f32 %0, %1, %2;" : "=r"(r) : "f"(hi), "f"(lo));
    return r;
}
// pack (a,b) to f16x2 hi + residual lo
__device__ __forceinline__ void pack_hl_f16(float a, float b, uint32_t& ph, uint32_t& pl) {
    ph = pk_h2(a, b);
    float ra = a - __half2float(__ushort_as_half((unsigned short)(ph & 0xffffu)));
    float rb = b - __half2float(__ushort_as_half((unsigned short)(ph >> 16)));
    pl = pk_h2(ra, rb);
}

// ---------------------------------------------------------------------------
// fp32 -> bf16 hi/lo split: all 5 tensors in ONE launch
// ---------------------------------------------------------------------------
__device__ __forceinline__ void split4(const float* __restrict__ src,
                                       __nv_bfloat16* __restrict__ hi,
                                       __nv_bfloat16* __restrict__ lo, int i)
{
    float4 v = *(const float4*)(src + i);
    __nv_bfloat16 ha = __float2bfloat16(v.x);
    __nv_bfloat16 hb = __float2bfloat16(v.y);
    __nv_bfloat16 hc = __float2bfloat16(v.z);
    __nv_bfloat16 hd = __float2bfloat16(v.w);
    __nv_bfloat16 la = __float2bfloat16(v.x - __bfloat162float(ha));
    __nv_bfloat16 lb = __float2bfloat16(v.y - __bfloat162float(hb));
    __nv_bfloat16 lc = __float2bfloat16(v.z - __bfloat162float(hc));
    __nv_bfloat16 ld = __float2bfloat16(v.w - __bfloat162float(hd));
    *(__nv_bfloat162*)(hi + i)     = __halves2bfloat162(ha, hb);
    *(__nv_bfloat162*)(hi + i + 2) = __halves2bfloat162(hc, hd);
    *(__nv_bfloat162*)(lo + i)     = __halves2bfloat162(la, lb);
    *(__nv_bfloat162*)(lo + i + 2) = __halves2bfloat162(lc, ld);
}

__global__ __launch_bounds__(256)
void split_all(const float* __restrict__ x,
               const float* __restrict__ Wq, const float* __restrict__ Wk,
               const float* __restrict__ Wv, const float* __restrict__ Wo)
{
    const int seg = blockIdx.y;
    const float* src; __nv_bfloat16 *hi, *lo;
    int base = 0;
    if (seg < 4) {
        src = x; hi = g_xh; lo = g_xl; base = seg * (Dd*Dd);
    } else if (seg == 4) { src = Wq; hi = g_wqh; lo = g_wql; }
    else if (seg == 5)   { src = Wk; hi = g_wkh; lo = g_wkl; }
    else if (seg == 6)   { src = Wv; hi = g_wvh; lo = g_wvl; }
    else                 { src = Wo; hi = g_woh; lo = g_wol; }
    int i = base + (blockIdx.x * 256 + threadIdx.x) * 4;
    split4(src, hi, lo, i);
}

// ---------------------------------------------------------------------------
// HMMA bf16x3 GEMM. Epilogue MODE: 0 = fp32+bias; 1 = fp16 hi/lo (Q);
// 2 = fp16 single (K,V). Tile 128x128x32, 2-stage cp.async, 2 CTAs/SM.
// ---------------------------------------------------------------------------
#define GM 128
#define GN 128
#define GKC 32
#define NCHUNK (Dd / GKC)        // 32
#define TILEB (128 * GKC * 2)    // 8192
#define STAGEB (4 * TILEB)       // 32KB: AH | AL | BH | BL
#define GEMM_SMEM (2 * STAGEB)   // 64KB

__device__ __forceinline__ uint32_t sw_addr(uint32_t base, int row, int unit) {
    return base + row * 64 + ((unit ^ ((row >> 1) & 3)) << 4);
}

__device__ __forceinline__ void cp_tile(uint32_t sdst, const __nv_bfloat16* __restrict__ g,
                                        int tid)
{
    #pragma unroll
    for (int i = 0; i < 2; i++) {
        int u   = tid + i * 256;
        int row = u >> 2;
        int cu  = u & 3;
        CP_ASYNC16(sw_addr(sdst, row, cu), g + (size_t)row * Dd + cu * 8);
    }
}

__device__ __forceinline__ void cp_stage(uint32_t s,
    const __nv_bfloat16* gAh, const __nv_bfloat16* gAl,
    const __nv_bfloat16* gBh, const __nv_bfloat16* gBl, int kc, int tid)
{
    cp_tile(s,           gAh + kc, tid);
    cp_tile(s + TILEB,   gAl + kc, tid);
    cp_tile(s + 2*TILEB, gBh + kc, tid);
    cp_tile(s + 3*TILEB, gBl + kc, tid);
    CP_COMMIT();
}

template<int MODE>
__device__ __forceinline__ void gemm_tc_body(
    const __nv_bfloat16* __restrict__ Ah, const __nv_bfloat16* __restrict__ Al,
    const __nv_bfloat16* __restrict__ Bh, const __nv_bfloat16* __restrict__ Bl,
    const float* __restrict__ bias, float* __restrict__ C,
    __half* __restrict__ Ch, __half* __restrict__ Cl, float scale)
{
    extern __shared__ char smem[];
    const uint32_t sb = smem_u32(smem);
    const int tid = threadIdx.x;
    const int wid = tid >> 5;
    const int lid = tid & 31;
    const int wm  = wid >> 2;
    const int wn  = wid & 3;
    const int m0  = blockIdx.y * GM;
    const int n0  = blockIdx.x * GN;

    const __nv_bfloat16* gAh = Ah + (size_t)m0 * Dd;
    const __nv_bfloat16* gAl = Al + (size_t)m0 * Dd;
    const __nv_bfloat16* gBh = Bh + (size_t)n0 * Dd;
    const __nv_bfloat16* gBl = Bl + (size_t)n0 * Dd;

    float acc[4][4][4];
    #pragma unroll
    for (int i = 0; i < 4; i++)
        #pragma unroll
        for (int j = 0; j < 4; j++)
            #pragma unroll
            for (int k = 0; k < 4; k++) acc[i][j][k] = 0.f;

    const int a_row = wm * 64 + (lid & 15);
    const int a_ku  = lid >> 4;
    const int b_row = wn * 32 + (lid & 7) + ((lid >> 4) << 3);
    const int b_ku  = (lid >> 3) & 1;

    cp_stage(sb, gAh, gAl, gBh, gBl, 0, tid);

    for (int c = 0; c < NCHUNK; c++) {
        CP_WAIT(0);
        __syncthreads();
        if (c + 1 < NCHUNK)
            cp_stage(sb + ((c + 1) & 1) * STAGEB, gAh, gAl, gBh, gBl, (c + 1) * GKC, tid);

        const uint32_t sa_h = sb + (c & 1) * STAGEB;
        const uint32_t sa_l = sa_h + TILEB;
        const uint32_t sbh  = sa_h + 2*TILEB;
        const uint32_t sbl  = sa_h + 3*TILEB;

        #pragma unroll
        for (int ks = 0; ks < 2; ks++) {
            const int ku = ks * 2;
            uint32_t bh[8], bl[8];
            #pragma unroll
            for (int pr = 0; pr < 2; pr++) {
                ldm_x4(bh[pr*4+0], bh[pr*4+1], bh[pr*4+2], bh[pr*4+3],
                       sw_addr(sbh, b_row + pr*16, ku + b_ku));
                ldm_x4(bl[pr*4+0], bl[pr*4+1], bl[pr*4+2], bl[pr*4+3],
                       sw_addr(sbl, b_row + pr*16, ku + b_ku));
            }
            #pragma unroll
            for (int mt = 0; mt < 4; mt++) {
                uint32_t ah[4], al[4];
                ldm_x4(ah[0], ah[1], ah[2], ah[3],
                       sw_addr(sa_h, a_row + mt*16, ku + a_ku));
                ldm_x4(al[0], al[1], al[2], al[3],
                       sw_addr(sa_l, a_row + mt*16, ku + a_ku));
                #pragma unroll
                for (int nt = 0; nt < 4; nt++)
                    mma16816(acc[mt][nt], ah, &bh[nt*2]);
                #pragma unroll
                for (int nt = 0; nt < 4; nt++)
                    mma16816(acc[mt][nt], al, &bh[nt*2]);
                #pragma unroll
                for (int nt = 0; nt < 4; nt++)
                    mma16816(acc[mt][nt], ah, &bl[nt*2]);
            }
        }
    }

    #pragma unroll
    for (int mt = 0; mt < 4; mt++) {
        const int row = m0 + wm*64 + mt*16 + (lid >> 2);
        #pragma unroll
        for (int nt = 0; nt < 4; nt++) {
            const int col = n0 + wn*32 + nt*8 + (lid & 3)*2;
            #pragma unroll
            for (int half = 0; half < 2; half++) {
                const int r = row + half * 8;
                float va = acc[mt][nt][half*2+0];
                float vb = acc[mt][nt][half*2+1];
                if (MODE == 0) {
                    float2 bv = *(const float2*)(bias + col);
                    *(float2*)(C + (size_t)r * Dd + col) = make_float2(va + bv.x, vb + bv.y);
                } else if (MODE == 1) {
                    uint32_t ph, pl;
                    pack_hl_f16(va * scale, vb * scale, ph, pl);
                    *(uint32_t*)(Ch + (size_t)r * Dd + col) = ph;
                    *(uint32_t*)(Cl + (size_t)r * Dd + col) = pl;
                } else {
                    *(uint32_t*)(Ch + (size_t)r * Dd + col) = pk_h2(va, vb);
                }
            }
        }
    }
}

__global__ __launch_bounds__(256, 2)
void gemm_qkv_tc()
{
    if (blockIdx.z == 0) {
        // Q: fp16 hi/lo, pre-scaled by (1/sqrt(HD)) * log2(e)
        gemm_tc_body<1>(g_xh, g_xl, g_wqh, g_wql, nullptr, nullptr,
                        g_Qh, g_Ql, 0.18033688f);
    } else if (blockIdx.z == 1) {
        gemm_tc_body<2>(g_xh, g_xl, g_wkh, g_wkl, nullptr, nullptr,
                        g_Kf, nullptr, 1.f);
    } else {
        gemm_tc_body<2>(g_xh, g_xl, g_wvh, g_wvl, nullptr, nullptr,
                        g_Vf, nullptr, 1.f);
    }
}

__global__ __launch_bounds__(256, 2)
void gemm_o_tc(const float* bias, float* out)
{
    gemm_tc_body<0>(g_aoh, g_aol, g_woh, g_wol, bias, out, nullptr, nullptr, 1.f);
}

// ---------------------------------------------------------------------------
// fp16 flash attention. Block = 128 q rows of one (b,h); 8 warps x 16 rows.
// Q fp16 hi/lo (hi resident, lo reloaded); K,V single fp16.
// 2-term QK^T (Qh*K + Ql*K), 2-term PV (Ph*V + Pl*V). Base-2 softmax.
// KV chunks of 64 keys, 2-stage cp.async, 2 CTAs/SM.
// ---------------------------------------------------------------------------
#define AQ 128
#define AKC 64
#define SQH 0
#define SQL 16384
#define SKV 32768
#define KVSTAGE 16384   // K 0 | V 8192
#define ATT_SMEM (SKV + 2 * KVSTAGE)   // 65536

__device__ __forceinline__ uint32_t asw(uint32_t base, int row, int unit) {
    return base + row * 128 + ((unit ^ (row & 7)) << 4);
}

__device__ __forceinline__ void cp_kv(uint32_t sbase, int brow0, int h, int tid)
{
    #pragma unroll
    for (int i = 0; i < 2; i++) {
        int u = tid + i * 256;
        int row = u >> 3;
        int un = u & 7;
        size_t g = ((size_t)(brow0 + row)) * Dd + h * HD + un * 8;
        CP_ASYNC16(asw(sbase,        row, un), g_Kf + g);
        CP_ASYNC16(asw(sbase + 8192, row, un), g_Vf + g);
    }
    CP_COMMIT();
}

__global__ __launch_bounds__(256, 2)
void attn_mma()
{
    extern __shared__ char smem[];
    const uint32_t sb = smem_u32(smem);
    const int tid = threadIdx.x;
    const int wid = tid >> 5;
    const int lid = tid & 31;
    const int q0  = blockIdx.x * AQ;
    const int b   = blockIdx.y >> 4;
    const int h   = blockIdx.y & 15;

    // stage Q (hi/lo): 128 rows x 8 units each
    #pragma unroll
    for (int i = 0; i < 4; i++) {
        int u = tid + i * 256;
        int row = u >> 3;
        int un = u & 7;
        size_t g = ((size_t)(b * Ss + q0 + row)) * Dd + h * HD + un * 8;
        CP_ASYNC16(asw(sb + SQH, row, un), g_Qh + g);
        CP_ASYNC16(asw(sb + SQL, row, un), g_Ql + g);
    }
    CP_COMMIT();

    // prologue KV chunk 0 -> stage 0
    cp_kv(sb + SKV, b * Ss, h, tid);

    CP_WAIT(1);   // Q resident
    __syncthreads();

    const int q_r  = wid * 16 + (lid & 15);
    const int q_ub = lid >> 4;

    // Q-hi fragments resident; Q-lo reloaded per chunk
    uint32_t qh[4][4];
    #pragma unroll
    for (int ks = 0; ks < 4; ks++)
        ldm_x4(qh[ks][0], qh[ks][1], qh[ks][2], qh[ks][3],
               asw(sb + SQH, q_r, ks*2 + q_ub));

    float o[8][4];
    #pragma unroll
    for (int i = 0; i < 8; i++)
        #pragma unroll
        for (int j = 0; j < 4; j++) o[i][j] = 0.f;
    float m0 = -CUDART_INF_F, m1 = -CUDART_INF_F, l0 = 0.f, l1 = 0.f;

    const int kb_row = (lid & 7) + ((lid >> 4) << 3);
    const int kb_ku  = (lid >> 3) & 1;
    const int v_row  = lid & 15;
    const int v_ub   = lid >> 4;

    const int NC = Ss / AKC;    // 32
    for (int c = 0; c < NC; c++) {
        CP_WAIT(0);
        __syncthreads();
        if (c + 1 < NC)
            cp_kv(sb + SKV + ((c + 1) & 1) * KVSTAGE, b * Ss + (c + 1) * AKC, h, tid);

        const uint32_t sk = sb + SKV + (c & 1) * KVSTAGE;
        const uint32_t sv = sk + 8192;

        // S = Q K^T  (fp16 x2), 16x64 per warp; scores in log2 domain
        float s[8][4];
        #pragma unroll
        for (int i = 0; i < 8; i++)
            #pragma unroll
            for (int j = 0; j < 4; j++) s[i][j] = 0.f;

        #pragma unroll
        for (int ks = 0; ks < 4; ks++) {
            uint32_t ql4[4];
            ldm_x4(ql4[0], ql4[1], ql4[2], ql4[3],
                   asw(sb + SQL, q_r, ks*2 + q_ub));
            #pragma unroll
            for (int g = 0; g < 4; g++) {
                uint32_t k4[4];
                ldm_x4(k4[0], k4[1], k4[2], k4[3],
                       asw(sk, g*16 + kb_row, ks*2 + kb_ku));
                mma16816h(s[2*g],   qh[ks], &k4[0]);
                mma16816h(s[2*g+1], qh[ks], &k4[2]);
                mma16816h(s[2*g],   ql4,    &k4[0]);
                mma16816h(s[2*g+1], ql4,    &k4[2]);
            }
        }

        // online softmax, base 2
        float rm0 = fmaxf(s[0][0], s[0][1]);
        float rm1 = fmaxf(s[0][2], s[0][3]);
        #pragma unroll
        for (int nt = 1; nt < 8; nt++) {
            rm0 = fmaxf(rm0, fmaxf(s[nt][0], s[nt][1]));
            rm1 = fmaxf(rm1, fmaxf(s[nt][2], s[nt][3]));
        }
        rm0 = fmaxf(rm0, __shfl_xor_sync(0xffffffffu, rm0, 1));
        rm0 = fmaxf(rm0, __shfl_xor_sync(0xffffffffu, rm0, 2));
        rm1 = fmaxf(rm1, __shfl_xor_sync(0xffffffffu, rm1, 1));
        rm1 = fmaxf(rm1, __shfl_xor_sync(0xffffffffu, rm1, 2));
        const float mn0 = fmaxf(m0, rm0);
        const float mn1 = fmaxf(m1, rm1);
        const float c0 = exp2f(m0 - mn0);
        const float c1 = exp2f(m1 - mn1);
        float sum0 = 0.f, sum1 = 0.f;
        #pragma unroll
        for (int nt = 0; nt < 8; nt++) {
            s[nt][0] = exp2f(s[nt][0] - mn0); sum0 += s[nt][0];
            s[nt][1] = exp2f(s[nt][1] - mn0); sum0 += s[nt][1];
            s[nt][2] = exp2f(s[nt][2] - mn1); sum1 += s[nt][2];
            s[nt][3] = exp2f(s[nt][3] - mn1); sum1 += s[nt][3];
            o[nt][0] *= c0; o[nt][1] *= c0;
            o[nt][2] *= c1; o[nt][3] *= c1;
        }
        sum0 += __shfl_xor_sync(0xffffffffu, sum0, 1);
        sum0 += __shfl_xor_sync(0xffffffffu, sum0, 2);
        sum1 += __shfl_xor_sync(0xffffffffu, sum1, 1);
        sum1 += __shfl_xor_sync(0xffffffffu, sum1, 2);
        l0 = l0 * c0 + sum0;
        l1 = l1 * c1 + sum1;
        m0 = mn0; m1 = mn1;

        // O += P V  (fp16 x2: P hi/lo, V single)
        #pragma unroll
        for (int kt = 0; kt < 4; kt++) {
            uint32_t pah[4], pal[4];
            {
                const float* t0 = s[2*kt];
                const float* t1 = s[2*kt+1];
                pack_hl_f16(t0[0], t0[1], pah[0], pal[0]);
                pack_hl_f16(t0[2], t0[3], pah[1], pal[1]);
                pack_hl_f16(t1[0], t1[1], pah[2], pal[2]);
                pack_hl_f16(t1[2], t1[3], pah[3], pal[3]);
            }
            #pragma unroll
            for (int db = 0; db < 4; db++) {
                uint32_t v4[4];
                ldm_x4_t(v4[0], v4[1], v4[2], v4[3],
                         asw(sv, kt*16 + v_row, db*2 + v_ub));
                mma16816h(o[2*db + 0], pah, &v4[0]);
                mma16816h(o[2*db + 1], pah, &v4[2]);
                mma16816h(o[2*db + 0], pal, &v4[0]);
                mma16816h(o[2*db + 1], pal, &v4[2]);
            }
        }
    }

    // normalize + write AO as bf16 hi/lo (feeds bf16x3 out-projection)
    const float inv0 = 1.f / l0;
    const float inv1 = 1.f / l1;
    const int gr0 = b * Ss + q0 + wid*16 + (lid >> 2);
    #pragma unroll
    for (int nt = 0; nt < 8; nt++) {
        const int col = h * HD + nt*8 + (lid & 3)*2;
        float va = o[nt][0] * inv0, vb = o[nt][1] * inv0;
        float vc = o[nt][2] * inv1, vd = o[nt][3] * inv1;
        uint32_t ph0, pl0, ph1, pl1;
        pack_hl(va, vb, ph0, pl0);
        pack_hl(vc, vd, ph1, pl1);
        *(uint32_t*)(g_aoh + (size_t)gr0 * Dd + col)       = ph0;
        *(uint32_t*)(g_aol + (size_t)gr0 * Dd + col)       = pl0;
        *(uint32_t*)(g_aoh + (size_t)(gr0 + 8) * Dd + col) = ph1;
        *(uint32_t*)(g_aol + (size_t)(gr0 + 8) * Dd + col) = pl1;
    }
}

// ---------------------------------------------------------------------------
extern "C" void kernel_launch(void* const* d_in, const int* in_sizes, int n_in,
                              void* d_out, int out_size)
{
    const float* x  = (const float*)d_in[0];
    const float* Wq = (const float*)d_in[1];
    const float* Wk = (const float*)d_in[2];
    const float* Wv = (const float*)d_in[3];
    const float* Wo = (const float*)d_in[4];
    const float* bo = (const float*)d_in[5];
    float* out = (float*)d_out;

    cudaFuncSetAttribute(gemm_qkv_tc, cudaFuncAttributeMaxDynamicSharedMemorySize, GEMM_SMEM);
    cudaFuncSetAttribute(gemm_o_tc,   cudaFuncAttributeMaxDynamicSharedMemorySize, GEMM_SMEM);
    cudaFuncSetAttribute(attn_mma,    cudaFuncAttributeMaxDynamicSharedMemorySize, ATT_SMEM);

    // 1) split fp32 inputs -> bf16 hi/lo (one launch)
    dim3 gsp((Dd*Dd)/1024, 8);
    split_all<<<gsp, 256>>>(x, Wq, Wk, Wv, Wo);

    // 2) QKV projections: Q -> fp16 hi/lo (pre-scaled), K/V -> fp16
    dim3 gqkv(Dd / GN, Mtot / GM, 3);
    gemm_qkv_tc<<<gqkv, 256, GEMM_SMEM>>>();

    // 3) fp16 flash attention -> AO bf16 hi/lo
    dim3 gattn(Ss / AQ, Bb * Hh);
    attn_mma<<<gattn, 256, ATT_SMEM>>>();

    // 4) output projection (+bias) -> fp32 out
    dim3 gout(Dd / GN, Mtot / GM, 1);
    gemm_o_tc<<<gout, 256, GEMM_SMEM>>>(bo, out);
}

// round 13
// speedup vs baseline: 1.6255x; 1.2183x over previous
#include <cuda_runtime.h>
#include <cuda_bf16.h>
#include <cuda_fp16.h>
#include <math_constants.h>
#include <cstdint>

// Problem constants
#define Bb 2
#define Ss 2048
#define Dd 1024
#define Hh 16
#define HD 64
#define Mtot (Bb*Ss)   // 4096 rows

// ---------------------------------------------------------------------------
// Scratch (__device__ globals; allocation-free rule)
// ---------------------------------------------------------------------------
__device__ __half g_xh [Mtot*Dd], g_xl [Mtot*Dd];   // x fp16 hi/lo
__device__ __half g_wqf[Dd*Dd];                     // weights fp16 single
__device__ __half g_wkf[Dd*Dd];
__device__ __half g_wvf[Dd*Dd];
__device__ __half g_wof[Dd*Dd];
__device__ __half g_Qh [Mtot*Dd], g_Ql [Mtot*Dd];   // fp16 hi/lo, pre-scaled 0.125*log2e
__device__ __half g_Kf [Mtot*Dd];                   // fp16 single
__device__ __half g_Vf [Mtot*Dd];                   // fp16 single
__device__ __half g_aoh[Mtot*Dd], g_aol[Mtot*Dd];   // AO fp16 hi/lo

// ---------------------------------------------------------------------------
// PTX helpers (compute_103-safe: ldmatrix / mma.sync / cp.async)
// ---------------------------------------------------------------------------
__device__ __forceinline__ uint32_t smem_u32(const void* p) {
    uint32_t a;
    asm("{ .reg .u64 t; cvta.to.shared.u64 t, %1; cvt.u32.u64 %0, t; }"
        : "=r"(a) : "l"(p));
    return a;
}

__device__ __forceinline__ void ldm_x4(uint32_t& r0, uint32_t& r1,
                                       uint32_t& r2, uint32_t& r3, uint32_t addr) {
    asm volatile("ldmatrix.sync.aligned.m8n8.x4.shared.b16 {%0,%1,%2,%3}, [%4];"
                 : "=r"(r0), "=r"(r1), "=r"(r2), "=r"(r3) : "r"(addr));
}

__device__ __forceinline__ void ldm_x4_t(uint32_t& r0, uint32_t& r1,
                                         uint32_t& r2, uint32_t& r3, uint32_t addr) {
    asm volatile("ldmatrix.sync.aligned.m8n8.x4.trans.shared.b16 {%0,%1,%2,%3}, [%4];"
                 : "=r"(r0), "=r"(r1), "=r"(r2), "=r"(r3) : "r"(addr));
}

// fp16 mma
__device__ __forceinline__ void mma16816h(float* c, const uint32_t* a, const uint32_t* b) {
    asm volatile(
        "mma.sync.aligned.m16n8k16.row.col.f32.f16.f16.f32 "
        "{%0,%1,%2,%3}, {%4,%5,%6,%7}, {%8,%9}, {%0,%1,%2,%3};"
        : "+f"(c[0]), "+f"(c[1]), "+f"(c[2]), "+f"(c[3])
        : "r"(a[0]), "r"(a[1]), "r"(a[2]), "r"(a[3]), "r"(b[0]), "r"(b[1]));
}

#define CP_ASYNC16(dst, src) \
    asm volatile("cp.async.cg.shared.global [%0], [%1], 16;" :: "r"(dst), "l"(src))
#define CP_COMMIT() asm volatile("cp.async.commit_group;" ::: "memory")
#define CP_WAIT(n)  asm volatile("cp.async.wait_group %0;" :: "n"(n) : "memory")

// pack two fp32 -> f16x2 reg (first arg in low half)
__device__ __forceinline__ uint32_t pk_h2(float lo, float hi) {
    uint32_t r;
    asm("cvt.rn.f16x2.f32 %0, %1, %2;" : "=r"(r) : "f"(hi), "f"(lo));
    return r;
}
// pack (a,b) to f16x2 hi + residual lo
__device__ __forceinline__ void pack_hl_f16(float a, float b, uint32_t& ph, uint32_t& pl) {
    ph = pk_h2(a, b);
    float ra = a - __half2float(__ushort_as_half((unsigned short)(ph & 0xffffu)));
    float rb = b - __half2float(__ushort_as_half((unsigned short)(ph >> 16)));
    pl = pk_h2(ra, rb);
}

// ---------------------------------------------------------------------------
// Splits: x -> fp16 hi/lo; weights -> fp16 single. One launch.
// blockIdx.y: 0..3 -> quarter of x; 4..7 -> Wq/Wk/Wv/Wo
// ---------------------------------------------------------------------------
__global__ __launch_bounds__(256)
void split_all(const float* __restrict__ x,
               const float* __restrict__ Wq, const float* __restrict__ Wk,
               const float* __restrict__ Wv, const float* __restrict__ Wo)
{
    const int seg = blockIdx.y;
    if (seg < 4) {
        int i = seg * (Dd*Dd) + (blockIdx.x * 256 + threadIdx.x) * 4;
        float4 v = *(const float4*)(x + i);
        uint32_t ph0, pl0, ph1, pl1;
        pack_hl_f16(v.x, v.y, ph0, pl0);
        pack_hl_f16(v.z, v.w, ph1, pl1);
        *(uint32_t*)(g_xh + i)     = ph0;
        *(uint32_t*)(g_xh + i + 2) = ph1;
        *(uint32_t*)(g_xl + i)     = pl0;
        *(uint32_t*)(g_xl + i + 2) = pl1;
    } else {
        const float* src; __half* dst;
        if (seg == 4)      { src = Wq; dst = g_wqf; }
        else if (seg == 5) { src = Wk; dst = g_wkf; }
        else if (seg == 6) { src = Wv; dst = g_wvf; }
        else               { src = Wo; dst = g_wof; }
        int i = (blockIdx.x * 256 + threadIdx.x) * 4;
        float4 v = *(const float4*)(src + i);
        *(uint32_t*)(dst + i)     = pk_h2(v.x, v.y);
        *(uint32_t*)(dst + i + 2) = pk_h2(v.z, v.w);
    }
}

// ---------------------------------------------------------------------------
// fp16 x2 GEMM: C = (Ah+Al) @ B^T, A fp16 hi/lo, B fp16 single.
// Epilogue MODE: 0 = fp32+bias; 1 = fp16 hi/lo (Q, scaled); 2 = fp16 single.
// Tile 128x128x32, 8 warps, warp tile 64x32, 2-stage cp.async, 2 CTAs/SM.
// ---------------------------------------------------------------------------
#define GM 128
#define GN 128
#define GKC 32
#define NCHUNK (Dd / GKC)        // 32
#define TILEB (128 * GKC * 2)    // 8192
#define STAGEB (3 * TILEB)       // 24KB: AH | AL | B
#define GEMM_SMEM (2 * STAGEB)   // 48KB

__device__ __forceinline__ uint32_t sw_addr(uint32_t base, int row, int unit) {
    return base + row * 64 + ((unit ^ ((row >> 1) & 3)) << 4);
}

__device__ __forceinline__ void cp_tile(uint32_t sdst, const __half* __restrict__ g,
                                        int tid)
{
    #pragma unroll
    for (int i = 0; i < 2; i++) {
        int u   = tid + i * 256;
        int row = u >> 2;
        int cu  = u & 3;
        CP_ASYNC16(sw_addr(sdst, row, cu), g + (size_t)row * Dd + cu * 8);
    }
}

__device__ __forceinline__ void cp_stage(uint32_t s,
    const __half* gAh, const __half* gAl, const __half* gB, int kc, int tid)
{
    cp_tile(s,           gAh + kc, tid);
    cp_tile(s + TILEB,   gAl + kc, tid);
    cp_tile(s + 2*TILEB, gB  + kc, tid);
    CP_COMMIT();
}

template<int MODE>
__device__ __forceinline__ void gemm_tc_body(
    const __half* __restrict__ Ah, const __half* __restrict__ Al,
    const __half* __restrict__ B,
    const float* __restrict__ bias, float* __restrict__ C,
    __half* __restrict__ Ch, __half* __restrict__ Cl, float scale)
{
    extern __shared__ char smem[];
    const uint32_t sb = smem_u32(smem);
    const int tid = threadIdx.x;
    const int wid = tid >> 5;
    const int lid = tid & 31;
    const int wm  = wid >> 2;
    const int wn  = wid & 3;
    const int m0  = blockIdx.y * GM;
    const int n0  = blockIdx.x * GN;

    const __half* gAh = Ah + (size_t)m0 * Dd;
    const __half* gAl = Al + (size_t)m0 * Dd;
    const __half* gB  = B  + (size_t)n0 * Dd;

    float acc[4][4][4];
    #pragma unroll
    for (int i = 0; i < 4; i++)
        #pragma unroll
        for (int j = 0; j < 4; j++)
            #pragma unroll
            for (int k = 0; k < 4; k++) acc[i][j][k] = 0.f;

    const int a_row = wm * 64 + (lid & 15);
    const int a_ku  = lid >> 4;
    const int b_row = wn * 32 + (lid & 7) + ((lid >> 4) << 3);
    const int b_ku  = (lid >> 3) & 1;

    cp_stage(sb, gAh, gAl, gB, 0, tid);

    for (int c = 0; c < NCHUNK; c++) {
        CP_WAIT(0);
        __syncthreads();
        if (c + 1 < NCHUNK)
            cp_stage(sb + ((c + 1) & 1) * STAGEB, gAh, gAl, gB, (c + 1) * GKC, tid);

        const uint32_t sa_h = sb + (c & 1) * STAGEB;
        const uint32_t sa_l = sa_h + TILEB;
        const uint32_t sbb  = sa_h + 2*TILEB;

        #pragma unroll
        for (int ks = 0; ks < 2; ks++) {
            const int ku = ks * 2;
            uint32_t bf[8];
            #pragma unroll
            for (int pr = 0; pr < 2; pr++)
                ldm_x4(bf[pr*4+0], bf[pr*4+1], bf[pr*4+2], bf[pr*4+3],
                       sw_addr(sbb, b_row + pr*16, ku + b_ku));
            #pragma unroll
            for (int mt = 0; mt < 4; mt++) {
                uint32_t ah[4], al[4];
                ldm_x4(ah[0], ah[1], ah[2], ah[3],
                       sw_addr(sa_h, a_row + mt*16, ku + a_ku));
                ldm_x4(al[0], al[1], al[2], al[3],
                       sw_addr(sa_l, a_row + mt*16, ku + a_ku));
                #pragma unroll
                for (int nt = 0; nt < 4; nt++)
                    mma16816h(acc[mt][nt], ah, &bf[nt*2]);
                #pragma unroll
                for (int nt = 0; nt < 4; nt++)
                    mma16816h(acc[mt][nt], al, &bf[nt*2]);
            }
        }
    }

    #pragma unroll
    for (int mt = 0; mt < 4; mt++) {
        const int row = m0 + wm*64 + mt*16 + (lid >> 2);
        #pragma unroll
        for (int nt = 0; nt < 4; nt++) {
            const int col = n0 + wn*32 + nt*8 + (lid & 3)*2;
            #pragma unroll
            for (int half = 0; half < 2; half++) {
                const int r = row + half * 8;
                float va = acc[mt][nt][half*2+0];
                float vb = acc[mt][nt][half*2+1];
                if (MODE == 0) {
                    float2 bv = *(const float2*)(bias + col);
                    *(float2*)(C + (size_t)r * Dd + col) = make_float2(va + bv.x, vb + bv.y);
                } else if (MODE == 1) {
                    uint32_t ph, pl;
                    pack_hl_f16(va * scale, vb * scale, ph, pl);
                    *(uint32_t*)(Ch + (size_t)r * Dd + col) = ph;
                    *(uint32_t*)(Cl + (size_t)r * Dd + col) = pl;
                } else {
                    *(uint32_t*)(Ch + (size_t)r * Dd + col) = pk_h2(va, vb);
                }
            }
        }
    }
}

__global__ __launch_bounds__(256, 2)
void gemm_qkv_tc()
{
    if (blockIdx.z == 0) {
        // Q: fp16 hi/lo, pre-scaled by (1/sqrt(HD)) * log2(e)
        gemm_tc_body<1>(g_xh, g_xl, g_wqf, nullptr, nullptr,
                        g_Qh, g_Ql, 0.18033688f);
    } else if (blockIdx.z == 1) {
        gemm_tc_body<2>(g_xh, g_xl, g_wkf, nullptr, nullptr,
                        g_Kf, nullptr, 1.f);
    } else {
        gemm_tc_body<2>(g_xh, g_xl, g_wvf, nullptr, nullptr,
                        g_Vf, nullptr, 1.f);
    }
}

__global__ __launch_bounds__(256, 2)
void gemm_o_tc(const float* bias, float* out)
{
    gemm_tc_body<0>(g_aoh, g_aol, g_wof, bias, out, nullptr, nullptr, 1.f);
}

// ---------------------------------------------------------------------------
// fp16 flash attention (unchanged from R12). Block = 128 q rows of one (b,h).
// Q fp16 hi/lo (hi resident, lo reloaded); K,V single fp16.
// 2-term QK^T, 2-term PV. Base-2 softmax. 2-stage cp.async, 2 CTAs/SM.
// ---------------------------------------------------------------------------
#define AQ 128
#define AKC 64
#define SQH 0
#define SQL 16384
#define SKV 32768
#define KVSTAGE 16384   // K 0 | V 8192
#define ATT_SMEM (SKV + 2 * KVSTAGE)   // 65536

__device__ __forceinline__ uint32_t asw(uint32_t base, int row, int unit) {
    return base + row * 128 + ((unit ^ (row & 7)) << 4);
}

__device__ __forceinline__ void cp_kv(uint32_t sbase, int brow0, int h, int tid)
{
    #pragma unroll
    for (int i = 0; i < 2; i++) {
        int u = tid + i * 256;
        int row = u >> 3;
        int un = u & 7;
        size_t g = ((size_t)(brow0 + row)) * Dd + h * HD + un * 8;
        CP_ASYNC16(asw(sbase,        row, un), g_Kf + g);
        CP_ASYNC16(asw(sbase + 8192, row, un), g_Vf + g);
    }
    CP_COMMIT();
}

__global__ __launch_bounds__(256, 2)
void attn_mma()
{
    extern __shared__ char smem[];
    const uint32_t sb = smem_u32(smem);
    const int tid = threadIdx.x;
    const int wid = tid >> 5;
    const int lid = tid & 31;
    const int q0  = blockIdx.x * AQ;
    const int b   = blockIdx.y >> 4;
    const int h   = blockIdx.y & 15;

    // stage Q (hi/lo): 128 rows x 8 units each
    #pragma unroll
    for (int i = 0; i < 4; i++) {
        int u = tid + i * 256;
        int row = u >> 3;
        int un = u & 7;
        size_t g = ((size_t)(b * Ss + q0 + row)) * Dd + h * HD + un * 8;
        CP_ASYNC16(asw(sb + SQH, row, un), g_Qh + g);
        CP_ASYNC16(asw(sb + SQL, row, un), g_Ql + g);
    }
    CP_COMMIT();

    // prologue KV chunk 0 -> stage 0
    cp_kv(sb + SKV, b * Ss, h, tid);

    CP_WAIT(1);   // Q resident
    __syncthreads();

    const int q_r  = wid * 16 + (lid & 15);
    const int q_ub = lid >> 4;

    // Q-hi fragments resident; Q-lo reloaded per chunk
    uint32_t qh[4][4];
    #pragma unroll
    for (int ks = 0; ks < 4; ks++)
        ldm_x4(qh[ks][0], qh[ks][1], qh[ks][2], qh[ks][3],
               asw(sb + SQH, q_r, ks*2 + q_ub));

    float o[8][4];
    #pragma unroll
    for (int i = 0; i < 8; i++)
        #pragma unroll
        for (int j = 0; j < 4; j++) o[i][j] = 0.f;
    float m0 = -CUDART_INF_F, m1 = -CUDART_INF_F, l0 = 0.f, l1 = 0.f;

    const int kb_row = (lid & 7) + ((lid >> 4) << 3);
    const int kb_ku  = (lid >> 3) & 1;
    const int v_row  = lid & 15;
    const int v_ub   = lid >> 4;

    const int NC = Ss / AKC;    // 32
    for (int c = 0; c < NC; c++) {
        CP_WAIT(0);
        __syncthreads();
        if (c + 1 < NC)
            cp_kv(sb + SKV + ((c + 1) & 1) * KVSTAGE, b * Ss + (c + 1) * AKC, h, tid);

        const uint32_t sk = sb + SKV + (c & 1) * KVSTAGE;
        const uint32_t sv = sk + 8192;

        // S = Q K^T  (fp16 x2), 16x64 per warp; scores in log2 domain
        float s[8][4];
        #pragma unroll
        for (int i = 0; i < 8; i++)
            #pragma unroll
            for (int j = 0; j < 4; j++) s[i][j] = 0.f;

        #pragma unroll
        for (int ks = 0; ks < 4; ks++) {
            uint32_t ql4[4];
            ldm_x4(ql4[0], ql4[1], ql4[2], ql4[3],
                   asw(sb + SQL, q_r, ks*2 + q_ub));
            #pragma unroll
            for (int g = 0; g < 4; g++) {
                uint32_t k4[4];
                ldm_x4(k4[0], k4[1], k4[2], k4[3],
                       asw(sk, g*16 + kb_row, ks*2 + kb_ku));
                mma16816h(s[2*g],   qh[ks], &k4[0]);
                mma16816h(s[2*g+1], qh[ks], &k4[2]);
                mma16816h(s[2*g],   ql4,    &k4[0]);
                mma16816h(s[2*g+1], ql4,    &k4[2]);
            }
        }

        // online softmax, base 2
        float rm0 = fmaxf(s[0][0], s[0][1]);
        float rm1 = fmaxf(s[0][2], s[0][3]);
        #pragma unroll
        for (int nt = 1; nt < 8; nt++) {
            rm0 = fmaxf(rm0, fmaxf(s[nt][0], s[nt][1]));
            rm1 = fmaxf(rm1, fmaxf(s[nt][2], s[nt][3]));
        }
        rm0 = fmaxf(rm0, __shfl_xor_sync(0xffffffffu, rm0, 1));
        rm0 = fmaxf(rm0, __shfl_xor_sync(0xffffffffu, rm0, 2));
        rm1 = fmaxf(rm1, __shfl_xor_sync(0xffffffffu, rm1, 1));
        rm1 = fmaxf(rm1, __shfl_xor_sync(0xffffffffu, rm1, 2));
        const float mn0 = fmaxf(m0, rm0);
        const float mn1 = fmaxf(m1, rm1);
        const float c0 = exp2f(m0 - mn0);
        const float c1 = exp2f(m1 - mn1);
        float sum0 = 0.f, sum1 = 0.f;
        #pragma unroll
        for (int nt = 0; nt < 8; nt++) {
            s[nt][0] = exp2f(s[nt][0] - mn0); sum0 += s[nt][0];
            s[nt][1] = exp2f(s[nt][1] - mn0); sum0 += s[nt][1];
            s[nt][2] = exp2f(s[nt][2] - mn1); sum1 += s[nt][2];
            s[nt][3] = exp2f(s[nt][3] - mn1); sum1 += s[nt][3];
            o[nt][0] *= c0; o[nt][1] *= c0;
            o[nt][2] *= c1; o[nt][3] *= c1;
        }
        sum0 += __shfl_xor_sync(0xffffffffu, sum0, 1);
        sum0 += __shfl_xor_sync(0xffffffffu, sum0, 2);
        sum1 += __shfl_xor_sync(0xffffffffu, sum1, 1);
        sum1 += __shfl_xor_sync(0xffffffffu, sum1, 2);
        l0 = l0 * c0 + sum0;
        l1 = l1 * c1 + sum1;
        m0 = mn0; m1 = mn1;

        // O += P V  (fp16 x2: P hi/lo, V single)
        #pragma unroll
        for (int kt = 0; kt < 4; kt++) {
            uint32_t pah[4], pal[4];
            {
                const float* t0 = s[2*kt];
                const float* t1 = s[2*kt+1];
                pack_hl_f16(t0[0], t0[1], pah[0], pal[0]);
                pack_hl_f16(t0[2], t0[3], pah[1], pal[1]);
                pack_hl_f16(t1[0], t1[1], pah[2], pal[2]);
                pack_hl_f16(t1[2], t1[3], pah[3], pal[3]);
            }
            #pragma unroll
            for (int db = 0; db < 4; db++) {
                uint32_t v4[4];
                ldm_x4_t(v4[0], v4[1], v4[2], v4[3],
                         asw(sv, kt*16 + v_row, db*2 + v_ub));
                mma16816h(o[2*db + 0], pah, &v4[0]);
                mma16816h(o[2*db + 1], pah, &v4[2]);
                mma16816h(o[2*db + 0], pal, &v4[0]);
                mma16816h(o[2*db + 1], pal, &v4[2]);
            }
        }
    }

    // normalize + write AO as fp16 hi/lo (feeds fp16x2 out-projection)
    const float inv0 = 1.f / l0;
    const float inv1 = 1.f / l1;
    const int gr0 = b * Ss + q0 + wid*16 + (lid >> 2);
    #pragma unroll
    for (int nt = 0; nt < 8; nt++) {
        const int col = h * HD + nt*8 + (lid & 3)*2;
        float va = o[nt][0] * inv0, vb = o[nt][1] * inv0;
        float vc = o[nt][2] * inv1, vd = o[nt][3] * inv1;
        uint32_t ph0, pl0, ph1, pl1;
        pack_hl_f16(va, vb, ph0, pl0);
        pack_hl_f16(vc, vd, ph1, pl1);
        *(uint32_t*)(g_aoh + (size_t)gr0 * Dd + col)       = ph0;
        *(uint32_t*)(g_aol + (size_t)gr0 * Dd + col)       = pl0;
        *(uint32_t*)(g_aoh + (size_t)(gr0 + 8) * Dd + col) = ph1;
        *(uint32_t*)(g_aol + (size_t)(gr0 + 8) * Dd + col) = pl1;
    }
}

// ---------------------------------------------------------------------------
extern "C" void kernel_launch(void* const* d_in, const int* in_sizes, int n_in,
                              void* d_out, int out_size)
{
    const float* x  = (const float*)d_in[0];
    const float* Wq = (const float*)d_in[1];
    const float* Wk = (const float*)d_in[2];
    const float* Wv = (const float*)d_in[3];
    const float* Wo = (const float*)d_in[4];
    const float* bo = (const float*)d_in[5];
    float* out = (float*)d_out;

    cudaFuncSetAttribute(gemm_qkv_tc, cudaFuncAttributeMaxDynamicSharedMemorySize, GEMM_SMEM);
    cudaFuncSetAttribute(gemm_o_tc,   cudaFuncAttributeMaxDynamicSharedMemorySize, GEMM_SMEM);
    cudaFuncSetAttribute(attn_mma,    cudaFuncAttributeMaxDynamicSharedMemorySize, ATT_SMEM);

    // 1) split: x -> fp16 hi/lo, weights -> fp16 single (one launch)
    dim3 gsp((Dd*Dd)/1024, 8);
    split_all<<<gsp, 256>>>(x, Wq, Wk, Wv, Wo);

    // 2) QKV projections (fp16 x2): Q -> fp16 hi/lo (pre-scaled), K/V -> fp16
    dim3 gqkv(Dd / GN, Mtot / GM, 3);
    gemm_qkv_tc<<<gqkv, 256, GEMM_SMEM>>>();

    // 3) fp16 flash attention -> AO fp16 hi/lo
    dim3 gattn(Ss / AQ, Bb * Hh);
    attn_mma<<<gattn, 256, ATT_SMEM>>>();

    // 4) output projection (fp16 x2, +bias) -> fp32 out
    dim3 gout(Dd / GN, Mtot / GM, 1);
    gemm_o_tc<<<gout, 256, GEMM_SMEM>>>(bo, out);
}

// round 14
// speedup vs baseline: 1.8883x; 1.1617x over previous
#include <cuda_runtime.h>
#include <cuda_bf16.h>
#include <cuda_fp16.h>
#include <math_constants.h>
#include <cstdint>

// Problem constants
#define Bb 2
#define Ss 2048
#define Dd 1024
#define Hh 16
#define HD 64
#define Mtot (Bb*Ss)   // 4096 rows

// ---------------------------------------------------------------------------
// Scratch (__device__ globals; allocation-free rule)
// ---------------------------------------------------------------------------
__device__ __half g_xh [Mtot*Dd], g_xl [Mtot*Dd];   // x fp16 hi/lo
__device__ __half g_wqf[Dd*Dd];                     // weights fp16 single
__device__ __half g_wkf[Dd*Dd];
__device__ __half g_wvf[Dd*Dd];
__device__ __half g_wof[Dd*Dd];
__device__ __half g_Qh [Mtot*Dd], g_Ql [Mtot*Dd];   // fp16 hi/lo, pre-scaled 0.125*log2e
__device__ __half g_Kf [Mtot*Dd];                   // fp16 single
__device__ __half g_Vf [Mtot*Dd];                   // fp16 single
__device__ __half g_aoh[Mtot*Dd], g_aol[Mtot*Dd];   // AO fp16 hi/lo

// ---------------------------------------------------------------------------
// PTX helpers (compute_103-safe: ldmatrix / mma.sync / cp.async)
// ---------------------------------------------------------------------------
__device__ __forceinline__ uint32_t smem_u32(const void* p) {
    uint32_t a;
    asm("{ .reg .u64 t; cvta.to.shared.u64 t, %1; cvt.u32.u64 %0, t; }"
        : "=r"(a) : "l"(p));
    return a;
}

__device__ __forceinline__ void ldm_x4(uint32_t& r0, uint32_t& r1,
                                       uint32_t& r2, uint32_t& r3, uint32_t addr) {
    asm volatile("ldmatrix.sync.aligned.m8n8.x4.shared.b16 {%0,%1,%2,%3}, [%4];"
                 : "=r"(r0), "=r"(r1), "=r"(r2), "=r"(r3) : "r"(addr));
}

__device__ __forceinline__ void ldm_x4_t(uint32_t& r0, uint32_t& r1,
                                         uint32_t& r2, uint32_t& r3, uint32_t addr) {
    asm volatile("ldmatrix.sync.aligned.m8n8.x4.trans.shared.b16 {%0,%1,%2,%3}, [%4];"
                 : "=r"(r0), "=r"(r1), "=r"(r2), "=r"(r3) : "r"(addr));
}

// fp16 mma
__device__ __forceinline__ void mma16816h(float* c, const uint32_t* a, const uint32_t* b) {
    asm volatile(
        "mma.sync.aligned.m16n8k16.row.col.f32.f16.f16.f32 "
        "{%0,%1,%2,%3}, {%4,%5,%6,%7}, {%8,%9}, {%0,%1,%2,%3};"
        : "+f"(c[0]), "+f"(c[1]), "+f"(c[2]), "+f"(c[3])
        : "r"(a[0]), "r"(a[1]), "r"(a[2]), "r"(a[3]), "r"(b[0]), "r"(b[1]));
}

#define CP_ASYNC16(dst, src) \
    asm volatile("cp.async.cg.shared.global [%0], [%1], 16;" :: "r"(dst), "l"(src))
#define CP_COMMIT() asm volatile("cp.async.commit_group;" ::: "memory")
#define CP_WAIT(n)  asm volatile("cp.async.wait_group %0;" :: "n"(n) : "memory")

// pack two fp32 -> f16x2 reg (first arg in low half)
__device__ __forceinline__ uint32_t pk_h2(float lo, float hi) {
    uint32_t r;
    asm("cvt.rn.f16x2.f32 %0, %1, %2;" : "=r"(r) : "f"(hi), "f"(lo));
    return r;
}
// pack (a,b) to f16x2 hi + residual lo
__device__ __forceinline__ void pack_hl_f16(float a, float b, uint32_t& ph, uint32_t& pl) {
    ph = pk_h2(a, b);
    float ra = a - __half2float(__ushort_as_half((unsigned short)(ph & 0xffffu)));
    float rb = b - __half2float(__ushort_as_half((unsigned short)(ph >> 16)));
    pl = pk_h2(ra, rb);
}

// shared 128B-row swizzle: 8 x 16B units per row, unit ^= row&7
__device__ __forceinline__ uint32_t asw(uint32_t base, int row, int unit) {
    return base + row * 128 + ((unit ^ (row & 7)) << 4);
}

// ---------------------------------------------------------------------------
// Splits: x -> fp16 hi/lo; weights -> fp16 single. One launch.
// blockIdx.y: 0..3 -> quarter of x; 4..7 -> Wq/Wk/Wv/Wo
// ---------------------------------------------------------------------------
__global__ __launch_bounds__(256)
void split_all(const float* __restrict__ x,
               const float* __restrict__ Wq, const float* __restrict__ Wk,
               const float* __restrict__ Wv, const float* __restrict__ Wo)
{
    const int seg = blockIdx.y;
    if (seg < 4) {
        int i = seg * (Dd*Dd) + (blockIdx.x * 256 + threadIdx.x) * 4;
        float4 v = *(const float4*)(x + i);
        uint32_t ph0, pl0, ph1, pl1;
        pack_hl_f16(v.x, v.y, ph0, pl0);
        pack_hl_f16(v.z, v.w, ph1, pl1);
        *(uint32_t*)(g_xh + i)     = ph0;
        *(uint32_t*)(g_xh + i + 2) = ph1;
        *(uint32_t*)(g_xl + i)     = pl0;
        *(uint32_t*)(g_xl + i + 2) = pl1;
    } else {
        const float* src; __half* dst;
        if (seg == 4)      { src = Wq; dst = g_wqf; }
        else if (seg == 5) { src = Wk; dst = g_wkf; }
        else if (seg == 6) { src = Wv; dst = g_wvf; }
        else               { src = Wo; dst = g_wof; }
        int i = (blockIdx.x * 256 + threadIdx.x) * 4;
        float4 v = *(const float4*)(src + i);
        *(uint32_t*)(dst + i)     = pk_h2(v.x, v.y);
        *(uint32_t*)(dst + i + 2) = pk_h2(v.z, v.w);
    }
}

// ---------------------------------------------------------------------------
// fp16 x2 GEMM: C = (Ah+Al) @ B^T, A fp16 hi/lo, B fp16 single.
// Epilogue MODE: 0 = fp32+bias; 1 = fp16 hi/lo (Q, scaled); 2 = fp16 single.
// Tile 128x128x64 (K-chunk 64), 8 warps, 2-stage cp.async, 2 CTAs/SM.
// ---------------------------------------------------------------------------
#define GM 128
#define GN 128
#define GKC 64
#define NCHUNK (Dd / GKC)        // 16
#define TILEB (128 * GKC * 2)    // 16384 (128 rows x 128B)
#define STAGEB (3 * TILEB)       // 48KB: AH | AL | B
#define GEMM_SMEM (2 * STAGEB)   // 96KB

__device__ __forceinline__ void cp_tile(uint32_t sdst, const __half* __restrict__ g,
                                        int tid)
{
    #pragma unroll
    for (int i = 0; i < 4; i++) {
        int u   = tid + i * 256;     // 0..1023
        int row = u >> 3;
        int un  = u & 7;
        CP_ASYNC16(asw(sdst, row, un), g + (size_t)row * Dd + un * 8);
    }
}

__device__ __forceinline__ void cp_stage(uint32_t s,
    const __half* gAh, const __half* gAl, const __half* gB, int kc, int tid)
{
    cp_tile(s,           gAh + kc, tid);
    cp_tile(s + TILEB,   gAl + kc, tid);
    cp_tile(s + 2*TILEB, gB  + kc, tid);
    CP_COMMIT();
}

template<int MODE>
__device__ __forceinline__ void gemm_tc_body(
    const __half* __restrict__ Ah, const __half* __restrict__ Al,
    const __half* __restrict__ B,
    const float* __restrict__ bias, float* __restrict__ C,
    __half* __restrict__ Ch, __half* __restrict__ Cl, float scale)
{
    extern __shared__ char smem[];
    const uint32_t sb = smem_u32(smem);
    const int tid = threadIdx.x;
    const int wid = tid >> 5;
    const int lid = tid & 31;
    const int wm  = wid >> 2;
    const int wn  = wid & 3;
    const int m0  = blockIdx.y * GM;
    const int n0  = blockIdx.x * GN;

    const __half* gAh = Ah + (size_t)m0 * Dd;
    const __half* gAl = Al + (size_t)m0 * Dd;
    const __half* gB  = B  + (size_t)n0 * Dd;

    float acc[4][4][4];
    #pragma unroll
    for (int i = 0; i < 4; i++)
        #pragma unroll
        for (int j = 0; j < 4; j++)
            #pragma unroll
            for (int k = 0; k < 4; k++) acc[i][j][k] = 0.f;

    const int a_row = wm * 64 + (lid & 15);
    const int a_ku  = lid >> 4;
    const int b_row = wn * 32 + (lid & 7) + ((lid >> 4) << 3);
    const int b_ku  = (lid >> 3) & 1;

    cp_stage(sb, gAh, gAl, gB, 0, tid);

    for (int c = 0; c < NCHUNK; c++) {
        CP_WAIT(0);
        __syncthreads();
        if (c + 1 < NCHUNK)
            cp_stage(sb + ((c + 1) & 1) * STAGEB, gAh, gAl, gB, (c + 1) * GKC, tid);

        const uint32_t sa_h = sb + (c & 1) * STAGEB;
        const uint32_t sa_l = sa_h + TILEB;
        const uint32_t sbb  = sa_h + 2*TILEB;

        #pragma unroll
        for (int ks = 0; ks < 4; ks++) {       // 4 k16 steps per 64-chunk
            const int ku = ks * 2;
            uint32_t bf[8];
            #pragma unroll
            for (int pr = 0; pr < 2; pr++)
                ldm_x4(bf[pr*4+0], bf[pr*4+1], bf[pr*4+2], bf[pr*4+3],
                       asw(sbb, b_row + pr*16, ku + b_ku));
            #pragma unroll
            for (int mt = 0; mt < 4; mt++) {
                uint32_t ah[4], al[4];
                ldm_x4(ah[0], ah[1], ah[2], ah[3],
                       asw(sa_h, a_row + mt*16, ku + a_ku));
                ldm_x4(al[0], al[1], al[2], al[3],
                       asw(sa_l, a_row + mt*16, ku + a_ku));
                #pragma unroll
                for (int nt = 0; nt < 4; nt++)
                    mma16816h(acc[mt][nt], ah, &bf[nt*2]);
                #pragma unroll
                for (int nt = 0; nt < 4; nt++)
                    mma16816h(acc[mt][nt], al, &bf[nt*2]);
            }
        }
    }

    #pragma unroll
    for (int mt = 0; mt < 4; mt++) {
        const int row = m0 + wm*64 + mt*16 + (lid >> 2);
        #pragma unroll
        for (int nt = 0; nt < 4; nt++) {
            const int col = n0 + wn*32 + nt*8 + (lid & 3)*2;
            #pragma unroll
            for (int half = 0; half < 2; half++) {
                const int r = row + half * 8;
                float va = acc[mt][nt][half*2+0];
                float vb = acc[mt][nt][half*2+1];
                if (MODE == 0) {
                    float2 bv = *(const float2*)(bias + col);
                    *(float2*)(C + (size_t)r * Dd + col) = make_float2(va + bv.x, vb + bv.y);
                } else if (MODE == 1) {
                    uint32_t ph, pl;
                    pack_hl_f16(va * scale, vb * scale, ph, pl);
                    *(uint32_t*)(Ch + (size_t)r * Dd + col) = ph;
                    *(uint32_t*)(Cl + (size_t)r * Dd + col) = pl;
                } else {
                    *(uint32_t*)(Ch + (size_t)r * Dd + col) = pk_h2(va, vb);
                }
            }
        }
    }
}

__global__ __launch_bounds__(256, 2)
void gemm_qkv_tc()
{
    if (blockIdx.z == 0) {
        // Q: fp16 hi/lo, pre-scaled by (1/sqrt(HD)) * log2(e)
        gemm_tc_body<1>(g_xh, g_xl, g_wqf, nullptr, nullptr,
                        g_Qh, g_Ql, 0.18033688f);
    } else if (blockIdx.z == 1) {
        gemm_tc_body<2>(g_xh, g_xl, g_wkf, nullptr, nullptr,
                        g_Kf, nullptr, 1.f);
    } else {
        gemm_tc_body<2>(g_xh, g_xl, g_wvf, nullptr, nullptr,
                        g_Vf, nullptr, 1.f);
    }
}

__global__ __launch_bounds__(256, 2)
void gemm_o_tc(const float* bias, float* out)
{
    gemm_tc_body<0>(g_aoh, g_aol, g_wof, bias, out, nullptr, nullptr, 1.f);
}

// ---------------------------------------------------------------------------
// fp16 flash attention. Block = 128 q rows of one (b,h); 8 warps x 16 rows.
// Q fp16 hi/lo (hi resident, lo reloaded); K,V single fp16; P single fp16.
// 2-term QK^T, 1-term PV. Base-2 softmax. 2-stage cp.async, 2 CTAs/SM.
// ---------------------------------------------------------------------------
#define AQ 128
#define AKC 64
#define SQH 0
#define SQL 16384
#define SKV 32768
#define KVSTAGE 16384   // K 0 | V 8192
#define ATT_SMEM (SKV + 2 * KVSTAGE)   // 65536

__device__ __forceinline__ void cp_kv(uint32_t sbase, int brow0, int h, int tid)
{
    #pragma unroll
    for (int i = 0; i < 2; i++) {
        int u = tid + i * 256;
        int row = u >> 3;
        int un = u & 7;
        size_t g = ((size_t)(brow0 + row)) * Dd + h * HD + un * 8;
        CP_ASYNC16(asw(sbase,        row, un), g_Kf + g);
        CP_ASYNC16(asw(sbase + 8192, row, un), g_Vf + g);
    }
    CP_COMMIT();
}

__global__ __launch_bounds__(256, 2)
void attn_mma()
{
    extern __shared__ char smem[];
    const uint32_t sb = smem_u32(smem);
    const int tid = threadIdx.x;
    const int wid = tid >> 5;
    const int lid = tid & 31;
    const int q0  = blockIdx.x * AQ;
    const int b   = blockIdx.y >> 4;
    const int h   = blockIdx.y & 15;

    // stage Q (hi/lo): 128 rows x 8 units each
    #pragma unroll
    for (int i = 0; i < 4; i++) {
        int u = tid + i * 256;
        int row = u >> 3;
        int un = u & 7;
        size_t g = ((size_t)(b * Ss + q0 + row)) * Dd + h * HD + un * 8;
        CP_ASYNC16(asw(sb + SQH, row, un), g_Qh + g);
        CP_ASYNC16(asw(sb + SQL, row, un), g_Ql + g);
    }
    CP_COMMIT();

    // prologue KV chunk 0 -> stage 0
    cp_kv(sb + SKV, b * Ss, h, tid);

    CP_WAIT(1);   // Q resident
    __syncthreads();

    const int q_r  = wid * 16 + (lid & 15);
    const int q_ub = lid >> 4;

    // Q-hi fragments resident; Q-lo reloaded per chunk
    uint32_t qh[4][4];
    #pragma unroll
    for (int ks = 0; ks < 4; ks++)
        ldm_x4(qh[ks][0], qh[ks][1], qh[ks][2], qh[ks][3],
               asw(sb + SQH, q_r, ks*2 + q_ub));

    float o[8][4];
    #pragma unroll
    for (int i = 0; i < 8; i++)
        #pragma unroll
        for (int j = 0; j < 4; j++) o[i][j] = 0.f;
    float m0 = -CUDART_INF_F, m1 = -CUDART_INF_F, l0 = 0.f, l1 = 0.f;

    const int kb_row = (lid & 7) + ((lid >> 4) << 3);
    const int kb_ku  = (lid >> 3) & 1;
    const int v_row  = lid & 15;
    const int v_ub   = lid >> 4;

    const int NC = Ss / AKC;    // 32
    for (int c = 0; c < NC; c++) {
        CP_WAIT(0);
        __syncthreads();
        if (c + 1 < NC)
            cp_kv(sb + SKV + ((c + 1) & 1) * KVSTAGE, b * Ss + (c + 1) * AKC, h, tid);

        const uint32_t sk = sb + SKV + (c & 1) * KVSTAGE;
        const uint32_t sv = sk + 8192;

        // S = Q K^T  (fp16 x2), 16x64 per warp; scores in log2 domain
        float s[8][4];
        #pragma unroll
        for (int i = 0; i < 8; i++)
            #pragma unroll
            for (int j = 0; j < 4; j++) s[i][j] = 0.f;

        #pragma unroll
        for (int ks = 0; ks < 4; ks++) {
            uint32_t ql4[4];
            ldm_x4(ql4[0], ql4[1], ql4[2], ql4[3],
                   asw(sb + SQL, q_r, ks*2 + q_ub));
            #pragma unroll
            for (int g = 0; g < 4; g++) {
                uint32_t k4[4];
                ldm_x4(k4[0], k4[1], k4[2], k4[3],
                       asw(sk, g*16 + kb_row, ks*2 + kb_ku));
                mma16816h(s[2*g],   qh[ks], &k4[0]);
                mma16816h(s[2*g+1], qh[ks], &k4[2]);
                mma16816h(s[2*g],   ql4,    &k4[0]);
                mma16816h(s[2*g+1], ql4,    &k4[2]);
            }
        }

        // online softmax, base 2
        float rm0 = fmaxf(s[0][0], s[0][1]);
        float rm1 = fmaxf(s[0][2], s[0][3]);
        #pragma unroll
        for (int nt = 1; nt < 8; nt++) {
            rm0 = fmaxf(rm0, fmaxf(s[nt][0], s[nt][1]));
            rm1 = fmaxf(rm1, fmaxf(s[nt][2], s[nt][3]));
        }
        rm0 = fmaxf(rm0, __shfl_xor_sync(0xffffffffu, rm0, 1));
        rm0 = fmaxf(rm0, __shfl_xor_sync(0xffffffffu, rm0, 2));
        rm1 = fmaxf(rm1, __shfl_xor_sync(0xffffffffu, rm1, 1));
        rm1 = fmaxf(rm1, __shfl_xor_sync(0xffffffffu, rm1, 2));
        const float mn0 = fmaxf(m0, rm0);
        const float mn1 = fmaxf(m1, rm1);
        const float c0 = exp2f(m0 - mn0);
        const float c1 = exp2f(m1 - mn1);
        float sum0 = 0.f, sum1 = 0.f;
        #pragma unroll
        for (int nt = 0; nt < 8; nt++) {
            s[nt][0] = exp2f(s[nt][0] - mn0); sum0 += s[nt][0];
            s[nt][1] = exp2f(s[nt][1] - mn0); sum0 += s[nt][1];
            s[nt][2] = exp2f(s[nt][2] - mn1); sum1 += s[nt][2];
            s[nt][3] = exp2f(s[nt][3] - mn1); sum1 += s[nt][3];
            o[nt][0] *= c0; o[nt][1] *= c0;
            o[nt][2] *= c1; o[nt][3] *= c1;
        }
        sum0 += __shfl_xor_sync(0xffffffffu, sum0, 1);
        sum0 += __shfl_xor_sync(0xffffffffu, sum0, 2);
        sum1 += __shfl_xor_sync(0xffffffffu, sum1, 1);
        sum1 += __shfl_xor_sync(0xffffffffu, sum1, 2);
        l0 = l0 * c0 + sum0;
        l1 = l1 * c1 + sum1;
        m0 = mn0; m1 = mn1;

        // O += P V  (P single fp16, V single fp16: 1 mma per pair)
        #pragma unroll
        for (int kt = 0; kt < 4; kt++) {
            uint32_t pa[4];
            {
                const float* t0 = s[2*kt];
                const float* t1 = s[2*kt+1];
                pa[0] = pk_h2(t0[0], t0[1]);
                pa[1] = pk_h2(t0[2], t0[3]);
                pa[2] = pk_h2(t1[0], t1[1]);
                pa[3] = pk_h2(t1[2], t1[3]);
            }
            #pragma unroll
            for (int db = 0; db < 4; db++) {
                uint32_t v4[4];
                ldm_x4_t(v4[0], v4[1], v4[2], v4[3],
                         asw(sv, kt*16 + v_row, db*2 + v_ub));
                mma16816h(o[2*db + 0], pa, &v4[0]);
                mma16816h(o[2*db + 1], pa, &v4[2]);
            }
        }
    }

    // normalize + write AO as fp16 hi/lo (feeds fp16x2 out-projection)
    const float inv0 = 1.f / l0;
    const float inv1 = 1.f / l1;
    const int gr0 = b * Ss + q0 + wid*16 + (lid >> 2);
    #pragma unroll
    for (int nt = 0; nt < 8; nt++) {
        const int col = h * HD + nt*8 + (lid & 3)*2;
        float va = o[nt][0] * inv0, vb = o[nt][1] * inv0;
        float vc = o[nt][2] * inv1, vd = o[nt][3] * inv1;
        uint32_t ph0, pl0, ph1, pl1;
        pack_hl_f16(va, vb, ph0, pl0);
        pack_hl_f16(vc, vd, ph1, pl1);
        *(uint32_t*)(g_aoh + (size_t)gr0 * Dd + col)       = ph0;
        *(uint32_t*)(g_aol + (size_t)gr0 * Dd + col)       = pl0;
        *(uint32_t*)(g_aoh + (size_t)(gr0 + 8) * Dd + col) = ph1;
        *(uint32_t*)(g_aol + (size_t)(gr0 + 8) * Dd + col) = pl1;
    }
}

// ---------------------------------------------------------------------------
extern "C" void kernel_launch(void* const* d_in, const int* in_sizes, int n_in,
                              void* d_out, int out_size)
{
    const float* x  = (const float*)d_in[0];
    const float* Wq = (const float*)d_in[1];
    const float* Wk = (const float*)d_in[2];
    const float* Wv = (const float*)d_in[3];
    const float* Wo = (const float*)d_in[4];
    const float* bo = (const float*)d_in[5];
    float* out = (float*)d_out;

    cudaFuncSetAttribute(gemm_qkv_tc, cudaFuncAttributeMaxDynamicSharedMemorySize, GEMM_SMEM);
    cudaFuncSetAttribute(gemm_o_tc,   cudaFuncAttributeMaxDynamicSharedMemorySize, GEMM_SMEM);
    cudaFuncSetAttribute(attn_mma,    cudaFuncAttributeMaxDynamicSharedMemorySize, ATT_SMEM);

    // 1) split: x -> fp16 hi/lo, weights -> fp16 single (one launch)
    dim3 gsp((Dd*Dd)/1024, 8);
    split_all<<<gsp, 256>>>(x, Wq, Wk, Wv, Wo);

    // 2) QKV projections (fp16 x2): Q -> fp16 hi/lo (pre-scaled), K/V -> fp16
    dim3 gqkv(Dd / GN, Mtot / GM, 3);
    gemm_qkv_tc<<<gqkv, 256, GEMM_SMEM>>>();

    // 3) fp16 flash attention -> AO fp16 hi/lo
    dim3 gattn(Ss / AQ, Bb * Hh);
    attn_mma<<<gattn, 256, ATT_SMEM>>>();

    // 4) output projection (fp16 x2, +bias) -> fp32 out
    dim3 gout(Dd / GN, Mtot / GM, 1);
    gemm_o_tc<<<gout, 256, GEMM_SMEM>>>(bo, out);
}

// round 15
// speedup vs baseline: 2.8126x; 1.4895x over previous
#include <cuda_runtime.h>
#include <cuda_fp16.h>
#include <math_constants.h>
#include <cstdint>

// Problem constants
#define Bb 2
#define Ss 2048
#define Dd 1024
#define Hh 16
#define HD 64
#define Mtot (Bb*Ss)   // 4096 rows

// ---------------------------------------------------------------------------
// Scratch (__device__ globals; allocation-free rule) — all single fp16
// ---------------------------------------------------------------------------
__device__ __half g_xf [Mtot*Dd];
__device__ __half g_wqf[Dd*Dd];
__device__ __half g_wkf[Dd*Dd];
__device__ __half g_wvf[Dd*Dd];
__device__ __half g_wof[Dd*Dd];
__device__ __half g_Qf [Mtot*Dd];   // pre-scaled by 0.125*log2(e)
__device__ __half g_Kf [Mtot*Dd];
__device__ __half g_Vf [Mtot*Dd];
__device__ __half g_aof[Mtot*Dd];

// ---------------------------------------------------------------------------
// PTX helpers (compute_103-safe: ldmatrix / mma.sync / cp.async)
// ---------------------------------------------------------------------------
__device__ __forceinline__ uint32_t smem_u32(const void* p) {
    uint32_t a;
    asm("{ .reg .u64 t; cvta.to.shared.u64 t, %1; cvt.u32.u64 %0, t; }"
        : "=r"(a) : "l"(p));
    return a;
}

__device__ __forceinline__ void ldm_x4(uint32_t& r0, uint32_t& r1,
                                       uint32_t& r2, uint32_t& r3, uint32_t addr) {
    asm volatile("ldmatrix.sync.aligned.m8n8.x4.shared.b16 {%0,%1,%2,%3}, [%4];"
                 : "=r"(r0), "=r"(r1), "=r"(r2), "=r"(r3) : "r"(addr));
}

__device__ __forceinline__ void ldm_x4_t(uint32_t& r0, uint32_t& r1,
                                         uint32_t& r2, uint32_t& r3, uint32_t addr) {
    asm volatile("ldmatrix.sync.aligned.m8n8.x4.trans.shared.b16 {%0,%1,%2,%3}, [%4];"
                 : "=r"(r0), "=r"(r1), "=r"(r2), "=r"(r3) : "r"(addr));
}

// fp16 mma
__device__ __forceinline__ void mma16816h(float* c, const uint32_t* a, const uint32_t* b) {
    asm volatile(
        "mma.sync.aligned.m16n8k16.row.col.f32.f16.f16.f32 "
        "{%0,%1,%2,%3}, {%4,%5,%6,%7}, {%8,%9}, {%0,%1,%2,%3};"
        : "+f"(c[0]), "+f"(c[1]), "+f"(c[2]), "+f"(c[3])
        : "r"(a[0]), "r"(a[1]), "r"(a[2]), "r"(a[3]), "r"(b[0]), "r"(b[1]));
}

#define CP_ASYNC16(dst, src) \
    asm volatile("cp.async.cg.shared.global [%0], [%1], 16;" :: "r"(dst), "l"(src))
#define CP_COMMIT() asm volatile("cp.async.commit_group;" ::: "memory")
#define CP_WAIT(n)  asm volatile("cp.async.wait_group %0;" :: "n"(n) : "memory")

// pack two fp32 -> f16x2 reg (first arg in low half)
__device__ __forceinline__ uint32_t pk_h2(float lo, float hi) {
    uint32_t r;
    asm("cvt.rn.f16x2.f32 %0, %1, %2;" : "=r"(r) : "f"(hi), "f"(lo));
    return r;
}

// shared 128B-row swizzle: 8 x 16B units per row, unit ^= row&7
__device__ __forceinline__ uint32_t asw(uint32_t base, int row, int unit) {
    return base + row * 128 + ((unit ^ (row & 7)) << 4);
}

// ---------------------------------------------------------------------------
// Split: fp32 -> fp16 single for x + 4 weights, one launch.
// blockIdx.y: 0..3 -> quarter of x; 4..7 -> Wq/Wk/Wv/Wo
// ---------------------------------------------------------------------------
__global__ __launch_bounds__(256)
void split_all(const float* __restrict__ x,
               const float* __restrict__ Wq, const float* __restrict__ Wk,
               const float* __restrict__ Wv, const float* __restrict__ Wo)
{
    const int seg = blockIdx.y;
    const float* src; __half* dst; int base = 0;
    if (seg < 4)       { src = x;  dst = g_xf;  base = seg * (Dd*Dd); }
    else if (seg == 4) { src = Wq; dst = g_wqf; }
    else if (seg == 5) { src = Wk; dst = g_wkf; }
    else if (seg == 6) { src = Wv; dst = g_wvf; }
    else               { src = Wo; dst = g_wof; }
    int i = base + (blockIdx.x * 256 + threadIdx.x) * 4;
    float4 v = *(const float4*)(src + (seg < 4 ? i : i - base) + (seg < 4 ? 0 : 0));
    // note: for x, src index includes base; for weights it shouldn't
    if (seg < 4) v = *(const float4*)(x + i);
    else         v = *(const float4*)(src + (i - base));
    *(uint32_t*)(dst + i)     = pk_h2(v.x, v.y);
    *(uint32_t*)(dst + i + 2) = pk_h2(v.z, v.w);
}

// ---------------------------------------------------------------------------
// fp16 GEMM: C = A @ B^T, both single fp16 (1 mma per k16).
// Epilogue MODE: 0 = fp32+bias -> C; 1 = fp16 single (scaled) -> Ch.
// Tile 128x128x64, 8 warps, warp tile 64x32, 2-stage cp.async, 2 CTAs/SM.
// ---------------------------------------------------------------------------
#define GM 128
#define GN 128
#define GKC 64
#define NCHUNK (Dd / GKC)        // 16
#define TILEB (128 * GKC * 2)    // 16384 (128 rows x 128B)
#define STAGEB (2 * TILEB)       // 32KB: A | B
#define GEMM_SMEM (2 * STAGEB)   // 64KB

__device__ __forceinline__ void cp_tile(uint32_t sdst, const __half* __restrict__ g,
                                        int tid)
{
    #pragma unroll
    for (int i = 0; i < 4; i++) {
        int u   = tid + i * 256;     // 0..1023
        int row = u >> 3;
        int un  = u & 7;
        CP_ASYNC16(asw(sdst, row, un), g + (size_t)row * Dd + un * 8);
    }
}

__device__ __forceinline__ void cp_stage(uint32_t s,
    const __half* gA, const __half* gB, int kc, int tid)
{
    cp_tile(s,         gA + kc, tid);
    cp_tile(s + TILEB, gB + kc, tid);
    CP_COMMIT();
}

template<int MODE>
__device__ __forceinline__ void gemm_tc_body(
    const __half* __restrict__ A, const __half* __restrict__ B,
    const float* __restrict__ bias, float* __restrict__ C,
    __half* __restrict__ Ch, float scale)
{
    extern __shared__ char smem[];
    const uint32_t sb = smem_u32(smem);
    const int tid = threadIdx.x;
    const int wid = tid >> 5;
    const int lid = tid & 31;
    const int wm  = wid >> 2;
    const int wn  = wid & 3;
    const int m0  = blockIdx.y * GM;
    const int n0  = blockIdx.x * GN;

    const __half* gA = A + (size_t)m0 * Dd;
    const __half* gB = B + (size_t)n0 * Dd;

    float acc[4][4][4];
    #pragma unroll
    for (int i = 0; i < 4; i++)
        #pragma unroll
        for (int j = 0; j < 4; j++)
            #pragma unroll
            for (int k = 0; k < 4; k++) acc[i][j][k] = 0.f;

    const int a_row = wm * 64 + (lid & 15);
    const int a_ku  = lid >> 4;
    const int b_row = wn * 32 + (lid & 7) + ((lid >> 4) << 3);
    const int b_ku  = (lid >> 3) & 1;

    cp_stage(sb, gA, gB, 0, tid);

    for (int c = 0; c < NCHUNK; c++) {
        CP_WAIT(0);
        __syncthreads();
        if (c + 1 < NCHUNK)
            cp_stage(sb + ((c + 1) & 1) * STAGEB, gA, gB, (c + 1) * GKC, tid);

        const uint32_t sa  = sb + (c & 1) * STAGEB;
        const uint32_t sbb = sa + TILEB;

        #pragma unroll
        for (int ks = 0; ks < 4; ks++) {       // 4 k16 steps per 64-chunk
            const int ku = ks * 2;
            uint32_t bf[8];
            #pragma unroll
            for (int pr = 0; pr < 2; pr++)
                ldm_x4(bf[pr*4+0], bf[pr*4+1], bf[pr*4+2], bf[pr*4+3],
                       asw(sbb, b_row + pr*16, ku + b_ku));
            #pragma unroll
            for (int mt = 0; mt < 4; mt++) {
                uint32_t af[4];
                ldm_x4(af[0], af[1], af[2], af[3],
                       asw(sa, a_row + mt*16, ku + a_ku));
                #pragma unroll
                for (int nt = 0; nt < 4; nt++)
                    mma16816h(acc[mt][nt], af, &bf[nt*2]);
            }
        }
    }

    #pragma unroll
    for (int mt = 0; mt < 4; mt++) {
        const int row = m0 + wm*64 + mt*16 + (lid >> 2);
        #pragma unroll
        for (int nt = 0; nt < 4; nt++) {
            const int col = n0 + wn*32 + nt*8 + (lid & 3)*2;
            #pragma unroll
            for (int half = 0; half < 2; half++) {
                const int r = row + half * 8;
                float va = acc[mt][nt][half*2+0];
                float vb = acc[mt][nt][half*2+1];
                if (MODE == 0) {
                    float2 bv = *(const float2*)(bias + col);
                    *(float2*)(C + (size_t)r * Dd + col) = make_float2(va + bv.x, vb + bv.y);
                } else {
                    *(uint32_t*)(Ch + (size_t)r * Dd + col) = pk_h2(va * scale, vb * scale);
                }
            }
        }
    }
}

__global__ __launch_bounds__(256, 2)
void gemm_qkv_tc()
{
    if (blockIdx.z == 0) {
        // Q pre-scaled by (1/sqrt(HD)) * log2(e) for base-2 softmax
        gemm_tc_body<1>(g_xf, g_wqf, nullptr, nullptr, g_Qf, 0.18033688f);
    } else if (blockIdx.z == 1) {
        gemm_tc_body<1>(g_xf, g_wkf, nullptr, nullptr, g_Kf, 1.f);
    } else {
        gemm_tc_body<1>(g_xf, g_wvf, nullptr, nullptr, g_Vf, 1.f);
    }
}

__global__ __launch_bounds__(256, 2)
void gemm_o_tc(const float* bias, float* out)
{
    gemm_tc_body<0>(g_aof, g_wof, bias, out, nullptr, 1.f);
}

// ---------------------------------------------------------------------------
// fp16 flash attention, all operands single fp16 (1-term everywhere).
// Block = 128 q rows of one (b,h); 8 warps x 16 rows. KV chunks of 64 keys,
// 2-stage cp.async, 2 CTAs/SM, base-2 softmax.
// ---------------------------------------------------------------------------
#define AQ 128
#define AKC 64
#define SQ 0
#define SKV 16384
#define KVSTAGE 16384   // K 0 | V 8192
#define ATT_SMEM (SKV + 2 * KVSTAGE)   // 49152

__device__ __forceinline__ void cp_kv(uint32_t sbase, int brow0, int h, int tid)
{
    #pragma unroll
    for (int i = 0; i < 2; i++) {
        int u = tid + i * 256;
        int row = u >> 3;
        int un = u & 7;
        size_t g = ((size_t)(brow0 + row)) * Dd + h * HD + un * 8;
        CP_ASYNC16(asw(sbase,        row, un), g_Kf + g);
        CP_ASYNC16(asw(sbase + 8192, row, un), g_Vf + g);
    }
    CP_COMMIT();
}

__global__ __launch_bounds__(256, 2)
void attn_mma()
{
    extern __shared__ char smem[];
    const uint32_t sb = smem_u32(smem);
    const int tid = threadIdx.x;
    const int wid = tid >> 5;
    const int lid = tid & 31;
    const int q0  = blockIdx.x * AQ;
    const int b   = blockIdx.y >> 4;
    const int h   = blockIdx.y & 15;

    // stage Q: 128 rows x 8 units
    #pragma unroll
    for (int i = 0; i < 4; i++) {
        int u = tid + i * 256;
        int row = u >> 3;
        int un = u & 7;
        size_t g = ((size_t)(b * Ss + q0 + row)) * Dd + h * HD + un * 8;
        CP_ASYNC16(asw(sb + SQ, row, un), g_Qf + g);
    }
    CP_COMMIT();

    // prologue KV chunk 0 -> stage 0
    cp_kv(sb + SKV, b * Ss, h, tid);

    CP_WAIT(1);   // Q resident
    __syncthreads();

    const int q_r  = wid * 16 + (lid & 15);
    const int q_ub = lid >> 4;

    // Q fragments resident (16 regs)
    uint32_t qf[4][4];
    #pragma unroll
    for (int ks = 0; ks < 4; ks++)
        ldm_x4(qf[ks][0], qf[ks][1], qf[ks][2], qf[ks][3],
               asw(sb + SQ, q_r, ks*2 + q_ub));

    float o[8][4];
    #pragma unroll
    for (int i = 0; i < 8; i++)
        #pragma unroll
        for (int j = 0; j < 4; j++) o[i][j] = 0.f;
    float m0 = -CUDART_INF_F, m1 = -CUDART_INF_F, l0 = 0.f, l1 = 0.f;

    const int kb_row = (lid & 7) + ((lid >> 4) << 3);
    const int kb_ku  = (lid >> 3) & 1;
    const int v_row  = lid & 15;
    const int v_ub   = lid >> 4;

    const int NC = Ss / AKC;    // 32
    for (int c = 0; c < NC; c++) {
        CP_WAIT(0);
        __syncthreads();
        if (c + 1 < NC)
            cp_kv(sb + SKV + ((c + 1) & 1) * KVSTAGE, b * Ss + (c + 1) * AKC, h, tid);

        const uint32_t sk = sb + SKV + (c & 1) * KVSTAGE;
        const uint32_t sv = sk + 8192;

        // S = Q K^T (1 term), 16x64 per warp; scores in log2 domain
        float s[8][4];
        #pragma unroll
        for (int i = 0; i < 8; i++)
            #pragma unroll
            for (int j = 0; j < 4; j++) s[i][j] = 0.f;

        #pragma unroll
        for (int ks = 0; ks < 4; ks++) {
            #pragma unroll
            for (int g = 0; g < 4; g++) {
                uint32_t k4[4];
                ldm_x4(k4[0], k4[1], k4[2], k4[3],
                       asw(sk, g*16 + kb_row, ks*2 + kb_ku));
                mma16816h(s[2*g],   qf[ks], &k4[0]);
                mma16816h(s[2*g+1], qf[ks], &k4[2]);
            }
        }

        // online softmax, base 2
        float rm0 = fmaxf(s[0][0], s[0][1]);
        float rm1 = fmaxf(s[0][2], s[0][3]);
        #pragma unroll
        for (int nt = 1; nt < 8; nt++) {
            rm0 = fmaxf(rm0, fmaxf(s[nt][0], s[nt][1]));
            rm1 = fmaxf(rm1, fmaxf(s[nt][2], s[nt][3]));
        }
        rm0 = fmaxf(rm0, __shfl_xor_sync(0xffffffffu, rm0, 1));
        rm0 = fmaxf(rm0, __shfl_xor_sync(0xffffffffu, rm0, 2));
        rm1 = fmaxf(rm1, __shfl_xor_sync(0xffffffffu, rm1, 1));
        rm1 = fmaxf(rm1, __shfl_xor_sync(0xffffffffu, rm1, 2));
        const float mn0 = fmaxf(m0, rm0);
        const float mn1 = fmaxf(m1, rm1);
        const float c0 = exp2f(m0 - mn0);
        const float c1 = exp2f(m1 - mn1);
        float sum0 = 0.f, sum1 = 0.f;
        #pragma unroll
        for (int nt = 0; nt < 8; nt++) {
            s[nt][0] = exp2f(s[nt][0] - mn0); sum0 += s[nt][0];
            s[nt][1] = exp2f(s[nt][1] - mn0); sum0 += s[nt][1];
            s[nt][2] = exp2f(s[nt][2] - mn1); sum1 += s[nt][2];
            s[nt][3] = exp2f(s[nt][3] - mn1); sum1 += s[nt][3];
            o[nt][0] *= c0; o[nt][1] *= c0;
            o[nt][2] *= c1; o[nt][3] *= c1;
        }
        sum0 += __shfl_xor_sync(0xffffffffu, sum0, 1);
        sum0 += __shfl_xor_sync(0xffffffffu, sum0, 2);
        sum1 += __shfl_xor_sync(0xffffffffu, sum1, 1);
        sum1 += __shfl_xor_sync(0xffffffffu, sum1, 2);
        l0 = l0 * c0 + sum0;
        l1 = l1 * c1 + sum1;
        m0 = mn0; m1 = mn1;

        // O += P V (both single fp16)
        #pragma unroll
        for (int kt = 0; kt < 4; kt++) {
            uint32_t pa[4];
            {
                const float* t0 = s[2*kt];
                const float* t1 = s[2*kt+1];
                pa[0] = pk_h2(t0[0], t0[1]);
                pa[1] = pk_h2(t0[2], t0[3]);
                pa[2] = pk_h2(t1[0], t1[1]);
                pa[3] = pk_h2(t1[2], t1[3]);
            }
            #pragma unroll
            for (int db = 0; db < 4; db++) {
                uint32_t v4[4];
                ldm_x4_t(v4[0], v4[1], v4[2], v4[3],
                         asw(sv, kt*16 + v_row, db*2 + v_ub));
                mma16816h(o[2*db + 0], pa, &v4[0]);
                mma16816h(o[2*db + 1], pa, &v4[2]);
            }
        }
    }

    // normalize + write AO single fp16
    const float inv0 = 1.f / l0;
    const float inv1 = 1.f / l1;
    const int gr0 = b * Ss + q0 + wid*16 + (lid >> 2);
    #pragma unroll
    for (int nt = 0; nt < 8; nt++) {
        const int col = h * HD + nt*8 + (lid & 3)*2;
        *(uint32_t*)(g_aof + (size_t)gr0 * Dd + col) =
            pk_h2(o[nt][0] * inv0, o[nt][1] * inv0);
        *(uint32_t*)(g_aof + (size_t)(gr0 + 8) * Dd + col) =
            pk_h2(o[nt][2] * inv1, o[nt][3] * inv1);
    }
}

// ---------------------------------------------------------------------------
extern "C" void kernel_launch(void* const* d_in, const int* in_sizes, int n_in,
                              void* d_out, int out_size)
{
    const float* x  = (const float*)d_in[0];
    const float* Wq = (const float*)d_in[1];
    const float* Wk = (const float*)d_in[2];
    const float* Wv = (const float*)d_in[3];
    const float* Wo = (const float*)d_in[4];
    const float* bo = (const float*)d_in[5];
    float* out = (float*)d_out;

    cudaFuncSetAttribute(gemm_qkv_tc, cudaFuncAttributeMaxDynamicSharedMemorySize, GEMM_SMEM);
    cudaFuncSetAttribute(gemm_o_tc,   cudaFuncAttributeMaxDynamicSharedMemorySize, GEMM_SMEM);
    cudaFuncSetAttribute(attn_mma,    cudaFuncAttributeMaxDynamicSharedMemorySize, ATT_SMEM);

    // 1) convert fp32 -> fp16 (x quarters + 4 weights, one launch)
    dim3 gsp((Dd*Dd)/1024, 8);
    split_all<<<gsp, 256>>>(x, Wq, Wk, Wv, Wo);

    // 2) QKV projections (fp16 x1): Q pre-scaled
    dim3 gqkv(Dd / GN, Mtot / GM, 3);
    gemm_qkv_tc<<<gqkv, 256, GEMM_SMEM>>>();

    // 3) fp16 flash attention -> AO fp16
    dim3 gattn(Ss / AQ, Bb * Hh);
    attn_mma<<<gattn, 256, ATT_SMEM>>>();

    // 4) output projection (+bias) -> fp32 out
    dim3 gout(Dd / GN, Mtot / GM, 1);
    gemm_o_tc<<<gout, 256, GEMM_SMEM>>>(bo, out);
}